// round 11
// baseline (speedup 1.0000x reference)
#include <cuda_runtime.h>
#include <math.h>

#define FULL 0xffffffffu
#define BB   16
#define TT   1024
#define HHID 1024
#define SS   32
#define CC   3
#define NHH  16
#define DHH  64
#define HH2  512
#define G4   2048

// ---------------- scratch ----------------
__device__ float g_xs_f[BB*TT*G4];
__device__ float g_xs_b[BB*TT*G4];
__device__ float g_enc [BB*TT*HHID];
__device__ float g_hbuf[2][2][BB][HH2];
__device__ float g_feat [BB*SS*HHID];
__device__ float g_q    [BB*SS*HHID];
__device__ float g_k    [BB*SS*HHID];
__device__ float g_v    [BB*SS*HHID];
__device__ float g_ctx  [BB*SS*HHID];
__device__ float g_ao   [BB*SS*HHID];
__device__ float g_feat2[BB*SS*HHID];
__device__ float g_terms[BB*SS*4];
__device__ float g_wt[4][HHID*HHID];

// monotonic per-direction barrier counters, own 128B lines
struct __align__(128) PadCtr { unsigned v; unsigned pad[31]; };
__device__ PadCtr g_ctr[2];

// ---------------- monotonic flat barrier ----------------
__device__ __forceinline__ void dir_barrier_mono(int dir, unsigned target)
{
    __syncthreads();
    if (threadIdx.x == 0) {
        unsigned* ctr = &g_ctr[dir].v;
        asm volatile("red.release.gpu.global.add.u32 [%0], %1;" :: "l"(ctr), "r"(1u) : "memory");
        unsigned v;
        do {
            asm volatile("ld.acquire.gpu.global.u32 %0, [%1];" : "=r"(v) : "l"(ctr) : "memory");
        } while (v < target);
    }
    __syncthreads();
}

// ---------------- init kernel ----------------
__global__ void init_kernel()
{
    const int i = blockIdx.x * blockDim.x + threadIdx.x;
    if (i < BB * SS * 4) g_terms[i] = 0.f;
    if (i == 0) { g_ctr[0].v = 0u; g_ctr[1].v = 0u; }
}

// ---------------- cp.async helpers ----------------
__device__ __forceinline__ void cp_async16(unsigned saddr, const void* gptr)
{
    asm volatile("cp.async.cg.shared.global [%0], [%1], 16;" :: "r"(saddr), "l"(gptr));
}
__device__ __forceinline__ void cp_commit() { asm volatile("cp.async.commit_group;"); }
template<int N>
__device__ __forceinline__ void cp_wait() { asm volatile("cp.async.wait_group %0;" :: "n"(N)); }

// ---------------- tf32 mma helpers ----------------
__device__ __forceinline__ void ldsm_x4(unsigned& r0, unsigned& r1, unsigned& r2, unsigned& r3,
                                        unsigned saddr)
{
    asm volatile("ldmatrix.sync.aligned.m8n8.x4.shared.b16 {%0,%1,%2,%3}, [%4];"
                 : "=r"(r0), "=r"(r1), "=r"(r2), "=r"(r3) : "r"(saddr));
}
__device__ __forceinline__ void mma_tf32(float* c, unsigned a0, unsigned a1, unsigned a2, unsigned a3,
                                         unsigned b0, unsigned b1)
{
    asm volatile(
        "mma.sync.aligned.m16n8k8.row.col.f32.tf32.tf32.f32 "
        "{%0,%1,%2,%3}, {%4,%5,%6,%7}, {%8,%9}, {%0,%1,%2,%3};"
        : "+f"(c[0]), "+f"(c[1]), "+f"(c[2]), "+f"(c[3])
        : "r"(a0), "r"(a1), "r"(a2), "r"(a3), "r"(b0), "r"(b1));
}

// ---------------- tf32 GEMM: C[M,N] = A[M,K] @ B[N,K]^T + bias  (3-stage cp.async) ----------------
#define PAD 20
__global__ void __launch_bounds__(256)
tf32_gemm_tn(const float* __restrict__ A, const float* __restrict__ B,
             const float* __restrict__ bias, float* __restrict__ C,
             int M, int N, int K)
{
    __shared__ float As[3][128][PAD];
    __shared__ float Bs[3][128][PAD];
    const int tid  = threadIdx.x;
    const int warp = tid >> 5;
    const int lane = tid & 31;
    const int wm   = warp >> 2;
    const int wn   = warp & 3;
    const int bm   = blockIdx.y * 128;
    const int bn   = blockIdx.x * 128;

    float c[4][4][4];
#pragma unroll
    for (int i = 0; i < 4; i++)
#pragma unroll
        for (int j = 0; j < 4; j++)
#pragma unroll
            for (int r = 0; r < 4; r++) c[i][j][r] = 0.f;

    const int lr = tid >> 1;
    const int cc = (tid & 1) * 8;

    const float* Ag = A + (size_t)(bm + lr) * K + cc;
    const float* Bg = B + (size_t)(bn + lr) * K + cc;

    const unsigned sA = (unsigned)__cvta_generic_to_shared(&As[0][lr][cc]);
    const unsigned sB = (unsigned)__cvta_generic_to_shared(&Bs[0][lr][cc]);
    const unsigned STG = 128 * PAD * 4;

    const int fr = lane & 15;
    const int fc = ((lane >> 4) << 2);

    const int KT = K / 16;
    // prologue: stages 0 and 1
#pragma unroll
    for (int p = 0; p < 2; p++) {
        if (p < KT) {
            const float* Ap = Ag + (size_t)p * 16;
            const float* Bp = Bg + (size_t)p * 16;
            cp_async16(sA + p * STG,      Ap);
            cp_async16(sA + p * STG + 16, Ap + 4);
            cp_async16(sB + p * STG,      Bp);
            cp_async16(sB + p * STG + 16, Bp + 4);
        }
        cp_commit();
    }

    for (int kt = 0; kt < KT; kt++) {
        const int cur = kt % 3;
        if (kt + 2 < KT) {
            const int nst = (kt + 2) % 3;
            const float* Ap = Ag + (size_t)(kt + 2) * 16;
            const float* Bp = Bg + (size_t)(kt + 2) * 16;
            cp_async16(sA + nst * STG,      Ap);
            cp_async16(sA + nst * STG + 16, Ap + 4);
            cp_async16(sB + nst * STG,      Bp);
            cp_async16(sB + nst * STG + 16, Bp + 4);
            cp_commit();
            cp_wait<2>();
        } else if (kt + 1 < KT) {
            cp_wait<1>();
        } else {
            cp_wait<0>();
        }
        __syncthreads();

#pragma unroll
        for (int ks = 0; ks < 2; ks++) {
            const int k0 = ks * 8 + fc;
            unsigned b0a, b1a, b2a, b3a, b0b, b1b, b2b, b3b;
            {
                unsigned sa = (unsigned)__cvta_generic_to_shared(&Bs[cur][wn*32 + fr][k0]);
                ldsm_x4(b0a, b1a, b2a, b3a, sa);
                unsigned sb = (unsigned)__cvta_generic_to_shared(&Bs[cur][wn*32 + 16 + fr][k0]);
                ldsm_x4(b0b, b1b, b2b, b3b, sb);
            }
#pragma unroll
            for (int mf = 0; mf < 4; mf++) {
                unsigned a0, a1, a2, a3;
                unsigned sa = (unsigned)__cvta_generic_to_shared(&As[cur][wm*64 + mf*16 + fr][k0]);
                ldsm_x4(a0, a1, a2, a3, sa);
                mma_tf32(c[mf][0], a0, a1, a2, a3, b0a, b2a);
                mma_tf32(c[mf][1], a0, a1, a2, a3, b1a, b3a);
                mma_tf32(c[mf][2], a0, a1, a2, a3, b0b, b2b);
                mma_tf32(c[mf][3], a0, a1, a2, a3, b1b, b3b);
            }
        }
        __syncthreads();
    }

    const int g  = lane >> 2;
    const int tg = lane & 3;
#pragma unroll
    for (int mf = 0; mf < 4; mf++) {
        const int row0 = bm + wm*64 + mf*16 + g;
#pragma unroll
        for (int nf = 0; nf < 4; nf++) {
            const int col0 = bn + wn*32 + nf*8 + 2*tg;
            const float2 bv = *(const float2*)&bias[col0];
            float2 v0 = make_float2(c[mf][nf][0] + bv.x, c[mf][nf][1] + bv.y);
            float2 v1 = make_float2(c[mf][nf][2] + bv.x, c[mf][nf][3] + bv.y);
            *(float2*)&C[(size_t)row0 * N + col0]       = v0;
            *(float2*)&C[(size_t)(row0 + 8) * N + col0] = v1;
        }
    }
}

// ---------------- 1024x1024 transpose ----------------
__global__ void __launch_bounds__(256)
transpose_kernel(const float* __restrict__ in, float* __restrict__ out)
{
    __shared__ float tile[32][33];
    const int bx = blockIdx.x * 32, by = blockIdx.y * 32;
    const int tx = threadIdx.x & 31, ty4 = (threadIdx.x >> 5) * 4;
#pragma unroll
    for (int r = 0; r < 4; r++)
        tile[ty4 + r][tx] = in[(size_t)(by + ty4 + r) * HHID + bx + tx];
    __syncthreads();
#pragma unroll
    for (int r = 0; r < 4; r++)
        out[(size_t)(bx + ty4 + r) * HHID + by + tx] = tile[tx][ty4 + r];
}

// ---------------- persistent bidirectional LSTM scan ----------------
// 64 CTAs total: 32 per dir, 16 units per CTA. Rows = 4 gates x 16 units = 64.
// 8 warps = 4 row-groups (16 rows) x 2 k-slices (256 k). Weights in 128 regs/thread.
#define HPAD 516
__global__ void __launch_bounds__(256)
lstm_scan_kernel(const float* __restrict__ Whh_f, const float* __restrict__ Whh_b)
{
    __shared__ float h_sh[16 * HPAD];
    __shared__ float red[2][64][18];

    const int cid  = blockIdx.x;
    const int dir  = cid >> 5;
    const int ug   = cid & 31;
    const int U0   = ug * 16;
    const int tid  = threadIdx.x;
    const int w    = tid >> 5;
    const int lane = tid & 31;
    const int rg   = w >> 1;       // 0..3
    const int ksl  = w & 1;        // 0..1
    const int kb   = ksl * 256;
    const int qr   = lane >> 2;
    const int qc   = lane & 3;
    const int r_lo = rg * 16 + qr;
    const int r_hi = r_lo + 8;
    const int fr   = lane & 15;
    const int fc   = (lane >> 4) << 2;

    const float* __restrict__ Whh = dir ? Whh_b : Whh_f;
    const float* __restrict__ xs  = dir ? g_xs_b : g_xs_f;

    // persistent A fragments (32 j-slices x 4 regs = 128 regs)
    unsigned a[32][4];
    {
        const int grow_lo = (r_lo >> 4) * HH2 + U0 + (r_lo & 15);
        const int grow_hi = (r_hi >> 4) * HH2 + U0 + (r_hi & 15);
        const float* Wlo = Whh + (size_t)grow_lo * HH2;
        const float* Whi = Whh + (size_t)grow_hi * HH2;
#pragma unroll
        for (int j = 0; j < 32; j++) {
            const int k0 = kb + j * 8 + qc;
            a[j][0] = __float_as_uint(Wlo[k0]);
            a[j][1] = __float_as_uint(Whi[k0]);
            a[j][2] = __float_as_uint(Wlo[k0 + 4]);
            a[j][3] = __float_as_uint(Whi[k0 + 4]);
        }
    }

    // cell thread: one (batch, unit) per thread (256 = 16 x 16)
    const int cb = tid >> 4;
    const int cu = tid & 15;
    float c_state = 0.f;

    for (int s = 0; s < TT; s++) {
        const int t = dir ? (TT - 1 - s) : s;

        // prefetch xs (gate-major rows of G4)
        const size_t xb = ((size_t)(cb * TT + t)) * G4 + U0 + cu;
        const float xp0 = xs[xb];
        const float xp1 = xs[xb + 512];
        const float xp2 = xs[xb + 1024];
        const float xp3 = xs[xb + 1536];

        if (s == 0) {
            for (int i = tid; i < 16 * HPAD; i += 256) h_sh[i] = 0.f;
        } else {
            const float* hg = &g_hbuf[dir][(s - 1) & 1][0][0];
            for (int idx = tid * 4; idx < BB * HH2; idx += 1024) {
                const float4 v = __ldcg((const float4*)&hg[idx]);
                const int b = idx >> 9, k = idx & 511;
                *(float4*)&h_sh[b * HPAD + k] = v;
            }
        }
        __syncthreads();

        // tensor-core matvec, split accumulators, 32 j-slices over 256 k
        float cl0[4] = {0,0,0,0}, cl1[4] = {0,0,0,0};
        float ch0[4] = {0,0,0,0}, ch1[4] = {0,0,0,0};
#pragma unroll
        for (int j = 0; j < 32; j += 2) {
            {
                const int k0 = kb + j * 8 + fc;
                unsigned m0, m1, m2, m3;
                const unsigned sa = (unsigned)__cvta_generic_to_shared(&h_sh[fr * HPAD + k0]);
                ldsm_x4(m0, m1, m2, m3, sa);
                mma_tf32(cl0, a[j][0], a[j][1], a[j][2], a[j][3], m0, m2);
                mma_tf32(ch0, a[j][0], a[j][1], a[j][2], a[j][3], m1, m3);
            }
            {
                const int k0 = kb + (j + 1) * 8 + fc;
                unsigned m0, m1, m2, m3;
                const unsigned sa = (unsigned)__cvta_generic_to_shared(&h_sh[fr * HPAD + k0]);
                ldsm_x4(m0, m1, m2, m3, sa);
                mma_tf32(cl1, a[j+1][0], a[j+1][1], a[j+1][2], a[j+1][3], m0, m2);
                mma_tf32(ch1, a[j+1][0], a[j+1][1], a[j+1][2], a[j+1][3], m1, m3);
            }
        }

        *(float2*)&red[ksl][r_lo][2 * qc]     = make_float2(cl0[0]+cl1[0], cl0[1]+cl1[1]);
        *(float2*)&red[ksl][r_hi][2 * qc]     = make_float2(cl0[2]+cl1[2], cl0[3]+cl1[3]);
        *(float2*)&red[ksl][r_lo][8 + 2 * qc] = make_float2(ch0[0]+ch1[0], ch0[1]+ch1[1]);
        *(float2*)&red[ksl][r_hi][8 + 2 * qc] = make_float2(ch0[2]+ch1[2], ch0[3]+ch1[3]);
        __syncthreads();

        // fused k-reduction (2 slices) + cell update, all 256 threads
        {
            const int r0 = 0 * 16 + cu, r1 = 1 * 16 + cu, r2 = 2 * 16 + cu, r3 = 3 * 16 + cu;
            const float zi = red[0][r0][cb] + red[1][r0][cb] + xp0;
            const float zf = red[0][r1][cb] + red[1][r1][cb] + xp1;
            const float zg = red[0][r2][cb] + red[1][r2][cb] + xp2;
            const float zo = red[0][r3][cb] + red[1][r3][cb] + xp3;
            const float is = 1.f / (1.f + expf(-zi));
            const float fs = 1.f / (1.f + expf(-zf));
            const float gv = tanhf(zg);
            const float os = 1.f / (1.f + expf(-zo));
            c_state = fs * c_state + is * gv;
            const float hn = os * tanhf(c_state);
            __stcg(&g_hbuf[dir][s & 1][cb][U0 + cu], hn);
            __stcg(&g_enc[((size_t)(cb * TT + t)) * HHID + dir * HH2 + U0 + cu], hn);
        }

        dir_barrier_mono(dir, 32u * (unsigned)(s + 1));
    }
}

// ---------------- span mean-pool + LayerNorm ----------------
__global__ void __launch_bounds__(256)
span_pool_ln_kernel(const int* __restrict__ heads, const int* __restrict__ tails,
                    const float* __restrict__ lng, const float* __restrict__ lnb)
{
    const int r = blockIdx.x;
    const int b = r >> 5;
    int p0 = heads[r] + 1; if (p0 < 0) p0 = 0;
    int p1 = tails[r];     if (p1 > TT) p1 = TT;
    const int tid = threadIdx.x;
    const int d = tid * 4;

    float s0=0,s1=0,s2=0,s3=0;
    for (int p = p0; p < p1; p++) {
        const float4 vv = *(const float4*)&g_enc[(size_t)(b * TT + p) * HHID + d];
        s0 += vv.x; s1 += vv.y; s2 += vv.z; s3 += vv.w;
    }
    int cnt = p1 - p0; if (cnt < 1) cnt = 1;
    const float inv = 1.f / (float)cnt;
    const float v0=s0*inv, v1=s1*inv, v2=s2*inv, v3=s3*inv;

    __shared__ float red[256];
    __shared__ float stats[2];
    red[tid] = v0+v1+v2+v3;
    __syncthreads();
    for (int st = 128; st > 0; st >>= 1) { if (tid < st) red[tid] += red[tid+st]; __syncthreads(); }
    if (tid == 0) stats[0] = red[0] * (1.f / HHID);
    __syncthreads();
    const float mean = stats[0];
    const float q0=v0-mean, q1=v1-mean, q2=v2-mean, q3=v3-mean;
    red[tid] = q0*q0+q1*q1+q2*q2+q3*q3;
    __syncthreads();
    for (int st = 128; st > 0; st >>= 1) { if (tid < st) red[tid] += red[tid+st]; __syncthreads(); }
    if (tid == 0) stats[1] = rsqrtf(red[0] * (1.f / HHID) + 1e-7f);
    __syncthreads();
    const float rstd = stats[1];
    float* out = &g_feat[(size_t)r * HHID + d];
    out[0] = q0*rstd*lng[d+0] + lnb[d+0];
    out[1] = q1*rstd*lng[d+1] + lnb[d+1];
    out[2] = q2*rstd*lng[d+2] + lnb[d+2];
    out[3] = q3*rstd*lng[d+3] + lnb[d+3];
}

// ---------------- attention ----------------
__global__ void __launch_bounds__(256)
attn_kernel(const int* __restrict__ am)
{
    const int bh = blockIdx.x;
    const int b = bh >> 4;
    const int h = bh & 15;
    __shared__ float qs[SS][DHH], ks[SS][DHH], vs[SS][DHH];
    __shared__ float sc[SS][SS + 1];
    const int tid = threadIdx.x;

    for (int i = tid; i < SS * DHH; i += 256) {
        const int s = i >> 6, d = i & 63;
        const size_t off = (size_t)(b * SS + s) * HHID + h * DHH + d;
        qs[s][d] = g_q[off];
        ks[s][d] = g_k[off];
        vs[s][d] = g_v[off];
    }
    __syncthreads();

    for (int i = tid; i < SS * SS; i += 256) {
        const int qq = i >> 5, kk = i & 31;
        float a = 0.f;
#pragma unroll
        for (int d = 0; d < DHH; d++) a += qs[qq][d] * ks[kk][d];
        const bool valid = (am[b * SS + qq] != 0) && (am[b * SS + kk] != 0);
        sc[qq][kk] = valid ? a * 0.125f : -1e9f;
    }
    __syncthreads();

    const int wid = tid >> 5, lane = tid & 31;
    for (int r = wid; r < SS; r += 8) {
        const float val = sc[r][lane];
        float m = val;
#pragma unroll
        for (int o = 16; o > 0; o >>= 1) m = fmaxf(m, __shfl_xor_sync(FULL, m, o));
        const float e = expf(val - m);
        float sum = e;
#pragma unroll
        for (int o = 16; o > 0; o >>= 1) sum += __shfl_xor_sync(FULL, sum, o);
        sc[r][lane] = e / sum;
    }
    __syncthreads();

    for (int i = tid; i < SS * DHH; i += 256) {
        const int qq = i >> 6, d = i & 63;
        float a = 0.f;
#pragma unroll
        for (int kk = 0; kk < SS; kk++) a += sc[qq][kk] * vs[kk][d];
        g_ctx[(size_t)(b * SS + qq) * HHID + h * DHH + d] = a;
    }
}

// ---------------- residual + LayerNorm ----------------
__global__ void __launch_bounds__(256)
resid_ln_kernel(const float* __restrict__ lng, const float* __restrict__ lnb)
{
    const int r = blockIdx.x;
    const int tid = threadIdx.x;
    const int d = tid * 4;
    const size_t base = (size_t)r * HHID + d;
    const float4 a = *(const float4*)&g_ao[base];
    const float4 f = *(const float4*)&g_feat[base];
    const float v0=a.x+f.x, v1=a.y+f.y, v2=a.z+f.z, v3=a.w+f.w;

    __shared__ float red[256];
    __shared__ float stats[2];
    red[tid] = v0+v1+v2+v3;
    __syncthreads();
    for (int st = 128; st > 0; st >>= 1) { if (tid < st) red[tid] += red[tid+st]; __syncthreads(); }
    if (tid == 0) stats[0] = red[0] * (1.f / HHID);
    __syncthreads();
    const float mean = stats[0];
    const float q0=v0-mean, q1=v1-mean, q2=v2-mean, q3=v3-mean;
    red[tid] = q0*q0+q1*q1+q2*q2+q3*q3;
    __syncthreads();
    for (int st = 128; st > 0; st >>= 1) { if (tid < st) red[tid] += red[tid+st]; __syncthreads(); }
    if (tid == 0) stats[1] = rsqrtf(red[0] * (1.f / HHID) + 1e-7f);
    __syncthreads();
    const float rstd = stats[1];
    float* out = &g_feat2[base];
    out[0] = q0*rstd*lng[d+0] + lnb[d+0];
    out[1] = q1*rstd*lng[d+1] + lnb[d+1];
    out[2] = q2*rstd*lng[d+2] + lnb[d+2];
    out[3] = q3*rstd*lng[d+3] + lnb[d+3];
}

// ---------------- classifier + per-span loss terms ----------------
__global__ void __launch_bounds__(128)
loss_terms_kernel(const int* __restrict__ labels, const float* __restrict__ wf,
                  const int* __restrict__ am,
                  const float* __restrict__ Wc, const float* __restrict__ bc)
{
    const int r = blockIdx.x;
    const int tid = threadIdx.x;
    const float* row = &g_feat2[(size_t)r * HHID];
    float d0=0, d1=0, d2=0;
    for (int i = tid; i < HHID; i += 128) {
        const float x = row[i];
        d0 += x * Wc[i*3+0];
        d1 += x * Wc[i*3+1];
        d2 += x * Wc[i*3+2];
    }
    __shared__ float r0[128], r1[128], r2[128];
    r0[tid]=d0; r1[tid]=d1; r2[tid]=d2;
    __syncthreads();
    for (int st = 64; st > 0; st >>= 1) {
        if (tid < st) { r0[tid]+=r0[tid+st]; r1[tid]+=r1[tid+st]; r2[tid]+=r2[tid+st]; }
        __syncthreads();
    }
    if (tid == 0) {
        const float z0 = r0[0]+bc[0], z1 = r1[0]+bc[1], z2 = r2[0]+bc[2];
        const float m = fmaxf(z0, fmaxf(z1, z2));
        const float e0 = expf(z0-m), e1 = expf(z1-m), e2 = expf(z2-m);
        const float lse = m + logf(e0+e1+e2);
        const int lab = labels[r];
        const bool valid = lab >= 0;
        const int lc = valid ? lab : 0;
        const float zl = (lc==0) ? z0 : ((lc==1) ? z1 : z2);
        const float logp = zl - lse;
        const float pt = expf(logp);
        const float spanm = ((am[r]!=0) && valid) ? 1.f : 0.f;
        const float vm = valid ? 1.f : 0.f;
        const float omp = 1.f - pt;
        g_terms[r*4+0] = (-logp * wf[r]) * spanm;
        g_terms[r*4+1] = spanm;
        g_terms[r*4+2] = (-(omp*omp) * logp) * vm;
        g_terms[r*4+3] = vm;
    }
}

__global__ void __launch_bounds__(256)
final_loss_kernel(float* __restrict__ out)
{
    const int tid = threadIdx.x;
    float a0=0,a1=0,a2=0,a3=0;
    for (int r = tid; r < BB*SS; r += 256) {
        a0 += g_terms[r*4+0]; a1 += g_terms[r*4+1];
        a2 += g_terms[r*4+2]; a3 += g_terms[r*4+3];
    }
    __shared__ float s0[256], s1[256], s2[256], s3[256];
    s0[tid]=a0; s1[tid]=a1; s2[tid]=a2; s3[tid]=a3;
    __syncthreads();
    for (int st = 128; st > 0; st >>= 1) {
        if (tid < st) { s0[tid]+=s0[tid+st]; s1[tid]+=s1[tid+st]; s2[tid]+=s2[tid+st]; s3[tid]+=s3[tid+st]; }
        __syncthreads();
    }
    if (tid == 0)
        out[0] = s0[0] / fmaxf(s1[0], 1.f) + s2[0] / fmaxf(s3[0], 1.f);
}

// ---------------- launch ----------------
extern "C" void kernel_launch(void* const* d_in, const int* in_sizes, int n_in,
                              void* d_out, int out_size)
{
    const float* hs     = (const float*)d_in[0];
    const int*   heads  = (const int*)  d_in[1];
    const int*   tails  = (const int*)  d_in[2];
    const int*   am     = (const int*)  d_in[3];
    const int*   labels = (const int*)  d_in[4];
    const float* wf     = (const float*)d_in[5];
    const float* Wih_f  = (const float*)d_in[6];
    const float* Whh_f  = (const float*)d_in[7];
    const float* b_f    = (const float*)d_in[8];
    const float* Wih_b  = (const float*)d_in[9];
    const float* Whh_b  = (const float*)d_in[10];
    const float* b_b    = (const float*)d_in[11];
    const float* ln1g   = (const float*)d_in[12];
    const float* ln1b   = (const float*)d_in[13];
    const float* Wq     = (const float*)d_in[14];
    const float* bq     = (const float*)d_in[15];
    const float* Wk     = (const float*)d_in[16];
    const float* bk     = (const float*)d_in[17];
    const float* Wv     = (const float*)d_in[18];
    const float* bv     = (const float*)d_in[19];
    const float* Wo     = (const float*)d_in[20];
    const float* bo     = (const float*)d_in[21];
    const float* ln2g   = (const float*)d_in[22];
    const float* ln2b   = (const float*)d_in[23];
    const float* Wc     = (const float*)d_in[24];
    const float* bc     = (const float*)d_in[25];

    float *p_xs_f, *p_xs_b, *p_feat, *p_q, *p_k, *p_v, *p_ctx, *p_ao, *p_wt;
    cudaGetSymbolAddress((void**)&p_xs_f,  g_xs_f);
    cudaGetSymbolAddress((void**)&p_xs_b,  g_xs_b);
    cudaGetSymbolAddress((void**)&p_feat,  g_feat);
    cudaGetSymbolAddress((void**)&p_q,     g_q);
    cudaGetSymbolAddress((void**)&p_k,     g_k);
    cudaGetSymbolAddress((void**)&p_v,     g_v);
    cudaGetSymbolAddress((void**)&p_ctx,   g_ctx);
    cudaGetSymbolAddress((void**)&p_ao,    g_ao);
    cudaGetSymbolAddress((void**)&p_wt,    g_wt);

    // index 0: init (loss terms + barrier counters)
    init_kernel<<<8, 256>>>();

    // input projections: tf32, 3-stage pipeline
    {
        dim3 grid(G4/128, (BB*TT)/128), blk(256);
        tf32_gemm_tn<<<grid, blk>>>(hs, Wih_f, b_f, p_xs_f, BB*TT, G4, HHID);
        tf32_gemm_tn<<<grid, blk>>>(hs, Wih_b, b_b, p_xs_b, BB*TT, G4, HHID);
    }

    // index 3: persistent bidirectional scan (64 CTAs, 16 units each)
    lstm_scan_kernel<<<64, 256>>>(Whh_f, Whh_b);

    // transpose QKV/O weights
    {
        dim3 grid(32, 32), blk(256);
        transpose_kernel<<<grid, blk>>>(Wq, p_wt + 0 * HHID * HHID);
        transpose_kernel<<<grid, blk>>>(Wk, p_wt + 1 * HHID * HHID);
        transpose_kernel<<<grid, blk>>>(Wv, p_wt + 2 * HHID * HHID);
        transpose_kernel<<<grid, blk>>>(Wo, p_wt + 3 * HHID * HHID);
    }

    // span pool + LN1
    span_pool_ln_kernel<<<BB*SS, 256>>>(heads, tails, ln1g, ln1b);

    // q,k,v
    {
        dim3 grid(HHID/128, (BB*SS)/128), blk(256);
        tf32_gemm_tn<<<grid, blk>>>(p_feat, p_wt + 0 * HHID * HHID, bq, p_q, BB*SS, HHID, HHID);
        tf32_gemm_tn<<<grid, blk>>>(p_feat, p_wt + 1 * HHID * HHID, bk, p_k, BB*SS, HHID, HHID);
        tf32_gemm_tn<<<grid, blk>>>(p_feat, p_wt + 2 * HHID * HHID, bv, p_v, BB*SS, HHID, HHID);
    }

    attn_kernel<<<BB*NHH, 256>>>(am);

    {
        dim3 grid(HHID/128, (BB*SS)/128), blk(256);
        tf32_gemm_tn<<<grid, blk>>>(p_ctx, p_wt + 3 * HHID * HHID, bo, p_ao, BB*SS, HHID, HHID);
    }

    resid_ln_kernel<<<BB*SS, 256>>>(ln2g, ln2b);

    loss_terms_kernel<<<BB*SS, 128>>>(labels, wf, am, Wc, bc);

    final_loss_kernel<<<1, 256>>>((float*)d_out);
}

// round 12
// speedup vs baseline: 1.0766x; 1.0766x over previous
#include <cuda_runtime.h>
#include <math.h>

#define FULL 0xffffffffu
#define BB   16
#define TT   1024
#define HHID 1024
#define SS   32
#define CC   3
#define NHH  16
#define DHH  64
#define HH2  512
#define G4   2048

// ---------------- scratch ----------------
__device__ float g_xs_f[BB*TT*G4];
__device__ float g_xs_b[BB*TT*G4];
__device__ float g_enc [BB*TT*HHID];
__device__ float g_hbuf[2][2][BB][HH2];
__device__ float g_feat [BB*SS*HHID];
__device__ float g_q    [BB*SS*HHID];
__device__ float g_k    [BB*SS*HHID];
__device__ float g_v    [BB*SS*HHID];
__device__ float g_ctx  [BB*SS*HHID];
__device__ float g_ao   [BB*SS*HHID];
__device__ float g_feat2[BB*SS*HHID];
__device__ float g_terms[BB*SS*4];
__device__ float g_wt[4][HHID*HHID];

// monotonic per-direction barrier counters, own 128B lines
struct __align__(128) PadCtr { unsigned v; unsigned pad[31]; };
__device__ PadCtr g_ctr[2];

// ---------------- monotonic flat barrier ----------------
__device__ __forceinline__ void dir_barrier_mono(int dir, unsigned target)
{
    __syncthreads();
    if (threadIdx.x == 0) {
        unsigned* ctr = &g_ctr[dir].v;
        asm volatile("red.release.gpu.global.add.u32 [%0], %1;" :: "l"(ctr), "r"(1u) : "memory");
        unsigned v;
        do {
            asm volatile("ld.acquire.gpu.global.u32 %0, [%1];" : "=r"(v) : "l"(ctr) : "memory");
        } while (v < target);
    }
    __syncthreads();
}

// ---------------- init kernel ----------------
__global__ void init_kernel()
{
    const int i = blockIdx.x * blockDim.x + threadIdx.x;
    if (i < BB * SS * 4) g_terms[i] = 0.f;
    if (i == 0) { g_ctr[0].v = 0u; g_ctr[1].v = 0u; }
}

// ---------------- cp.async helpers ----------------
__device__ __forceinline__ void cp_async16(unsigned saddr, const void* gptr)
{
    asm volatile("cp.async.cg.shared.global [%0], [%1], 16;" :: "r"(saddr), "l"(gptr));
}
__device__ __forceinline__ void cp_commit() { asm volatile("cp.async.commit_group;"); }
template<int N>
__device__ __forceinline__ void cp_wait() { asm volatile("cp.async.wait_group %0;" :: "n"(N)); }

// ---------------- tf32 mma helpers ----------------
__device__ __forceinline__ void ldsm_x4(unsigned& r0, unsigned& r1, unsigned& r2, unsigned& r3,
                                        unsigned saddr)
{
    asm volatile("ldmatrix.sync.aligned.m8n8.x4.shared.b16 {%0,%1,%2,%3}, [%4];"
                 : "=r"(r0), "=r"(r1), "=r"(r2), "=r"(r3) : "r"(saddr));
}
__device__ __forceinline__ void mma_tf32(float* c, unsigned a0, unsigned a1, unsigned a2, unsigned a3,
                                         unsigned b0, unsigned b1)
{
    asm volatile(
        "mma.sync.aligned.m16n8k8.row.col.f32.tf32.tf32.f32 "
        "{%0,%1,%2,%3}, {%4,%5,%6,%7}, {%8,%9}, {%0,%1,%2,%3};"
        : "+f"(c[0]), "+f"(c[1]), "+f"(c[2]), "+f"(c[3])
        : "r"(a0), "r"(a1), "r"(a2), "r"(a3), "r"(b0), "r"(b1));
}

// ---------------- tf32 GEMM: C[M,N] = A[M,K] @ B[N,K]^T + bias  (3-stage cp.async) ----------------
#define PAD 20
__global__ void __launch_bounds__(256)
tf32_gemm_tn(const float* __restrict__ A, const float* __restrict__ B,
             const float* __restrict__ bias, float* __restrict__ C,
             int M, int N, int K)
{
    __shared__ float As[3][128][PAD];
    __shared__ float Bs[3][128][PAD];
    const int tid  = threadIdx.x;
    const int warp = tid >> 5;
    const int lane = tid & 31;
    const int wm   = warp >> 2;
    const int wn   = warp & 3;
    const int bm   = blockIdx.y * 128;
    const int bn   = blockIdx.x * 128;

    float c[4][4][4];
#pragma unroll
    for (int i = 0; i < 4; i++)
#pragma unroll
        for (int j = 0; j < 4; j++)
#pragma unroll
            for (int r = 0; r < 4; r++) c[i][j][r] = 0.f;

    const int lr = tid >> 1;
    const int cc = (tid & 1) * 8;

    const float* Ag = A + (size_t)(bm + lr) * K + cc;
    const float* Bg = B + (size_t)(bn + lr) * K + cc;

    const unsigned sA = (unsigned)__cvta_generic_to_shared(&As[0][lr][cc]);
    const unsigned sB = (unsigned)__cvta_generic_to_shared(&Bs[0][lr][cc]);
    const unsigned STG = 128 * PAD * 4;

    const int fr = lane & 15;
    const int fc = ((lane >> 4) << 2);

    const int KT = K / 16;
#pragma unroll
    for (int p = 0; p < 2; p++) {
        if (p < KT) {
            const float* Ap = Ag + (size_t)p * 16;
            const float* Bp = Bg + (size_t)p * 16;
            cp_async16(sA + p * STG,      Ap);
            cp_async16(sA + p * STG + 16, Ap + 4);
            cp_async16(sB + p * STG,      Bp);
            cp_async16(sB + p * STG + 16, Bp + 4);
        }
        cp_commit();
    }

    for (int kt = 0; kt < KT; kt++) {
        const int cur = kt % 3;
        if (kt + 2 < KT) {
            const int nst = (kt + 2) % 3;
            const float* Ap = Ag + (size_t)(kt + 2) * 16;
            const float* Bp = Bg + (size_t)(kt + 2) * 16;
            cp_async16(sA + nst * STG,      Ap);
            cp_async16(sA + nst * STG + 16, Ap + 4);
            cp_async16(sB + nst * STG,      Bp);
            cp_async16(sB + nst * STG + 16, Bp + 4);
            cp_commit();
            cp_wait<2>();
        } else if (kt + 1 < KT) {
            cp_wait<1>();
        } else {
            cp_wait<0>();
        }
        __syncthreads();

#pragma unroll
        for (int ks = 0; ks < 2; ks++) {
            const int k0 = ks * 8 + fc;
            unsigned b0a, b1a, b2a, b3a, b0b, b1b, b2b, b3b;
            {
                unsigned sa = (unsigned)__cvta_generic_to_shared(&Bs[cur][wn*32 + fr][k0]);
                ldsm_x4(b0a, b1a, b2a, b3a, sa);
                unsigned sb = (unsigned)__cvta_generic_to_shared(&Bs[cur][wn*32 + 16 + fr][k0]);
                ldsm_x4(b0b, b1b, b2b, b3b, sb);
            }
#pragma unroll
            for (int mf = 0; mf < 4; mf++) {
                unsigned a0, a1, a2, a3;
                unsigned sa = (unsigned)__cvta_generic_to_shared(&As[cur][wm*64 + mf*16 + fr][k0]);
                ldsm_x4(a0, a1, a2, a3, sa);
                mma_tf32(c[mf][0], a0, a1, a2, a3, b0a, b2a);
                mma_tf32(c[mf][1], a0, a1, a2, a3, b1a, b3a);
                mma_tf32(c[mf][2], a0, a1, a2, a3, b0b, b2b);
                mma_tf32(c[mf][3], a0, a1, a2, a3, b1b, b3b);
            }
        }
        __syncthreads();
    }

    const int g  = lane >> 2;
    const int tg = lane & 3;
#pragma unroll
    for (int mf = 0; mf < 4; mf++) {
        const int row0 = bm + wm*64 + mf*16 + g;
#pragma unroll
        for (int nf = 0; nf < 4; nf++) {
            const int col0 = bn + wn*32 + nf*8 + 2*tg;
            const float2 bv = *(const float2*)&bias[col0];
            float2 v0 = make_float2(c[mf][nf][0] + bv.x, c[mf][nf][1] + bv.y);
            float2 v1 = make_float2(c[mf][nf][2] + bv.x, c[mf][nf][3] + bv.y);
            *(float2*)&C[(size_t)row0 * N + col0]       = v0;
            *(float2*)&C[(size_t)(row0 + 8) * N + col0] = v1;
        }
    }
}

// ---------------- 1024x1024 transpose ----------------
__global__ void __launch_bounds__(256)
transpose_kernel(const float* __restrict__ in, float* __restrict__ out)
{
    __shared__ float tile[32][33];
    const int bx = blockIdx.x * 32, by = blockIdx.y * 32;
    const int tx = threadIdx.x & 31, ty4 = (threadIdx.x >> 5) * 4;
#pragma unroll
    for (int r = 0; r < 4; r++)
        tile[ty4 + r][tx] = in[(size_t)(by + ty4 + r) * HHID + bx + tx];
    __syncthreads();
#pragma unroll
    for (int r = 0; r < 4; r++)
        out[(size_t)(bx + ty4 + r) * HHID + by + tx] = tile[tx][ty4 + r];
}

// ---------------- persistent bidirectional LSTM scan (R10 config: 128 CTAs, 8 units) ----------------
#define HPAD 516
__global__ void __launch_bounds__(256)
lstm_scan_kernel(const float* __restrict__ Whh_f, const float* __restrict__ Whh_b)
{
    __shared__ float h_sh[16 * HPAD];
    __shared__ float red[4][32][18];

    const int cid  = blockIdx.x;
    const int dir  = cid >> 6;
    const int ug   = cid & 63;
    const int U0   = ug * 8;
    const int tid  = threadIdx.x;
    const int w    = tid >> 5;
    const int lane = tid & 31;
    const int rg   = w >> 2;
    const int ksl  = w & 3;
    const int kb   = ksl * 128;
    const int qr   = lane >> 2;
    const int qc   = lane & 3;
    const int r_lo = rg * 16 + qr;
    const int r_hi = r_lo + 8;
    const int fr   = lane & 15;
    const int fc   = (lane >> 4) << 2;

    const float* __restrict__ Whh = dir ? Whh_b : Whh_f;
    const float* __restrict__ xs  = dir ? g_xs_b : g_xs_f;

    // persistent A fragments
    unsigned a[16][4];
    {
        const int grow_lo = (r_lo >> 3) * HH2 + U0 + (r_lo & 7);
        const int grow_hi = (r_hi >> 3) * HH2 + U0 + (r_hi & 7);
        const float* Wlo = Whh + (size_t)grow_lo * HH2;
        const float* Whi = Whh + (size_t)grow_hi * HH2;
#pragma unroll
        for (int j = 0; j < 16; j++) {
            const int k0 = kb + j * 8 + qc;
            a[j][0] = __float_as_uint(Wlo[k0]);
            a[j][1] = __float_as_uint(Whi[k0]);
            a[j][2] = __float_as_uint(Wlo[k0 + 4]);
            a[j][3] = __float_as_uint(Whi[k0 + 4]);
        }
    }

    const int cb = tid >> 3;
    const int cu = tid & 7;
    float c_state = 0.f;

    for (int s = 0; s < TT; s++) {
        const int t = dir ? (TT - 1 - s) : s;

        float xp0 = 0.f, xp1 = 0.f, xp2 = 0.f, xp3 = 0.f;
        if (tid < 128) {
            const size_t xb = ((size_t)(cb * TT + t)) * G4 + U0 + cu;
            xp0 = xs[xb];
            xp1 = xs[xb + 512];
            xp2 = xs[xb + 1024];
            xp3 = xs[xb + 1536];
        }

        if (s == 0) {
            for (int i = tid; i < 16 * HPAD; i += 256) h_sh[i] = 0.f;
        } else {
            const float* hg = &g_hbuf[dir][(s - 1) & 1][0][0];
            for (int idx = tid * 4; idx < BB * HH2; idx += 1024) {
                const float4 v = __ldcg((const float4*)&hg[idx]);
                const int b = idx >> 9, k = idx & 511;
                *(float4*)&h_sh[b * HPAD + k] = v;
            }
        }
        __syncthreads();

        float cl0[4] = {0,0,0,0}, cl1[4] = {0,0,0,0};
        float ch0[4] = {0,0,0,0}, ch1[4] = {0,0,0,0};
#pragma unroll
        for (int j = 0; j < 16; j += 2) {
            {
                const int k0 = kb + j * 8 + fc;
                unsigned m0, m1, m2, m3;
                const unsigned sa = (unsigned)__cvta_generic_to_shared(&h_sh[fr * HPAD + k0]);
                ldsm_x4(m0, m1, m2, m3, sa);
                mma_tf32(cl0, a[j][0], a[j][1], a[j][2], a[j][3], m0, m2);
                mma_tf32(ch0, a[j][0], a[j][1], a[j][2], a[j][3], m1, m3);
            }
            {
                const int k0 = kb + (j + 1) * 8 + fc;
                unsigned m0, m1, m2, m3;
                const unsigned sa = (unsigned)__cvta_generic_to_shared(&h_sh[fr * HPAD + k0]);
                ldsm_x4(m0, m1, m2, m3, sa);
                mma_tf32(cl1, a[j+1][0], a[j+1][1], a[j+1][2], a[j+1][3], m0, m2);
                mma_tf32(ch1, a[j+1][0], a[j+1][1], a[j+1][2], a[j+1][3], m1, m3);
            }
        }

        *(float2*)&red[ksl][r_lo][2 * qc]     = make_float2(cl0[0]+cl1[0], cl0[1]+cl1[1]);
        *(float2*)&red[ksl][r_hi][2 * qc]     = make_float2(cl0[2]+cl1[2], cl0[3]+cl1[3]);
        *(float2*)&red[ksl][r_lo][8 + 2 * qc] = make_float2(ch0[0]+ch1[0], ch0[1]+ch1[1]);
        *(float2*)&red[ksl][r_hi][8 + 2 * qc] = make_float2(ch0[2]+ch1[2], ch0[3]+ch1[3]);
        __syncthreads();

        if (tid < 128) {
            const int r0 = 0 * 8 + cu, r1 = 1 * 8 + cu, r2 = 2 * 8 + cu, r3 = 3 * 8 + cu;
            const float zi = red[0][r0][cb] + red[1][r0][cb] + red[2][r0][cb] + red[3][r0][cb] + xp0;
            const float zf = red[0][r1][cb] + red[1][r1][cb] + red[2][r1][cb] + red[3][r1][cb] + xp1;
            const float zg = red[0][r2][cb] + red[1][r2][cb] + red[2][r2][cb] + red[3][r2][cb] + xp2;
            const float zo = red[0][r3][cb] + red[1][r3][cb] + red[2][r3][cb] + red[3][r3][cb] + xp3;
            const float is = 1.f / (1.f + expf(-zi));
            const float fs = 1.f / (1.f + expf(-zf));
            const float gv = tanhf(zg);
            const float os = 1.f / (1.f + expf(-zo));
            c_state = fs * c_state + is * gv;
            const float hn = os * tanhf(c_state);
            __stcg(&g_hbuf[dir][s & 1][cb][U0 + cu], hn);
            __stcg(&g_enc[((size_t)(cb * TT + t)) * HHID + dir * HH2 + U0 + cu], hn);
        }

        dir_barrier_mono(dir, 64u * (unsigned)(s + 1));
    }
}

// ---------------- span mean-pool + LayerNorm ----------------
__global__ void __launch_bounds__(256)
span_pool_ln_kernel(const int* __restrict__ heads, const int* __restrict__ tails,
                    const float* __restrict__ lng, const float* __restrict__ lnb)
{
    const int r = blockIdx.x;
    const int b = r >> 5;
    int p0 = heads[r] + 1; if (p0 < 0) p0 = 0;
    int p1 = tails[r];     if (p1 > TT) p1 = TT;
    const int tid = threadIdx.x;
    const int d = tid * 4;

    float s0=0,s1=0,s2=0,s3=0;
    for (int p = p0; p < p1; p++) {
        const float4 vv = *(const float4*)&g_enc[(size_t)(b * TT + p) * HHID + d];
        s0 += vv.x; s1 += vv.y; s2 += vv.z; s3 += vv.w;
    }
    int cnt = p1 - p0; if (cnt < 1) cnt = 1;
    const float inv = 1.f / (float)cnt;
    const float v0=s0*inv, v1=s1*inv, v2=s2*inv, v3=s3*inv;

    __shared__ float red[256];
    __shared__ float stats[2];
    red[tid] = v0+v1+v2+v3;
    __syncthreads();
    for (int st = 128; st > 0; st >>= 1) { if (tid < st) red[tid] += red[tid+st]; __syncthreads(); }
    if (tid == 0) stats[0] = red[0] * (1.f / HHID);
    __syncthreads();
    const float mean = stats[0];
    const float q0=v0-mean, q1=v1-mean, q2=v2-mean, q3=v3-mean;
    red[tid] = q0*q0+q1*q1+q2*q2+q3*q3;
    __syncthreads();
    for (int st = 128; st > 0; st >>= 1) { if (tid < st) red[tid] += red[tid+st]; __syncthreads(); }
    if (tid == 0) stats[1] = rsqrtf(red[0] * (1.f / HHID) + 1e-7f);
    __syncthreads();
    const float rstd = stats[1];
    float* out = &g_feat[(size_t)r * HHID + d];
    out[0] = q0*rstd*lng[d+0] + lnb[d+0];
    out[1] = q1*rstd*lng[d+1] + lnb[d+1];
    out[2] = q2*rstd*lng[d+2] + lnb[d+2];
    out[3] = q3*rstd*lng[d+3] + lnb[d+3];
}

// ---------------- attention ----------------
__global__ void __launch_bounds__(256)
attn_kernel(const int* __restrict__ am)
{
    const int bh = blockIdx.x;
    const int b = bh >> 4;
    const int h = bh & 15;
    __shared__ float qs[SS][DHH], ks[SS][DHH], vs[SS][DHH];
    __shared__ float sc[SS][SS + 1];
    const int tid = threadIdx.x;

    for (int i = tid; i < SS * DHH; i += 256) {
        const int s = i >> 6, d = i & 63;
        const size_t off = (size_t)(b * SS + s) * HHID + h * DHH + d;
        qs[s][d] = g_q[off];
        ks[s][d] = g_k[off];
        vs[s][d] = g_v[off];
    }
    __syncthreads();

    for (int i = tid; i < SS * SS; i += 256) {
        const int qq = i >> 5, kk = i & 31;
        float a = 0.f;
#pragma unroll
        for (int d = 0; d < DHH; d++) a += qs[qq][d] * ks[kk][d];
        const bool valid = (am[b * SS + qq] != 0) && (am[b * SS + kk] != 0);
        sc[qq][kk] = valid ? a * 0.125f : -1e9f;
    }
    __syncthreads();

    const int wid = tid >> 5, lane = tid & 31;
    for (int r = wid; r < SS; r += 8) {
        const float val = sc[r][lane];
        float m = val;
#pragma unroll
        for (int o = 16; o > 0; o >>= 1) m = fmaxf(m, __shfl_xor_sync(FULL, m, o));
        const float e = expf(val - m);
        float sum = e;
#pragma unroll
        for (int o = 16; o > 0; o >>= 1) sum += __shfl_xor_sync(FULL, sum, o);
        sc[r][lane] = e / sum;
    }
    __syncthreads();

    for (int i = tid; i < SS * DHH; i += 256) {
        const int qq = i >> 6, d = i & 63;
        float a = 0.f;
#pragma unroll
        for (int kk = 0; kk < SS; kk++) a += sc[qq][kk] * vs[kk][d];
        g_ctx[(size_t)(b * SS + qq) * HHID + h * DHH + d] = a;
    }
}

// ---------------- residual + LayerNorm ----------------
__global__ void __launch_bounds__(256)
resid_ln_kernel(const float* __restrict__ lng, const float* __restrict__ lnb)
{
    const int r = blockIdx.x;
    const int tid = threadIdx.x;
    const int d = tid * 4;
    const size_t base = (size_t)r * HHID + d;
    const float4 a = *(const float4*)&g_ao[base];
    const float4 f = *(const float4*)&g_feat[base];
    const float v0=a.x+f.x, v1=a.y+f.y, v2=a.z+f.z, v3=a.w+f.w;

    __shared__ float red[256];
    __shared__ float stats[2];
    red[tid] = v0+v1+v2+v3;
    __syncthreads();
    for (int st = 128; st > 0; st >>= 1) { if (tid < st) red[tid] += red[tid+st]; __syncthreads(); }
    if (tid == 0) stats[0] = red[0] * (1.f / HHID);
    __syncthreads();
    const float mean = stats[0];
    const float q0=v0-mean, q1=v1-mean, q2=v2-mean, q3=v3-mean;
    red[tid] = q0*q0+q1*q1+q2*q2+q3*q3;
    __syncthreads();
    for (int st = 128; st > 0; st >>= 1) { if (tid < st) red[tid] += red[tid+st]; __syncthreads(); }
    if (tid == 0) stats[1] = rsqrtf(red[0] * (1.f / HHID) + 1e-7f);
    __syncthreads();
    const float rstd = stats[1];
    float* out = &g_feat2[base];
    out[0] = q0*rstd*lng[d+0] + lnb[d+0];
    out[1] = q1*rstd*lng[d+1] + lnb[d+1];
    out[2] = q2*rstd*lng[d+2] + lnb[d+2];
    out[3] = q3*rstd*lng[d+3] + lnb[d+3];
}

// ---------------- classifier + per-span loss terms ----------------
__global__ void __launch_bounds__(128)
loss_terms_kernel(const int* __restrict__ labels, const float* __restrict__ wf,
                  const int* __restrict__ am,
                  const float* __restrict__ Wc, const float* __restrict__ bc)
{
    const int r = blockIdx.x;
    const int tid = threadIdx.x;
    const float* row = &g_feat2[(size_t)r * HHID];
    float d0=0, d1=0, d2=0;
    for (int i = tid; i < HHID; i += 128) {
        const float x = row[i];
        d0 += x * Wc[i*3+0];
        d1 += x * Wc[i*3+1];
        d2 += x * Wc[i*3+2];
    }
    __shared__ float r0[128], r1[128], r2[128];
    r0[tid]=d0; r1[tid]=d1; r2[tid]=d2;
    __syncthreads();
    for (int st = 64; st > 0; st >>= 1) {
        if (tid < st) { r0[tid]+=r0[tid+st]; r1[tid]+=r1[tid+st]; r2[tid]+=r2[tid+st]; }
        __syncthreads();
    }
    if (tid == 0) {
        const float z0 = r0[0]+bc[0], z1 = r1[0]+bc[1], z2 = r2[0]+bc[2];
        const float m = fmaxf(z0, fmaxf(z1, z2));
        const float e0 = expf(z0-m), e1 = expf(z1-m), e2 = expf(z2-m);
        const float lse = m + logf(e0+e1+e2);
        const int lab = labels[r];
        const bool valid = lab >= 0;
        const int lc = valid ? lab : 0;
        const float zl = (lc==0) ? z0 : ((lc==1) ? z1 : z2);
        const float logp = zl - lse;
        const float pt = expf(logp);
        const float spanm = ((am[r]!=0) && valid) ? 1.f : 0.f;
        const float vm = valid ? 1.f : 0.f;
        const float omp = 1.f - pt;
        g_terms[r*4+0] = (-logp * wf[r]) * spanm;
        g_terms[r*4+1] = spanm;
        g_terms[r*4+2] = (-(omp*omp) * logp) * vm;
        g_terms[r*4+3] = vm;
    }
}

__global__ void __launch_bounds__(256)
final_loss_kernel(float* __restrict__ out)
{
    const int tid = threadIdx.x;
    float a0=0,a1=0,a2=0,a3=0;
    for (int r = tid; r < BB*SS; r += 256) {
        a0 += g_terms[r*4+0]; a1 += g_terms[r*4+1];
        a2 += g_terms[r*4+2]; a3 += g_terms[r*4+3];
    }
    __shared__ float s0[256], s1[256], s2[256], s3[256];
    s0[tid]=a0; s1[tid]=a1; s2[tid]=a2; s3[tid]=a3;
    __syncthreads();
    for (int st = 128; st > 0; st >>= 1) {
        if (tid < st) { s0[tid]+=s0[tid+st]; s1[tid]+=s1[tid+st]; s2[tid]+=s2[tid+st]; s3[tid]+=s3[tid+st]; }
        __syncthreads();
    }
    if (tid == 0)
        out[0] = s0[0] / fmaxf(s1[0], 1.f) + s2[0] / fmaxf(s3[0], 1.f);
}

// ---------------- launch ----------------
extern "C" void kernel_launch(void* const* d_in, const int* in_sizes, int n_in,
                              void* d_out, int out_size)
{
    const float* hs     = (const float*)d_in[0];
    const int*   heads  = (const int*)  d_in[1];
    const int*   tails  = (const int*)  d_in[2];
    const int*   am     = (const int*)  d_in[3];
    const int*   labels = (const int*)  d_in[4];
    const float* wf     = (const float*)d_in[5];
    const float* Wih_f  = (const float*)d_in[6];
    const float* Whh_f  = (const float*)d_in[7];
    const float* b_f    = (const float*)d_in[8];
    const float* Wih_b  = (const float*)d_in[9];
    const float* Whh_b  = (const float*)d_in[10];
    const float* b_b    = (const float*)d_in[11];
    const float* ln1g   = (const float*)d_in[12];
    const float* ln1b   = (const float*)d_in[13];
    const float* Wq     = (const float*)d_in[14];
    const float* bq     = (const float*)d_in[15];
    const float* Wk     = (const float*)d_in[16];
    const float* bk     = (const float*)d_in[17];
    const float* Wv     = (const float*)d_in[18];
    const float* bv     = (const float*)d_in[19];
    const float* Wo     = (const float*)d_in[20];
    const float* bo     = (const float*)d_in[21];
    const float* ln2g   = (const float*)d_in[22];
    const float* ln2b   = (const float*)d_in[23];
    const float* Wc     = (const float*)d_in[24];
    const float* bc     = (const float*)d_in[25];

    float *p_xs_f, *p_xs_b, *p_feat, *p_q, *p_k, *p_v, *p_ctx, *p_ao, *p_wt;
    cudaGetSymbolAddress((void**)&p_xs_f,  g_xs_f);
    cudaGetSymbolAddress((void**)&p_xs_b,  g_xs_b);
    cudaGetSymbolAddress((void**)&p_feat,  g_feat);
    cudaGetSymbolAddress((void**)&p_q,     g_q);
    cudaGetSymbolAddress((void**)&p_k,     g_k);
    cudaGetSymbolAddress((void**)&p_v,     g_v);
    cudaGetSymbolAddress((void**)&p_ctx,   g_ctx);
    cudaGetSymbolAddress((void**)&p_ao,    g_ao);
    cudaGetSymbolAddress((void**)&p_wt,    g_wt);

    // index 0: init (loss terms + barrier counters)
    init_kernel<<<8, 256>>>();

    // input projections: tf32, 3-stage pipeline
    {
        dim3 grid(G4/128, (BB*TT)/128), blk(256);
        tf32_gemm_tn<<<grid, blk>>>(hs, Wih_f, b_f, p_xs_f, BB*TT, G4, HHID);
        tf32_gemm_tn<<<grid, blk>>>(hs, Wih_b, b_b, p_xs_b, BB*TT, G4, HHID);
    }

    // index 3: persistent bidirectional scan (R10 config: 128 CTAs)
    lstm_scan_kernel<<<128, 256>>>(Whh_f, Whh_b);

    // transpose QKV/O weights
    {
        dim3 grid(32, 32), blk(256);
        transpose_kernel<<<grid, blk>>>(Wq, p_wt + 0 * HHID * HHID);
        transpose_kernel<<<grid, blk>>>(Wk, p_wt + 1 * HHID * HHID);
        transpose_kernel<<<grid, blk>>>(Wv, p_wt + 2 * HHID * HHID);
        transpose_kernel<<<grid, blk>>>(Wo, p_wt + 3 * HHID * HHID);
    }

    // span pool + LN1
    span_pool_ln_kernel<<<BB*SS, 256>>>(heads, tails, ln1g, ln1b);

    // q,k,v
    {
        dim3 grid(HHID/128, (BB*SS)/128), blk(256);
        tf32_gemm_tn<<<grid, blk>>>(p_feat, p_wt + 0 * HHID * HHID, bq, p_q, BB*SS, HHID, HHID);
        tf32_gemm_tn<<<grid, blk>>>(p_feat, p_wt + 1 * HHID * HHID, bk, p_k, BB*SS, HHID, HHID);
        tf32_gemm_tn<<<grid, blk>>>(p_feat, p_wt + 2 * HHID * HHID, bv, p_v, BB*SS, HHID, HHID);
    }

    attn_kernel<<<BB*NHH, 256>>>(am);

    {
        dim3 grid(HHID/128, (BB*SS)/128), blk(256);
        tf32_gemm_tn<<<grid, blk>>>(p_ctx, p_wt + 3 * HHID * HHID, bo, p_ao, BB*SS, HHID, HHID);
    }

    resid_ln_kernel<<<BB*SS, 256>>>(ln2g, ln2b);

    loss_terms_kernel<<<BB*SS, 128>>>(labels, wf, am, Wc, bc);

    final_loss_kernel<<<1, 256>>>((float*)d_out);
}

// round 13
// speedup vs baseline: 1.0819x; 1.0050x over previous
#include <cuda_runtime.h>
#include <math.h>

#define FULL 0xffffffffu
#define BB   16
#define TT   1024
#define HHID 1024
#define SS   32
#define CC   3
#define NHH  16
#define DHH  64
#define HH2  512
#define G4   2048

// ---------------- scratch ----------------
__device__ float g_xs_f[BB*TT*G4];
__device__ float g_xs_b[BB*TT*G4];
__device__ float g_enc [BB*TT*HHID];
__device__ float g_feat [BB*SS*HHID];
__device__ float g_q    [BB*SS*HHID];
__device__ float g_k    [BB*SS*HHID];
__device__ float g_v    [BB*SS*HHID];
__device__ float g_ctx  [BB*SS*HHID];
__device__ float g_ao   [BB*SS*HHID];
__device__ float g_feat2[BB*SS*HHID];
__device__ float g_terms[BB*SS*4];
__device__ float g_wt[4][HHID*HHID];

// monotonic per-direction barrier counters, own 128B lines
struct __align__(128) PadCtr { unsigned v; unsigned pad[31]; };
__device__ PadCtr g_ctr[2];

// ---------------- monotonic flat barrier ----------------
__device__ __forceinline__ void dir_barrier_mono(int dir, unsigned target)
{
    __syncthreads();
    if (threadIdx.x == 0) {
        unsigned* ctr = &g_ctr[dir].v;
        asm volatile("red.release.gpu.global.add.u32 [%0], %1;" :: "l"(ctr), "r"(1u) : "memory");
        unsigned v;
        do {
            asm volatile("ld.acquire.gpu.global.u32 %0, [%1];" : "=r"(v) : "l"(ctr) : "memory");
        } while (v < target);
    }
    __syncthreads();
}

// ---------------- init kernel ----------------
__global__ void init_kernel()
{
    const int i = blockIdx.x * blockDim.x + threadIdx.x;
    if (i < BB * SS * 4) g_terms[i] = 0.f;
    if (i == 0) { g_ctr[0].v = 0u; g_ctr[1].v = 0u; }
}

// ---------------- cp.async helpers ----------------
__device__ __forceinline__ void cp_async16(unsigned saddr, const void* gptr)
{
    asm volatile("cp.async.cg.shared.global [%0], [%1], 16;" :: "r"(saddr), "l"(gptr));
}
__device__ __forceinline__ void cp_commit() { asm volatile("cp.async.commit_group;"); }
template<int N>
__device__ __forceinline__ void cp_wait() { asm volatile("cp.async.wait_group %0;" :: "n"(N)); }

// ---------------- tf32 mma helpers ----------------
__device__ __forceinline__ void ldsm_x4(unsigned& r0, unsigned& r1, unsigned& r2, unsigned& r3,
                                        unsigned saddr)
{
    asm volatile("ldmatrix.sync.aligned.m8n8.x4.shared.b16 {%0,%1,%2,%3}, [%4];"
                 : "=r"(r0), "=r"(r1), "=r"(r2), "=r"(r3) : "r"(saddr));
}
__device__ __forceinline__ void mma_tf32(float* c, unsigned a0, unsigned a1, unsigned a2, unsigned a3,
                                         unsigned b0, unsigned b1)
{
    asm volatile(
        "mma.sync.aligned.m16n8k8.row.col.f32.tf32.tf32.f32 "
        "{%0,%1,%2,%3}, {%4,%5,%6,%7}, {%8,%9}, {%0,%1,%2,%3};"
        : "+f"(c[0]), "+f"(c[1]), "+f"(c[2]), "+f"(c[3])
        : "r"(a0), "r"(a1), "r"(a2), "r"(a3), "r"(b0), "r"(b1));
}

// ---------------- tf32 GEMM: C[M,N] = A[M,K] @ B[N,K]^T + bias  (2-stage, R10-exact) ----------------
#define PAD 20
__global__ void __launch_bounds__(256)
tf32_gemm_tn(const float* __restrict__ A, const float* __restrict__ B,
             const float* __restrict__ bias, float* __restrict__ C,
             int M, int N, int K)
{
    __shared__ float As[2][128][PAD];
    __shared__ float Bs[2][128][PAD];
    const int tid  = threadIdx.x;
    const int warp = tid >> 5;
    const int lane = tid & 31;
    const int wm   = warp >> 2;
    const int wn   = warp & 3;
    const int bm   = blockIdx.y * 128;
    const int bn   = blockIdx.x * 128;

    float c[4][4][4];
#pragma unroll
    for (int i = 0; i < 4; i++)
#pragma unroll
        for (int j = 0; j < 4; j++)
#pragma unroll
            for (int r = 0; r < 4; r++) c[i][j][r] = 0.f;

    const int lr = tid >> 1;
    const int cc = (tid & 1) * 8;

    const float* Ag = A + (size_t)(bm + lr) * K + cc;
    const float* Bg = B + (size_t)(bn + lr) * K + cc;

    const unsigned sA0 = (unsigned)__cvta_generic_to_shared(&As[0][lr][cc]);
    const unsigned sA1 = (unsigned)__cvta_generic_to_shared(&As[1][lr][cc]);
    const unsigned sB0 = (unsigned)__cvta_generic_to_shared(&Bs[0][lr][cc]);
    const unsigned sB1 = (unsigned)__cvta_generic_to_shared(&Bs[1][lr][cc]);

    const int fr = lane & 15;
    const int fc = ((lane >> 4) << 2);

    cp_async16(sA0,      Ag);
    cp_async16(sA0 + 16, Ag + 4);
    cp_async16(sB0,      Bg);
    cp_async16(sB0 + 16, Bg + 4);
    cp_commit();

    const int KT = K / 16;
    for (int kt = 0; kt < KT; kt++) {
        const int cur = kt & 1;
        if (kt + 1 < KT) {
            const float* Ap = Ag + (size_t)(kt + 1) * 16;
            const float* Bp = Bg + (size_t)(kt + 1) * 16;
            const unsigned dA = cur ? sA0 : sA1;
            const unsigned dB = cur ? sB0 : sB1;
            cp_async16(dA,      Ap);
            cp_async16(dA + 16, Ap + 4);
            cp_async16(dB,      Bp);
            cp_async16(dB + 16, Bp + 4);
            cp_commit();
            cp_wait<1>();
        } else {
            cp_wait<0>();
        }
        __syncthreads();

#pragma unroll
        for (int ks = 0; ks < 2; ks++) {
            const int k0 = ks * 8 + fc;
            unsigned b0a, b1a, b2a, b3a, b0b, b1b, b2b, b3b;
            {
                unsigned sa = (unsigned)__cvta_generic_to_shared(&Bs[cur][wn*32 + fr][k0]);
                ldsm_x4(b0a, b1a, b2a, b3a, sa);
                unsigned sb = (unsigned)__cvta_generic_to_shared(&Bs[cur][wn*32 + 16 + fr][k0]);
                ldsm_x4(b0b, b1b, b2b, b3b, sb);
            }
#pragma unroll
            for (int mf = 0; mf < 4; mf++) {
                unsigned a0, a1, a2, a3;
                unsigned sa = (unsigned)__cvta_generic_to_shared(&As[cur][wm*64 + mf*16 + fr][k0]);
                ldsm_x4(a0, a1, a2, a3, sa);
                mma_tf32(c[mf][0], a0, a1, a2, a3, b0a, b2a);
                mma_tf32(c[mf][1], a0, a1, a2, a3, b1a, b3a);
                mma_tf32(c[mf][2], a0, a1, a2, a3, b0b, b2b);
                mma_tf32(c[mf][3], a0, a1, a2, a3, b1b, b3b);
            }
        }
        __syncthreads();
    }

    const int g  = lane >> 2;
    const int tg = lane & 3;
#pragma unroll
    for (int mf = 0; mf < 4; mf++) {
        const int row0 = bm + wm*64 + mf*16 + g;
#pragma unroll
        for (int nf = 0; nf < 4; nf++) {
            const int col0 = bn + wn*32 + nf*8 + 2*tg;
            const float2 bv = *(const float2*)&bias[col0];
            float2 v0 = make_float2(c[mf][nf][0] + bv.x, c[mf][nf][1] + bv.y);
            float2 v1 = make_float2(c[mf][nf][2] + bv.x, c[mf][nf][3] + bv.y);
            *(float2*)&C[(size_t)row0 * N + col0]       = v0;
            *(float2*)&C[(size_t)(row0 + 8) * N + col0] = v1;
        }
    }
}

// ---------------- 1024x1024 transpose ----------------
__global__ void __launch_bounds__(256)
transpose_kernel(const float* __restrict__ in, float* __restrict__ out)
{
    __shared__ float tile[32][33];
    const int bx = blockIdx.x * 32, by = blockIdx.y * 32;
    const int tx = threadIdx.x & 31, ty4 = (threadIdx.x >> 5) * 4;
#pragma unroll
    for (int r = 0; r < 4; r++)
        tile[ty4 + r][tx] = in[(size_t)(by + ty4 + r) * HHID + bx + tx];
    __syncthreads();
#pragma unroll
    for (int r = 0; r < 4; r++)
        out[(size_t)(bx + ty4 + r) * HHID + by + tx] = tile[tx][ty4 + r];
}

// ---------------- persistent bidirectional LSTM scan (128 CTAs, h via g_enc) ----------------
#define HPAD 516
__global__ void __launch_bounds__(256)
lstm_scan_kernel(const float* __restrict__ Whh_f, const float* __restrict__ Whh_b)
{
    __shared__ float h_sh[16 * HPAD];
    __shared__ float red[4][32][18];

    const int cid  = blockIdx.x;
    const int dir  = cid >> 6;
    const int ug   = cid & 63;
    const int U0   = ug * 8;
    const int tid  = threadIdx.x;
    const int w    = tid >> 5;
    const int lane = tid & 31;
    const int rg   = w >> 2;
    const int ksl  = w & 3;
    const int kb   = ksl * 128;
    const int qr   = lane >> 2;
    const int qc   = lane & 3;
    const int r_lo = rg * 16 + qr;
    const int r_hi = r_lo + 8;
    const int fr   = lane & 15;
    const int fc   = (lane >> 4) << 2;

    const float* __restrict__ Whh = dir ? Whh_b : Whh_f;
    const float* __restrict__ xs  = dir ? g_xs_b : g_xs_f;

    // persistent A fragments
    unsigned a[16][4];
    {
        const int grow_lo = (r_lo >> 3) * HH2 + U0 + (r_lo & 7);
        const int grow_hi = (r_hi >> 3) * HH2 + U0 + (r_hi & 7);
        const float* Wlo = Whh + (size_t)grow_lo * HH2;
        const float* Whi = Whh + (size_t)grow_hi * HH2;
#pragma unroll
        for (int j = 0; j < 16; j++) {
            const int k0 = kb + j * 8 + qc;
            a[j][0] = __float_as_uint(Wlo[k0]);
            a[j][1] = __float_as_uint(Whi[k0]);
            a[j][2] = __float_as_uint(Wlo[k0 + 4]);
            a[j][3] = __float_as_uint(Whi[k0 + 4]);
        }
    }

    const int cb = tid >> 3;
    const int cu = tid & 7;
    float c_state = 0.f;

    for (int s = 0; s < TT; s++) {
        const int t = dir ? (TT - 1 - s) : s;

        float xp0 = 0.f, xp1 = 0.f, xp2 = 0.f, xp3 = 0.f;
        if (tid < 128) {
            const size_t xb = ((size_t)(cb * TT + t)) * G4 + U0 + cu;
            xp0 = xs[xb];
            xp1 = xs[xb + 512];
            xp2 = xs[xb + 1024];
            xp3 = xs[xb + 1536];
        }

        if (s == 0) {
            for (int i = tid; i < 16 * HPAD; i += 256) h_sh[i] = 0.f;
        } else {
            // previous h lives in g_enc at time t_prev (contiguous 512 floats per batch)
            const int tp = dir ? (t + 1) : (t - 1);
            for (int idx = tid * 4; idx < BB * HH2; idx += 1024) {
                const int b = idx >> 9, k = idx & 511;
                const float4 v = __ldcg((const float4*)&g_enc[((size_t)(b * TT + tp)) * HHID + dir * HH2 + k]);
                *(float4*)&h_sh[b * HPAD + k] = v;
            }
        }
        __syncthreads();

        float cl0[4] = {0,0,0,0}, cl1[4] = {0,0,0,0};
        float ch0[4] = {0,0,0,0}, ch1[4] = {0,0,0,0};
#pragma unroll
        for (int j = 0; j < 16; j += 2) {
            {
                const int k0 = kb + j * 8 + fc;
                unsigned m0, m1, m2, m3;
                const unsigned sa = (unsigned)__cvta_generic_to_shared(&h_sh[fr * HPAD + k0]);
                ldsm_x4(m0, m1, m2, m3, sa);
                mma_tf32(cl0, a[j][0], a[j][1], a[j][2], a[j][3], m0, m2);
                mma_tf32(ch0, a[j][0], a[j][1], a[j][2], a[j][3], m1, m3);
            }
            {
                const int k0 = kb + (j + 1) * 8 + fc;
                unsigned m0, m1, m2, m3;
                const unsigned sa = (unsigned)__cvta_generic_to_shared(&h_sh[fr * HPAD + k0]);
                ldsm_x4(m0, m1, m2, m3, sa);
                mma_tf32(cl1, a[j+1][0], a[j+1][1], a[j+1][2], a[j+1][3], m0, m2);
                mma_tf32(ch1, a[j+1][0], a[j+1][1], a[j+1][2], a[j+1][3], m1, m3);
            }
        }

        *(float2*)&red[ksl][r_lo][2 * qc]     = make_float2(cl0[0]+cl1[0], cl0[1]+cl1[1]);
        *(float2*)&red[ksl][r_hi][2 * qc]     = make_float2(cl0[2]+cl1[2], cl0[3]+cl1[3]);
        *(float2*)&red[ksl][r_lo][8 + 2 * qc] = make_float2(ch0[0]+ch1[0], ch0[1]+ch1[1]);
        *(float2*)&red[ksl][r_hi][8 + 2 * qc] = make_float2(ch0[2]+ch1[2], ch0[3]+ch1[3]);
        __syncthreads();

        if (tid < 128) {
            const int r0 = 0 * 8 + cu, r1 = 1 * 8 + cu, r2 = 2 * 8 + cu, r3 = 3 * 8 + cu;
            const float zi = red[0][r0][cb] + red[1][r0][cb] + red[2][r0][cb] + red[3][r0][cb] + xp0;
            const float zf = red[0][r1][cb] + red[1][r1][cb] + red[2][r1][cb] + red[3][r1][cb] + xp1;
            const float zg = red[0][r2][cb] + red[1][r2][cb] + red[2][r2][cb] + red[3][r2][cb] + xp2;
            const float zo = red[0][r3][cb] + red[1][r3][cb] + red[2][r3][cb] + red[3][r3][cb] + xp3;
            const float is = 1.f / (1.f + expf(-zi));
            const float fs = 1.f / (1.f + expf(-zf));
            const float gv = tanhf(zg);
            const float os = 1.f / (1.f + expf(-zo));
            c_state = fs * c_state + is * gv;
            const float hn = os * tanhf(c_state);
            __stcg(&g_enc[((size_t)(cb * TT + t)) * HHID + dir * HH2 + U0 + cu], hn);
        }

        dir_barrier_mono(dir, 64u * (unsigned)(s + 1));
    }
}

// ---------------- span mean-pool + LayerNorm ----------------
__global__ void __launch_bounds__(256)
span_pool_ln_kernel(const int* __restrict__ heads, const int* __restrict__ tails,
                    const float* __restrict__ lng, const float* __restrict__ lnb)
{
    const int r = blockIdx.x;
    const int b = r >> 5;
    int p0 = heads[r] + 1; if (p0 < 0) p0 = 0;
    int p1 = tails[r];     if (p1 > TT) p1 = TT;
    const int tid = threadIdx.x;
    const int d = tid * 4;

    float s0=0,s1=0,s2=0,s3=0;
    for (int p = p0; p < p1; p++) {
        const float4 vv = *(const float4*)&g_enc[(size_t)(b * TT + p) * HHID + d];
        s0 += vv.x; s1 += vv.y; s2 += vv.z; s3 += vv.w;
    }
    int cnt = p1 - p0; if (cnt < 1) cnt = 1;
    const float inv = 1.f / (float)cnt;
    const float v0=s0*inv, v1=s1*inv, v2=s2*inv, v3=s3*inv;

    __shared__ float red[256];
    __shared__ float stats[2];
    red[tid] = v0+v1+v2+v3;
    __syncthreads();
    for (int st = 128; st > 0; st >>= 1) { if (tid < st) red[tid] += red[tid+st]; __syncthreads(); }
    if (tid == 0) stats[0] = red[0] * (1.f / HHID);
    __syncthreads();
    const float mean = stats[0];
    const float q0=v0-mean, q1=v1-mean, q2=v2-mean, q3=v3-mean;
    red[tid] = q0*q0+q1*q1+q2*q2+q3*q3;
    __syncthreads();
    for (int st = 128; st > 0; st >>= 1) { if (tid < st) red[tid] += red[tid+st]; __syncthreads(); }
    if (tid == 0) stats[1] = rsqrtf(red[0] * (1.f / HHID) + 1e-7f);
    __syncthreads();
    const float rstd = stats[1];
    float* out = &g_feat[(size_t)r * HHID + d];
    out[0] = q0*rstd*lng[d+0] + lnb[d+0];
    out[1] = q1*rstd*lng[d+1] + lnb[d+1];
    out[2] = q2*rstd*lng[d+2] + lnb[d+2];
    out[3] = q3*rstd*lng[d+3] + lnb[d+3];
}

// ---------------- attention ----------------
__global__ void __launch_bounds__(256)
attn_kernel(const int* __restrict__ am)
{
    const int bh = blockIdx.x;
    const int b = bh >> 4;
    const int h = bh & 15;
    __shared__ float qs[SS][DHH], ks[SS][DHH], vs[SS][DHH];
    __shared__ float sc[SS][SS + 1];
    const int tid = threadIdx.x;

    for (int i = tid; i < SS * DHH; i += 256) {
        const int s = i >> 6, d = i & 63;
        const size_t off = (size_t)(b * SS + s) * HHID + h * DHH + d;
        qs[s][d] = g_q[off];
        ks[s][d] = g_k[off];
        vs[s][d] = g_v[off];
    }
    __syncthreads();

    for (int i = tid; i < SS * SS; i += 256) {
        const int qq = i >> 5, kk = i & 31;
        float a = 0.f;
#pragma unroll
        for (int d = 0; d < DHH; d++) a += qs[qq][d] * ks[kk][d];
        const bool valid = (am[b * SS + qq] != 0) && (am[b * SS + kk] != 0);
        sc[qq][kk] = valid ? a * 0.125f : -1e9f;
    }
    __syncthreads();

    const int wid = tid >> 5, lane = tid & 31;
    for (int r = wid; r < SS; r += 8) {
        const float val = sc[r][lane];
        float m = val;
#pragma unroll
        for (int o = 16; o > 0; o >>= 1) m = fmaxf(m, __shfl_xor_sync(FULL, m, o));
        const float e = expf(val - m);
        float sum = e;
#pragma unroll
        for (int o = 16; o > 0; o >>= 1) sum += __shfl_xor_sync(FULL, sum, o);
        sc[r][lane] = e / sum;
    }
    __syncthreads();

    for (int i = tid; i < SS * DHH; i += 256) {
        const int qq = i >> 6, d = i & 63;
        float a = 0.f;
#pragma unroll
        for (int kk = 0; kk < SS; kk++) a += sc[qq][kk] * vs[kk][d];
        g_ctx[(size_t)(b * SS + qq) * HHID + h * DHH + d] = a;
    }
}

// ---------------- residual + LayerNorm ----------------
__global__ void __launch_bounds__(256)
resid_ln_kernel(const float* __restrict__ lng, const float* __restrict__ lnb)
{
    const int r = blockIdx.x;
    const int tid = threadIdx.x;
    const int d = tid * 4;
    const size_t base = (size_t)r * HHID + d;
    const float4 a = *(const float4*)&g_ao[base];
    const float4 f = *(const float4*)&g_feat[base];
    const float v0=a.x+f.x, v1=a.y+f.y, v2=a.z+f.z, v3=a.w+f.w;

    __shared__ float red[256];
    __shared__ float stats[2];
    red[tid] = v0+v1+v2+v3;
    __syncthreads();
    for (int st = 128; st > 0; st >>= 1) { if (tid < st) red[tid] += red[tid+st]; __syncthreads(); }
    if (tid == 0) stats[0] = red[0] * (1.f / HHID);
    __syncthreads();
    const float mean = stats[0];
    const float q0=v0-mean, q1=v1-mean, q2=v2-mean, q3=v3-mean;
    red[tid] = q0*q0+q1*q1+q2*q2+q3*q3;
    __syncthreads();
    for (int st = 128; st > 0; st >>= 1) { if (tid < st) red[tid] += red[tid+st]; __syncthreads(); }
    if (tid == 0) stats[1] = rsqrtf(red[0] * (1.f / HHID) + 1e-7f);
    __syncthreads();
    const float rstd = stats[1];
    float* out = &g_feat2[base];
    out[0] = q0*rstd*lng[d+0] + lnb[d+0];
    out[1] = q1*rstd*lng[d+1] + lnb[d+1];
    out[2] = q2*rstd*lng[d+2] + lnb[d+2];
    out[3] = q3*rstd*lng[d+3] + lnb[d+3];
}

// ---------------- classifier + per-span loss terms ----------------
__global__ void __launch_bounds__(128)
loss_terms_kernel(const int* __restrict__ labels, const float* __restrict__ wf,
                  const int* __restrict__ am,
                  const float* __restrict__ Wc, const float* __restrict__ bc)
{
    const int r = blockIdx.x;
    const int tid = threadIdx.x;
    const float* row = &g_feat2[(size_t)r * HHID];
    float d0=0, d1=0, d2=0;
    for (int i = tid; i < HHID; i += 128) {
        const float x = row[i];
        d0 += x * Wc[i*3+0];
        d1 += x * Wc[i*3+1];
        d2 += x * Wc[i*3+2];
    }
    __shared__ float r0[128], r1[128], r2[128];
    r0[tid]=d0; r1[tid]=d1; r2[tid]=d2;
    __syncthreads();
    for (int st = 64; st > 0; st >>= 1) {
        if (tid < st) { r0[tid]+=r0[tid+st]; r1[tid]+=r1[tid+st]; r2[tid]+=r2[tid+st]; }
        __syncthreads();
    }
    if (tid == 0) {
        const float z0 = r0[0]+bc[0], z1 = r1[0]+bc[1], z2 = r2[0]+bc[2];
        const float m = fmaxf(z0, fmaxf(z1, z2));
        const float e0 = expf(z0-m), e1 = expf(z1-m), e2 = expf(z2-m);
        const float lse = m + logf(e0+e1+e2);
        const int lab = labels[r];
        const bool valid = lab >= 0;
        const int lc = valid ? lab : 0;
        const float zl = (lc==0) ? z0 : ((lc==1) ? z1 : z2);
        const float logp = zl - lse;
        const float pt = expf(logp);
        const float spanm = ((am[r]!=0) && valid) ? 1.f : 0.f;
        const float vm = valid ? 1.f : 0.f;
        const float omp = 1.f - pt;
        g_terms[r*4+0] = (-logp * wf[r]) * spanm;
        g_terms[r*4+1] = spanm;
        g_terms[r*4+2] = (-(omp*omp) * logp) * vm;
        g_terms[r*4+3] = vm;
    }
}

__global__ void __launch_bounds__(256)
final_loss_kernel(float* __restrict__ out)
{
    const int tid = threadIdx.x;
    float a0=0,a1=0,a2=0,a3=0;
    for (int r = tid; r < BB*SS; r += 256) {
        a0 += g_terms[r*4+0]; a1 += g_terms[r*4+1];
        a2 += g_terms[r*4+2]; a3 += g_terms[r*4+3];
    }
    __shared__ float s0[256], s1[256], s2[256], s3[256];
    s0[tid]=a0; s1[tid]=a1; s2[tid]=a2; s3[tid]=a3;
    __syncthreads();
    for (int st = 128; st > 0; st >>= 1) {
        if (tid < st) { s0[tid]+=s0[tid+st]; s1[tid]+=s1[tid+st]; s2[tid]+=s2[tid+st]; s3[tid]+=s3[tid+st]; }
        __syncthreads();
    }
    if (tid == 0)
        out[0] = s0[0] / fmaxf(s1[0], 1.f) + s2[0] / fmaxf(s3[0], 1.f);
}

// ---------------- launch ----------------
extern "C" void kernel_launch(void* const* d_in, const int* in_sizes, int n_in,
                              void* d_out, int out_size)
{
    const float* hs     = (const float*)d_in[0];
    const int*   heads  = (const int*)  d_in[1];
    const int*   tails  = (const int*)  d_in[2];
    const int*   am     = (const int*)  d_in[3];
    const int*   labels = (const int*)  d_in[4];
    const float* wf     = (const float*)d_in[5];
    const float* Wih_f  = (const float*)d_in[6];
    const float* Whh_f  = (const float*)d_in[7];
    const float* b_f    = (const float*)d_in[8];
    const float* Wih_b  = (const float*)d_in[9];
    const float* Whh_b  = (const float*)d_in[10];
    const float* b_b    = (const float*)d_in[11];
    const float* ln1g   = (const float*)d_in[12];
    const float* ln1b   = (const float*)d_in[13];
    const float* Wq     = (const float*)d_in[14];
    const float* bq     = (const float*)d_in[15];
    const float* Wk     = (const float*)d_in[16];
    const float* bk     = (const float*)d_in[17];
    const float* Wv     = (const float*)d_in[18];
    const float* bv     = (const float*)d_in[19];
    const float* Wo     = (const float*)d_in[20];
    const float* bo     = (const float*)d_in[21];
    const float* ln2g   = (const float*)d_in[22];
    const float* ln2b   = (const float*)d_in[23];
    const float* Wc     = (const float*)d_in[24];
    const float* bc     = (const float*)d_in[25];

    float *p_xs_f, *p_xs_b, *p_feat, *p_q, *p_k, *p_v, *p_ctx, *p_ao, *p_wt;
    cudaGetSymbolAddress((void**)&p_xs_f,  g_xs_f);
    cudaGetSymbolAddress((void**)&p_xs_b,  g_xs_b);
    cudaGetSymbolAddress((void**)&p_feat,  g_feat);
    cudaGetSymbolAddress((void**)&p_q,     g_q);
    cudaGetSymbolAddress((void**)&p_k,     g_k);
    cudaGetSymbolAddress((void**)&p_v,     g_v);
    cudaGetSymbolAddress((void**)&p_ctx,   g_ctx);
    cudaGetSymbolAddress((void**)&p_ao,    g_ao);
    cudaGetSymbolAddress((void**)&p_wt,    g_wt);

    // index 0: init (loss terms + barrier counters)
    init_kernel<<<8, 256>>>();

    // input projections: tf32, 2-stage (R10-exact)
    {
        dim3 grid(G4/128, (BB*TT)/128), blk(256);
        tf32_gemm_tn<<<grid, blk>>>(hs, Wih_f, b_f, p_xs_f, BB*TT, G4, HHID);
        tf32_gemm_tn<<<grid, blk>>>(hs, Wih_b, b_b, p_xs_b, BB*TT, G4, HHID);
    }

    // index 3: persistent bidirectional scan (128 CTAs, h via g_enc)
    lstm_scan_kernel<<<128, 256>>>(Whh_f, Whh_b);

    // transpose QKV/O weights
    {
        dim3 grid(32, 32), blk(256);
        transpose_kernel<<<grid, blk>>>(Wq, p_wt + 0 * HHID * HHID);
        transpose_kernel<<<grid, blk>>>(Wk, p_wt + 1 * HHID * HHID);
        transpose_kernel<<<grid, blk>>>(Wv, p_wt + 2 * HHID * HHID);
        transpose_kernel<<<grid, blk>>>(Wo, p_wt + 3 * HHID * HHID);
    }

    // span pool + LN1
    span_pool_ln_kernel<<<BB*SS, 256>>>(heads, tails, ln1g, ln1b);

    // q,k,v
    {
        dim3 grid(HHID/128, (BB*SS)/128), blk(256);
        tf32_gemm_tn<<<grid, blk>>>(p_feat, p_wt + 0 * HHID * HHID, bq, p_q, BB*SS, HHID, HHID);
        tf32_gemm_tn<<<grid, blk>>>(p_feat, p_wt + 1 * HHID * HHID, bk, p_k, BB*SS, HHID, HHID);
        tf32_gemm_tn<<<grid, blk>>>(p_feat, p_wt + 2 * HHID * HHID, bv, p_v, BB*SS, HHID, HHID);
    }

    attn_kernel<<<BB*NHH, 256>>>(am);

    {
        dim3 grid(HHID/128, (BB*SS)/128), blk(256);
        tf32_gemm_tn<<<grid, blk>>>(p_ctx, p_wt + 3 * HHID * HHID, bo, p_ao, BB*SS, HHID, HHID);
    }

    resid_ln_kernel<<<BB*SS, 256>>>(ln2g, ln2b);

    loss_terms_kernel<<<BB*SS, 128>>>(labels, wf, am, Wc, bc);

    final_loss_kernel<<<1, 256>>>((float*)d_out);
}

// round 14
// speedup vs baseline: 1.1186x; 1.0339x over previous
#include <cuda_runtime.h>
#include <math.h>

#define FULL 0xffffffffu
#define BB   16
#define TT   1024
#define HHID 1024
#define SS   32
#define CC   3
#define NHH  16
#define DHH  64
#define HH2  512
#define G4   2048

// ---------------- scratch ----------------
__device__ float g_xs_f[BB*TT*G4];
__device__ float g_xs_b[BB*TT*G4];
__device__ float g_enc [BB*TT*HHID];
__device__ float g_hbuf[2][2][BB][HH2];
__device__ float g_feat [BB*SS*HHID];
__device__ float g_q    [BB*SS*HHID];
__device__ float g_k    [BB*SS*HHID];
__device__ float g_v    [BB*SS*HHID];
__device__ float g_ctx  [BB*SS*HHID];
__device__ float g_ao   [BB*SS*HHID];
__device__ float g_feat2[BB*SS*HHID];
__device__ float g_terms[BB*SS*4];
__device__ float g_wt[4][HHID*HHID];

// monotonic per-direction barrier counters, own 128B lines
struct __align__(128) PadCtr { unsigned v; unsigned pad[31]; };
__device__ PadCtr g_ctr[2];

// ---------------- fast activation helpers ----------------
__device__ __forceinline__ float fast_sigmoid(float x)
{
    return __fdividef(1.f, 1.f + __expf(-x));
}
__device__ __forceinline__ float fast_tanh(float x)
{
    const float e2 = __expf(2.f * x);
    return __fdividef(e2 - 1.f, e2 + 1.f);
}

// ---------------- monotonic flat barrier ----------------
__device__ __forceinline__ void dir_barrier_mono(int dir, unsigned target)
{
    __syncthreads();
    if (threadIdx.x == 0) {
        unsigned* ctr = &g_ctr[dir].v;
        asm volatile("red.release.gpu.global.add.u32 [%0], %1;" :: "l"(ctr), "r"(1u) : "memory");
        unsigned v;
        do {
            asm volatile("ld.acquire.gpu.global.u32 %0, [%1];" : "=r"(v) : "l"(ctr) : "memory");
        } while (v < target);
    }
    __syncthreads();
}

// ---------------- init kernel ----------------
__global__ void init_kernel()
{
    const int i = blockIdx.x * blockDim.x + threadIdx.x;
    if (i < BB * SS * 4) g_terms[i] = 0.f;
    if (i == 0) { g_ctr[0].v = 0u; g_ctr[1].v = 0u; }
}

// ---------------- cp.async helpers ----------------
__device__ __forceinline__ void cp_async16(unsigned saddr, const void* gptr)
{
    asm volatile("cp.async.cg.shared.global [%0], [%1], 16;" :: "r"(saddr), "l"(gptr));
}
__device__ __forceinline__ void cp_commit() { asm volatile("cp.async.commit_group;"); }
template<int N>
__device__ __forceinline__ void cp_wait() { asm volatile("cp.async.wait_group %0;" :: "n"(N)); }

// ---------------- tf32 mma helpers ----------------
__device__ __forceinline__ void ldsm_x4(unsigned& r0, unsigned& r1, unsigned& r2, unsigned& r3,
                                        unsigned saddr)
{
    asm volatile("ldmatrix.sync.aligned.m8n8.x4.shared.b16 {%0,%1,%2,%3}, [%4];"
                 : "=r"(r0), "=r"(r1), "=r"(r2), "=r"(r3) : "r"(saddr));
}
__device__ __forceinline__ void mma_tf32(float* c, unsigned a0, unsigned a1, unsigned a2, unsigned a3,
                                         unsigned b0, unsigned b1)
{
    asm volatile(
        "mma.sync.aligned.m16n8k8.row.col.f32.tf32.tf32.f32 "
        "{%0,%1,%2,%3}, {%4,%5,%6,%7}, {%8,%9}, {%0,%1,%2,%3};"
        : "+f"(c[0]), "+f"(c[1]), "+f"(c[2]), "+f"(c[3])
        : "r"(a0), "r"(a1), "r"(a2), "r"(a3), "r"(b0), "r"(b1));
}

// ---------------- tf32 GEMM: C[M,N] = A[M,K] @ B[N,K]^T + bias  (2-stage, R10-exact) ----------------
#define PAD 20
__global__ void __launch_bounds__(256)
tf32_gemm_tn(const float* __restrict__ A, const float* __restrict__ B,
             const float* __restrict__ bias, float* __restrict__ C,
             int M, int N, int K)
{
    __shared__ float As[2][128][PAD];
    __shared__ float Bs[2][128][PAD];
    const int tid  = threadIdx.x;
    const int warp = tid >> 5;
    const int lane = tid & 31;
    const int wm   = warp >> 2;
    const int wn   = warp & 3;
    const int bm   = blockIdx.y * 128;
    const int bn   = blockIdx.x * 128;

    float c[4][4][4];
#pragma unroll
    for (int i = 0; i < 4; i++)
#pragma unroll
        for (int j = 0; j < 4; j++)
#pragma unroll
            for (int r = 0; r < 4; r++) c[i][j][r] = 0.f;

    const int lr = tid >> 1;
    const int cc = (tid & 1) * 8;

    const float* Ag = A + (size_t)(bm + lr) * K + cc;
    const float* Bg = B + (size_t)(bn + lr) * K + cc;

    const unsigned sA0 = (unsigned)__cvta_generic_to_shared(&As[0][lr][cc]);
    const unsigned sA1 = (unsigned)__cvta_generic_to_shared(&As[1][lr][cc]);
    const unsigned sB0 = (unsigned)__cvta_generic_to_shared(&Bs[0][lr][cc]);
    const unsigned sB1 = (unsigned)__cvta_generic_to_shared(&Bs[1][lr][cc]);

    const int fr = lane & 15;
    const int fc = ((lane >> 4) << 2);

    cp_async16(sA0,      Ag);
    cp_async16(sA0 + 16, Ag + 4);
    cp_async16(sB0,      Bg);
    cp_async16(sB0 + 16, Bg + 4);
    cp_commit();

    const int KT = K / 16;
    for (int kt = 0; kt < KT; kt++) {
        const int cur = kt & 1;
        if (kt + 1 < KT) {
            const float* Ap = Ag + (size_t)(kt + 1) * 16;
            const float* Bp = Bg + (size_t)(kt + 1) * 16;
            const unsigned dA = cur ? sA0 : sA1;
            const unsigned dB = cur ? sB0 : sB1;
            cp_async16(dA,      Ap);
            cp_async16(dA + 16, Ap + 4);
            cp_async16(dB,      Bp);
            cp_async16(dB + 16, Bp + 4);
            cp_commit();
            cp_wait<1>();
        } else {
            cp_wait<0>();
        }
        __syncthreads();

#pragma unroll
        for (int ks = 0; ks < 2; ks++) {
            const int k0 = ks * 8 + fc;
            unsigned b0a, b1a, b2a, b3a, b0b, b1b, b2b, b3b;
            {
                unsigned sa = (unsigned)__cvta_generic_to_shared(&Bs[cur][wn*32 + fr][k0]);
                ldsm_x4(b0a, b1a, b2a, b3a, sa);
                unsigned sb = (unsigned)__cvta_generic_to_shared(&Bs[cur][wn*32 + 16 + fr][k0]);
                ldsm_x4(b0b, b1b, b2b, b3b, sb);
            }
#pragma unroll
            for (int mf = 0; mf < 4; mf++) {
                unsigned a0, a1, a2, a3;
                unsigned sa = (unsigned)__cvta_generic_to_shared(&As[cur][wm*64 + mf*16 + fr][k0]);
                ldsm_x4(a0, a1, a2, a3, sa);
                mma_tf32(c[mf][0], a0, a1, a2, a3, b0a, b2a);
                mma_tf32(c[mf][1], a0, a1, a2, a3, b1a, b3a);
                mma_tf32(c[mf][2], a0, a1, a2, a3, b0b, b2b);
                mma_tf32(c[mf][3], a0, a1, a2, a3, b1b, b3b);
            }
        }
        __syncthreads();
    }

    const int g  = lane >> 2;
    const int tg = lane & 3;
#pragma unroll
    for (int mf = 0; mf < 4; mf++) {
        const int row0 = bm + wm*64 + mf*16 + g;
#pragma unroll
        for (int nf = 0; nf < 4; nf++) {
            const int col0 = bn + wn*32 + nf*8 + 2*tg;
            const float2 bv = *(const float2*)&bias[col0];
            float2 v0 = make_float2(c[mf][nf][0] + bv.x, c[mf][nf][1] + bv.y);
            float2 v1 = make_float2(c[mf][nf][2] + bv.x, c[mf][nf][3] + bv.y);
            *(float2*)&C[(size_t)row0 * N + col0]       = v0;
            *(float2*)&C[(size_t)(row0 + 8) * N + col0] = v1;
        }
    }
}

// ---------------- 1024x1024 transpose ----------------
__global__ void __launch_bounds__(256)
transpose_kernel(const float* __restrict__ in, float* __restrict__ out)
{
    __shared__ float tile[32][33];
    const int bx = blockIdx.x * 32, by = blockIdx.y * 32;
    const int tx = threadIdx.x & 31, ty4 = (threadIdx.x >> 5) * 4;
#pragma unroll
    for (int r = 0; r < 4; r++)
        tile[ty4 + r][tx] = in[(size_t)(by + ty4 + r) * HHID + bx + tx];
    __syncthreads();
#pragma unroll
    for (int r = 0; r < 4; r++)
        out[(size_t)(bx + ty4 + r) * HHID + by + tx] = tile[tx][ty4 + r];
}

// ---------------- persistent bidirectional LSTM scan (R10-exact + fast cell math) ----------------
#define HPAD 516
__global__ void __launch_bounds__(256)
lstm_scan_kernel(const float* __restrict__ Whh_f, const float* __restrict__ Whh_b)
{
    __shared__ float h_sh[16 * HPAD];
    __shared__ float red[4][32][18];

    const int cid  = blockIdx.x;
    const int dir  = cid >> 6;
    const int ug   = cid & 63;
    const int U0   = ug * 8;
    const int tid  = threadIdx.x;
    const int w    = tid >> 5;
    const int lane = tid & 31;
    const int rg   = w >> 2;
    const int ksl  = w & 3;
    const int kb   = ksl * 128;
    const int qr   = lane >> 2;
    const int qc   = lane & 3;
    const int r_lo = rg * 16 + qr;
    const int r_hi = r_lo + 8;
    const int fr   = lane & 15;
    const int fc   = (lane >> 4) << 2;

    const float* __restrict__ Whh = dir ? Whh_b : Whh_f;
    const float* __restrict__ xs  = dir ? g_xs_b : g_xs_f;

    // persistent A fragments
    unsigned a[16][4];
    {
        const int grow_lo = (r_lo >> 3) * HH2 + U0 + (r_lo & 7);
        const int grow_hi = (r_hi >> 3) * HH2 + U0 + (r_hi & 7);
        const float* Wlo = Whh + (size_t)grow_lo * HH2;
        const float* Whi = Whh + (size_t)grow_hi * HH2;
#pragma unroll
        for (int j = 0; j < 16; j++) {
            const int k0 = kb + j * 8 + qc;
            a[j][0] = __float_as_uint(Wlo[k0]);
            a[j][1] = __float_as_uint(Whi[k0]);
            a[j][2] = __float_as_uint(Wlo[k0 + 4]);
            a[j][3] = __float_as_uint(Whi[k0 + 4]);
        }
    }

    const int cb = tid >> 3;
    const int cu = tid & 7;
    float c_state = 0.f;

    for (int s = 0; s < TT; s++) {
        const int t = dir ? (TT - 1 - s) : s;

        float xp0 = 0.f, xp1 = 0.f, xp2 = 0.f, xp3 = 0.f;
        if (tid < 128) {
            const size_t xb = ((size_t)(cb * TT + t)) * G4 + U0 + cu;
            xp0 = xs[xb];
            xp1 = xs[xb + 512];
            xp2 = xs[xb + 1024];
            xp3 = xs[xb + 1536];
        }

        if (s == 0) {
            for (int i = tid; i < 16 * HPAD; i += 256) h_sh[i] = 0.f;
        } else {
            const float* hg = &g_hbuf[dir][(s - 1) & 1][0][0];
            for (int idx = tid * 4; idx < BB * HH2; idx += 1024) {
                const float4 v = __ldcg((const float4*)&hg[idx]);
                const int b = idx >> 9, k = idx & 511;
                *(float4*)&h_sh[b * HPAD + k] = v;
            }
        }
        __syncthreads();

        float cl0[4] = {0,0,0,0}, cl1[4] = {0,0,0,0};
        float ch0[4] = {0,0,0,0}, ch1[4] = {0,0,0,0};
#pragma unroll
        for (int j = 0; j < 16; j += 2) {
            {
                const int k0 = kb + j * 8 + fc;
                unsigned m0, m1, m2, m3;
                const unsigned sa = (unsigned)__cvta_generic_to_shared(&h_sh[fr * HPAD + k0]);
                ldsm_x4(m0, m1, m2, m3, sa);
                mma_tf32(cl0, a[j][0], a[j][1], a[j][2], a[j][3], m0, m2);
                mma_tf32(ch0, a[j][0], a[j][1], a[j][2], a[j][3], m1, m3);
            }
            {
                const int k0 = kb + (j + 1) * 8 + fc;
                unsigned m0, m1, m2, m3;
                const unsigned sa = (unsigned)__cvta_generic_to_shared(&h_sh[fr * HPAD + k0]);
                ldsm_x4(m0, m1, m2, m3, sa);
                mma_tf32(cl1, a[j+1][0], a[j+1][1], a[j+1][2], a[j+1][3], m0, m2);
                mma_tf32(ch1, a[j+1][0], a[j+1][1], a[j+1][2], a[j+1][3], m1, m3);
            }
        }

        *(float2*)&red[ksl][r_lo][2 * qc]     = make_float2(cl0[0]+cl1[0], cl0[1]+cl1[1]);
        *(float2*)&red[ksl][r_hi][2 * qc]     = make_float2(cl0[2]+cl1[2], cl0[3]+cl1[3]);
        *(float2*)&red[ksl][r_lo][8 + 2 * qc] = make_float2(ch0[0]+ch1[0], ch0[1]+ch1[1]);
        *(float2*)&red[ksl][r_hi][8 + 2 * qc] = make_float2(ch0[2]+ch1[2], ch0[3]+ch1[3]);
        __syncthreads();

        if (tid < 128) {
            const int r0 = 0 * 8 + cu, r1 = 1 * 8 + cu, r2 = 2 * 8 + cu, r3 = 3 * 8 + cu;
            const float zi = red[0][r0][cb] + red[1][r0][cb] + red[2][r0][cb] + red[3][r0][cb] + xp0;
            const float zf = red[0][r1][cb] + red[1][r1][cb] + red[2][r1][cb] + red[3][r1][cb] + xp1;
            const float zg = red[0][r2][cb] + red[1][r2][cb] + red[2][r2][cb] + red[3][r2][cb] + xp2;
            const float zo = red[0][r3][cb] + red[1][r3][cb] + red[2][r3][cb] + red[3][r3][cb] + xp3;
            const float is = fast_sigmoid(zi);
            const float fs = fast_sigmoid(zf);
            const float gv = fast_tanh(zg);
            const float os = fast_sigmoid(zo);
            c_state = fs * c_state + is * gv;
            const float hn = os * fast_tanh(c_state);
            __stcg(&g_hbuf[dir][s & 1][cb][U0 + cu], hn);
            __stcg(&g_enc[((size_t)(cb * TT + t)) * HHID + dir * HH2 + U0 + cu], hn);
        }

        dir_barrier_mono(dir, 64u * (unsigned)(s + 1));
    }
}

// ---------------- span mean-pool + LayerNorm ----------------
__global__ void __launch_bounds__(256)
span_pool_ln_kernel(const int* __restrict__ heads, const int* __restrict__ tails,
                    const float* __restrict__ lng, const float* __restrict__ lnb)
{
    const int r = blockIdx.x;
    const int b = r >> 5;
    int p0 = heads[r] + 1; if (p0 < 0) p0 = 0;
    int p1 = tails[r];     if (p1 > TT) p1 = TT;
    const int tid = threadIdx.x;
    const int d = tid * 4;

    float s0=0,s1=0,s2=0,s3=0;
    for (int p = p0; p < p1; p++) {
        const float4 vv = *(const float4*)&g_enc[(size_t)(b * TT + p) * HHID + d];
        s0 += vv.x; s1 += vv.y; s2 += vv.z; s3 += vv.w;
    }
    int cnt = p1 - p0; if (cnt < 1) cnt = 1;
    const float inv = 1.f / (float)cnt;
    const float v0=s0*inv, v1=s1*inv, v2=s2*inv, v3=s3*inv;

    __shared__ float red[256];
    __shared__ float stats[2];
    red[tid] = v0+v1+v2+v3;
    __syncthreads();
    for (int st = 128; st > 0; st >>= 1) { if (tid < st) red[tid] += red[tid+st]; __syncthreads(); }
    if (tid == 0) stats[0] = red[0] * (1.f / HHID);
    __syncthreads();
    const float mean = stats[0];
    const float q0=v0-mean, q1=v1-mean, q2=v2-mean, q3=v3-mean;
    red[tid] = q0*q0+q1*q1+q2*q2+q3*q3;
    __syncthreads();
    for (int st = 128; st > 0; st >>= 1) { if (tid < st) red[tid] += red[tid+st]; __syncthreads(); }
    if (tid == 0) stats[1] = rsqrtf(red[0] * (1.f / HHID) + 1e-7f);
    __syncthreads();
    const float rstd = stats[1];
    float* out = &g_feat[(size_t)r * HHID + d];
    out[0] = q0*rstd*lng[d+0] + lnb[d+0];
    out[1] = q1*rstd*lng[d+1] + lnb[d+1];
    out[2] = q2*rstd*lng[d+2] + lnb[d+2];
    out[3] = q3*rstd*lng[d+3] + lnb[d+3];
}

// ---------------- attention ----------------
__global__ void __launch_bounds__(256)
attn_kernel(const int* __restrict__ am)
{
    const int bh = blockIdx.x;
    const int b = bh >> 4;
    const int h = bh & 15;
    __shared__ float qs[SS][DHH], ks[SS][DHH], vs[SS][DHH];
    __shared__ float sc[SS][SS + 1];
    const int tid = threadIdx.x;

    for (int i = tid; i < SS * DHH; i += 256) {
        const int s = i >> 6, d = i & 63;
        const size_t off = (size_t)(b * SS + s) * HHID + h * DHH + d;
        qs[s][d] = g_q[off];
        ks[s][d] = g_k[off];
        vs[s][d] = g_v[off];
    }
    __syncthreads();

    for (int i = tid; i < SS * SS; i += 256) {
        const int qq = i >> 5, kk = i & 31;
        float a = 0.f;
#pragma unroll
        for (int d = 0; d < DHH; d++) a += qs[qq][d] * ks[kk][d];
        const bool valid = (am[b * SS + qq] != 0) && (am[b * SS + kk] != 0);
        sc[qq][kk] = valid ? a * 0.125f : -1e9f;
    }
    __syncthreads();

    const int wid = tid >> 5, lane = tid & 31;
    for (int r = wid; r < SS; r += 8) {
        const float val = sc[r][lane];
        float m = val;
#pragma unroll
        for (int o = 16; o > 0; o >>= 1) m = fmaxf(m, __shfl_xor_sync(FULL, m, o));
        const float e = expf(val - m);
        float sum = e;
#pragma unroll
        for (int o = 16; o > 0; o >>= 1) sum += __shfl_xor_sync(FULL, sum, o);
        sc[r][lane] = e / sum;
    }
    __syncthreads();

    for (int i = tid; i < SS * DHH; i += 256) {
        const int qq = i >> 6, d = i & 63;
        float a = 0.f;
#pragma unroll
        for (int kk = 0; kk < SS; kk++) a += sc[qq][kk] * vs[kk][d];
        g_ctx[(size_t)(b * SS + qq) * HHID + h * DHH + d] = a;
    }
}

// ---------------- residual + LayerNorm ----------------
__global__ void __launch_bounds__(256)
resid_ln_kernel(const float* __restrict__ lng, const float* __restrict__ lnb)
{
    const int r = blockIdx.x;
    const int tid = threadIdx.x;
    const int d = tid * 4;
    const size_t base = (size_t)r * HHID + d;
    const float4 a = *(const float4*)&g_ao[base];
    const float4 f = *(const float4*)&g_feat[base];
    const float v0=a.x+f.x, v1=a.y+f.y, v2=a.z+f.z, v3=a.w+f.w;

    __shared__ float red[256];
    __shared__ float stats[2];
    red[tid] = v0+v1+v2+v3;
    __syncthreads();
    for (int st = 128; st > 0; st >>= 1) { if (tid < st) red[tid] += red[tid+st]; __syncthreads(); }
    if (tid == 0) stats[0] = red[0] * (1.f / HHID);
    __syncthreads();
    const float mean = stats[0];
    const float q0=v0-mean, q1=v1-mean, q2=v2-mean, q3=v3-mean;
    red[tid] = q0*q0+q1*q1+q2*q2+q3*q3;
    __syncthreads();
    for (int st = 128; st > 0; st >>= 1) { if (tid < st) red[tid] += red[tid+st]; __syncthreads(); }
    if (tid == 0) stats[1] = rsqrtf(red[0] * (1.f / HHID) + 1e-7f);
    __syncthreads();
    const float rstd = stats[1];
    float* out = &g_feat2[base];
    out[0] = q0*rstd*lng[d+0] + lnb[d+0];
    out[1] = q1*rstd*lng[d+1] + lnb[d+1];
    out[2] = q2*rstd*lng[d+2] + lnb[d+2];
    out[3] = q3*rstd*lng[d+3] + lnb[d+3];
}

// ---------------- classifier + per-span loss terms ----------------
__global__ void __launch_bounds__(128)
loss_terms_kernel(const int* __restrict__ labels, const float* __restrict__ wf,
                  const int* __restrict__ am,
                  const float* __restrict__ Wc, const float* __restrict__ bc)
{
    const int r = blockIdx.x;
    const int tid = threadIdx.x;
    const float* row = &g_feat2[(size_t)r * HHID];
    float d0=0, d1=0, d2=0;
    for (int i = tid; i < HHID; i += 128) {
        const float x = row[i];
        d0 += x * Wc[i*3+0];
        d1 += x * Wc[i*3+1];
        d2 += x * Wc[i*3+2];
    }
    __shared__ float r0[128], r1[128], r2[128];
    r0[tid]=d0; r1[tid]=d1; r2[tid]=d2;
    __syncthreads();
    for (int st = 64; st > 0; st >>= 1) {
        if (tid < st) { r0[tid]+=r0[tid+st]; r1[tid]+=r1[tid+st]; r2[tid]+=r2[tid+st]; }
        __syncthreads();
    }
    if (tid == 0) {
        const float z0 = r0[0]+bc[0], z1 = r1[0]+bc[1], z2 = r2[0]+bc[2];
        const float m = fmaxf(z0, fmaxf(z1, z2));
        const float e0 = expf(z0-m), e1 = expf(z1-m), e2 = expf(z2-m);
        const float lse = m + logf(e0+e1+e2);
        const int lab = labels[r];
        const bool valid = lab >= 0;
        const int lc = valid ? lab : 0;
        const float zl = (lc==0) ? z0 : ((lc==1) ? z1 : z2);
        const float logp = zl - lse;
        const float pt = expf(logp);
        const float spanm = ((am[r]!=0) && valid) ? 1.f : 0.f;
        const float vm = valid ? 1.f : 0.f;
        const float omp = 1.f - pt;
        g_terms[r*4+0] = (-logp * wf[r]) * spanm;
        g_terms[r*4+1] = spanm;
        g_terms[r*4+2] = (-(omp*omp) * logp) * vm;
        g_terms[r*4+3] = vm;
    }
}

__global__ void __launch_bounds__(256)
final_loss_kernel(float* __restrict__ out)
{
    const int tid = threadIdx.x;
    float a0=0,a1=0,a2=0,a3=0;
    for (int r = tid; r < BB*SS; r += 256) {
        a0 += g_terms[r*4+0]; a1 += g_terms[r*4+1];
        a2 += g_terms[r*4+2]; a3 += g_terms[r*4+3];
    }
    __shared__ float s0[256], s1[256], s2[256], s3[256];
    s0[tid]=a0; s1[tid]=a1; s2[tid]=a2; s3[tid]=a3;
    __syncthreads();
    for (int st = 128; st > 0; st >>= 1) {
        if (tid < st) { s0[tid]+=s0[tid+st]; s1[tid]+=s1[tid+st]; s2[tid]+=s2[tid+st]; s3[tid]+=s3[tid+st]; }
        __syncthreads();
    }
    if (tid == 0)
        out[0] = s0[0] / fmaxf(s1[0], 1.f) + s2[0] / fmaxf(s3[0], 1.f);
}

// ---------------- launch ----------------
extern "C" void kernel_launch(void* const* d_in, const int* in_sizes, int n_in,
                              void* d_out, int out_size)
{
    const float* hs     = (const float*)d_in[0];
    const int*   heads  = (const int*)  d_in[1];
    const int*   tails  = (const int*)  d_in[2];
    const int*   am     = (const int*)  d_in[3];
    const int*   labels = (const int*)  d_in[4];
    const float* wf     = (const float*)d_in[5];
    const float* Wih_f  = (const float*)d_in[6];
    const float* Whh_f  = (const float*)d_in[7];
    const float* b_f    = (const float*)d_in[8];
    const float* Wih_b  = (const float*)d_in[9];
    const float* Whh_b  = (const float*)d_in[10];
    const float* b_b    = (const float*)d_in[11];
    const float* ln1g   = (const float*)d_in[12];
    const float* ln1b   = (const float*)d_in[13];
    const float* Wq     = (const float*)d_in[14];
    const float* bq     = (const float*)d_in[15];
    const float* Wk     = (const float*)d_in[16];
    const float* bk     = (const float*)d_in[17];
    const float* Wv     = (const float*)d_in[18];
    const float* bv     = (const float*)d_in[19];
    const float* Wo     = (const float*)d_in[20];
    const float* bo     = (const float*)d_in[21];
    const float* ln2g   = (const float*)d_in[22];
    const float* ln2b   = (const float*)d_in[23];
    const float* Wc     = (const float*)d_in[24];
    const float* bc     = (const float*)d_in[25];

    float *p_xs_f, *p_xs_b, *p_feat, *p_q, *p_k, *p_v, *p_ctx, *p_ao, *p_wt;
    cudaGetSymbolAddress((void**)&p_xs_f,  g_xs_f);
    cudaGetSymbolAddress((void**)&p_xs_b,  g_xs_b);
    cudaGetSymbolAddress((void**)&p_feat,  g_feat);
    cudaGetSymbolAddress((void**)&p_q,     g_q);
    cudaGetSymbolAddress((void**)&p_k,     g_k);
    cudaGetSymbolAddress((void**)&p_v,     g_v);
    cudaGetSymbolAddress((void**)&p_ctx,   g_ctx);
    cudaGetSymbolAddress((void**)&p_ao,    g_ao);
    cudaGetSymbolAddress((void**)&p_wt,    g_wt);

    // index 0: init (loss terms + barrier counters)
    init_kernel<<<8, 256>>>();

    // input projections: tf32, 2-stage (R10-exact)
    {
        dim3 grid(G4/128, (BB*TT)/128), blk(256);
        tf32_gemm_tn<<<grid, blk>>>(hs, Wih_f, b_f, p_xs_f, BB*TT, G4, HHID);
        tf32_gemm_tn<<<grid, blk>>>(hs, Wih_b, b_b, p_xs_b, BB*TT, G4, HHID);
    }

    // index 3: persistent bidirectional scan (R10 config + fast cell math)
    lstm_scan_kernel<<<128, 256>>>(Whh_f, Whh_b);

    // transpose QKV/O weights
    {
        dim3 grid(32, 32), blk(256);
        transpose_kernel<<<grid, blk>>>(Wq, p_wt + 0 * HHID * HHID);
        transpose_kernel<<<grid, blk>>>(Wk, p_wt + 1 * HHID * HHID);
        transpose_kernel<<<grid, blk>>>(Wv, p_wt + 2 * HHID * HHID);
        transpose_kernel<<<grid, blk>>>(Wo, p_wt + 3 * HHID * HHID);
    }

    // span pool + LN1
    span_pool_ln_kernel<<<BB*SS, 256>>>(heads, tails, ln1g, ln1b);

    // q,k,v
    {
        dim3 grid(HHID/128, (BB*SS)/128), blk(256);
        tf32_gemm_tn<<<grid, blk>>>(p_feat, p_wt + 0 * HHID * HHID, bq, p_q, BB*SS, HHID, HHID);
        tf32_gemm_tn<<<grid, blk>>>(p_feat, p_wt + 1 * HHID * HHID, bk, p_k, BB*SS, HHID, HHID);
        tf32_gemm_tn<<<grid, blk>>>(p_feat, p_wt + 2 * HHID * HHID, bv, p_v, BB*SS, HHID, HHID);
    }

    attn_kernel<<<BB*NHH, 256>>>(am);

    {
        dim3 grid(HHID/128, (BB*SS)/128), blk(256);
        tf32_gemm_tn<<<grid, blk>>>(p_ctx, p_wt + 3 * HHID * HHID, bo, p_ao, BB*SS, HHID, HHID);
    }

    resid_ln_kernel<<<BB*SS, 256>>>(ln2g, ln2b);

    loss_terms_kernel<<<BB*SS, 128>>>(labels, wf, am, Wc, bc);

    final_loss_kernel<<<1, 256>>>((float*)d_out);
}

// round 15
// speedup vs baseline: 1.1418x; 1.0208x over previous
#include <cuda_runtime.h>
#include <math.h>

#define FULL 0xffffffffu
#define BB   16
#define TT   1024
#define HHID 1024
#define SS   32
#define CC   3
#define NHH  16
#define DHH  64
#define HH2  512
#define G4   2048

// ---------------- scratch ----------------
__device__ float g_xs_f[BB*TT*G4];
__device__ float g_xs_b[BB*TT*G4];
__device__ float g_enc [BB*TT*HHID];
__device__ float g_hbuf[2][2][BB][HH2];
__device__ float g_feat [BB*SS*HHID];
__device__ float g_q    [BB*SS*HHID];
__device__ float g_k    [BB*SS*HHID];
__device__ float g_v    [BB*SS*HHID];
__device__ float g_ctx  [BB*SS*HHID];
__device__ float g_ao   [BB*SS*HHID];
__device__ float g_feat2[BB*SS*HHID];
__device__ float g_terms[BB*SS*4];
__device__ float g_wt[4][HHID*HHID];

// monotonic per-direction barrier counters, own 128B lines
struct __align__(128) PadCtr { unsigned v; unsigned pad[31]; };
__device__ PadCtr g_ctr[2];

// ---------------- fast activation helpers ----------------
__device__ __forceinline__ float fast_sigmoid(float x)
{
    return __fdividef(1.f, 1.f + __expf(-x));
}
__device__ __forceinline__ float fast_tanh(float x)
{
    const float e2 = __expf(2.f * x);
    return __fdividef(e2 - 1.f, e2 + 1.f);
}

// ---------------- monotonic flat barrier ----------------
__device__ __forceinline__ void dir_barrier_mono(int dir, unsigned target)
{
    __syncthreads();
    if (threadIdx.x == 0) {
        unsigned* ctr = &g_ctr[dir].v;
        asm volatile("red.release.gpu.global.add.u32 [%0], %1;" :: "l"(ctr), "r"(1u) : "memory");
        unsigned v;
        do {
            asm volatile("ld.acquire.gpu.global.u32 %0, [%1];" : "=r"(v) : "l"(ctr) : "memory");
        } while (v < target);
    }
    __syncthreads();
}

// ---------------- init kernel ----------------
__global__ void init_kernel()
{
    const int i = blockIdx.x * blockDim.x + threadIdx.x;
    if (i < BB * SS * 4) g_terms[i] = 0.f;
    if (i == 0) { g_ctr[0].v = 0u; g_ctr[1].v = 0u; }
}

// ---------------- cp.async helpers ----------------
__device__ __forceinline__ void cp_async16(unsigned saddr, const void* gptr)
{
    asm volatile("cp.async.cg.shared.global [%0], [%1], 16;" :: "r"(saddr), "l"(gptr));
}
__device__ __forceinline__ void cp_commit() { asm volatile("cp.async.commit_group;"); }
template<int N>
__device__ __forceinline__ void cp_wait() { asm volatile("cp.async.wait_group %0;" :: "n"(N)); }

// ---------------- tf32 mma helpers ----------------
__device__ __forceinline__ void ldsm_x4(unsigned& r0, unsigned& r1, unsigned& r2, unsigned& r3,
                                        unsigned saddr)
{
    asm volatile("ldmatrix.sync.aligned.m8n8.x4.shared.b16 {%0,%1,%2,%3}, [%4];"
                 : "=r"(r0), "=r"(r1), "=r"(r2), "=r"(r3) : "r"(saddr));
}
__device__ __forceinline__ void mma_tf32(float* c, unsigned a0, unsigned a1, unsigned a2, unsigned a3,
                                         unsigned b0, unsigned b1)
{
    asm volatile(
        "mma.sync.aligned.m16n8k8.row.col.f32.tf32.tf32.f32 "
        "{%0,%1,%2,%3}, {%4,%5,%6,%7}, {%8,%9}, {%0,%1,%2,%3};"
        : "+f"(c[0]), "+f"(c[1]), "+f"(c[2]), "+f"(c[3])
        : "r"(a0), "r"(a1), "r"(a2), "r"(a3), "r"(b0), "r"(b1));
}

// ---------------- tf32 GEMM: C[M,N] = A[M,K] @ B[N,K]^T + bias  (2-stage, A-prefetch) ----------------
#define PAD 20
__global__ void __launch_bounds__(256)
tf32_gemm_tn(const float* __restrict__ A, const float* __restrict__ B,
             const float* __restrict__ bias, float* __restrict__ C,
             int M, int N, int K)
{
    __shared__ float As[2][128][PAD];
    __shared__ float Bs[2][128][PAD];
    const int tid  = threadIdx.x;
    const int warp = tid >> 5;
    const int lane = tid & 31;
    const int wm   = warp >> 2;
    const int wn   = warp & 3;
    const int bm   = blockIdx.y * 128;
    const int bn   = blockIdx.x * 128;

    float c[4][4][4];
#pragma unroll
    for (int i = 0; i < 4; i++)
#pragma unroll
        for (int j = 0; j < 4; j++)
#pragma unroll
            for (int r = 0; r < 4; r++) c[i][j][r] = 0.f;

    const int lr = tid >> 1;
    const int cc = (tid & 1) * 8;

    const float* Ag = A + (size_t)(bm + lr) * K + cc;
    const float* Bg = B + (size_t)(bn + lr) * K + cc;

    const unsigned sA0 = (unsigned)__cvta_generic_to_shared(&As[0][lr][cc]);
    const unsigned sA1 = (unsigned)__cvta_generic_to_shared(&As[1][lr][cc]);
    const unsigned sB0 = (unsigned)__cvta_generic_to_shared(&Bs[0][lr][cc]);
    const unsigned sB1 = (unsigned)__cvta_generic_to_shared(&Bs[1][lr][cc]);

    const int fr = lane & 15;
    const int fc = ((lane >> 4) << 2);

    cp_async16(sA0,      Ag);
    cp_async16(sA0 + 16, Ag + 4);
    cp_async16(sB0,      Bg);
    cp_async16(sB0 + 16, Bg + 4);
    cp_commit();

    const int KT = K / 16;
    for (int kt = 0; kt < KT; kt++) {
        const int cur = kt & 1;
        if (kt + 1 < KT) {
            const float* Ap = Ag + (size_t)(kt + 1) * 16;
            const float* Bp = Bg + (size_t)(kt + 1) * 16;
            const unsigned dA = cur ? sA0 : sA1;
            const unsigned dB = cur ? sB0 : sB1;
            cp_async16(dA,      Ap);
            cp_async16(dA + 16, Ap + 4);
            cp_async16(dB,      Bp);
            cp_async16(dB + 16, Bp + 4);
            cp_commit();
            cp_wait<1>();
        } else {
            cp_wait<0>();
        }
        __syncthreads();

#pragma unroll
        for (int ks = 0; ks < 2; ks++) {
            const int k0 = ks * 8 + fc;
            // issue ALL fragment loads first (B x2, A x4) so ldsm latencies overlap
            unsigned b0a, b1a, b2a, b3a, b0b, b1b, b2b, b3b;
            unsigned av[4][4];
            {
                unsigned sa = (unsigned)__cvta_generic_to_shared(&Bs[cur][wn*32 + fr][k0]);
                ldsm_x4(b0a, b1a, b2a, b3a, sa);
                unsigned sb = (unsigned)__cvta_generic_to_shared(&Bs[cur][wn*32 + 16 + fr][k0]);
                ldsm_x4(b0b, b1b, b2b, b3b, sb);
            }
#pragma unroll
            for (int mf = 0; mf < 4; mf++) {
                unsigned sa = (unsigned)__cvta_generic_to_shared(&As[cur][wm*64 + mf*16 + fr][k0]);
                ldsm_x4(av[mf][0], av[mf][1], av[mf][2], av[mf][3], sa);
            }
#pragma unroll
            for (int mf = 0; mf < 4; mf++) {
                mma_tf32(c[mf][0], av[mf][0], av[mf][1], av[mf][2], av[mf][3], b0a, b2a);
                mma_tf32(c[mf][1], av[mf][0], av[mf][1], av[mf][2], av[mf][3], b1a, b3a);
                mma_tf32(c[mf][2], av[mf][0], av[mf][1], av[mf][2], av[mf][3], b0b, b2b);
                mma_tf32(c[mf][3], av[mf][0], av[mf][1], av[mf][2], av[mf][3], b1b, b3b);
            }
        }
        __syncthreads();
    }

    const int g  = lane >> 2;
    const int tg = lane & 3;
#pragma unroll
    for (int mf = 0; mf < 4; mf++) {
        const int row0 = bm + wm*64 + mf*16 + g;
#pragma unroll
        for (int nf = 0; nf < 4; nf++) {
            const int col0 = bn + wn*32 + nf*8 + 2*tg;
            const float2 bv = *(const float2*)&bias[col0];
            float2 v0 = make_float2(c[mf][nf][0] + bv.x, c[mf][nf][1] + bv.y);
            float2 v1 = make_float2(c[mf][nf][2] + bv.x, c[mf][nf][3] + bv.y);
            *(float2*)&C[(size_t)row0 * N + col0]       = v0;
            *(float2*)&C[(size_t)(row0 + 8) * N + col0] = v1;
        }
    }
}

// ---------------- 1024x1024 transpose ----------------
__global__ void __launch_bounds__(256)
transpose_kernel(const float* __restrict__ in, float* __restrict__ out)
{
    __shared__ float tile[32][33];
    const int bx = blockIdx.x * 32, by = blockIdx.y * 32;
    const int tx = threadIdx.x & 31, ty4 = (threadIdx.x >> 5) * 4;
#pragma unroll
    for (int r = 0; r < 4; r++)
        tile[ty4 + r][tx] = in[(size_t)(by + ty4 + r) * HHID + bx + tx];
    __syncthreads();
#pragma unroll
    for (int r = 0; r < 4; r++)
        out[(size_t)(bx + ty4 + r) * HHID + by + tx] = tile[tx][ty4 + r];
}

// ---------------- persistent bidirectional LSTM scan (R14-exact) ----------------
#define HPAD 516
__global__ void __launch_bounds__(256)
lstm_scan_kernel(const float* __restrict__ Whh_f, const float* __restrict__ Whh_b)
{
    __shared__ float h_sh[16 * HPAD];
    __shared__ float red[4][32][18];

    const int cid  = blockIdx.x;
    const int dir  = cid >> 6;
    const int ug   = cid & 63;
    const int U0   = ug * 8;
    const int tid  = threadIdx.x;
    const int w    = tid >> 5;
    const int lane = tid & 31;
    const int rg   = w >> 2;
    const int ksl  = w & 3;
    const int kb   = ksl * 128;
    const int qr   = lane >> 2;
    const int qc   = lane & 3;
    const int r_lo = rg * 16 + qr;
    const int r_hi = r_lo + 8;
    const int fr   = lane & 15;
    const int fc   = (lane >> 4) << 2;

    const float* __restrict__ Whh = dir ? Whh_b : Whh_f;
    const float* __restrict__ xs  = dir ? g_xs_b : g_xs_f;

    unsigned a[16][4];
    {
        const int grow_lo = (r_lo >> 3) * HH2 + U0 + (r_lo & 7);
        const int grow_hi = (r_hi >> 3) * HH2 + U0 + (r_hi & 7);
        const float* Wlo = Whh + (size_t)grow_lo * HH2;
        const float* Whi = Whh + (size_t)grow_hi * HH2;
#pragma unroll
        for (int j = 0; j < 16; j++) {
            const int k0 = kb + j * 8 + qc;
            a[j][0] = __float_as_uint(Wlo[k0]);
            a[j][1] = __float_as_uint(Whi[k0]);
            a[j][2] = __float_as_uint(Wlo[k0 + 4]);
            a[j][3] = __float_as_uint(Whi[k0 + 4]);
        }
    }

    const int cb = tid >> 3;
    const int cu = tid & 7;
    float c_state = 0.f;

    for (int s = 0; s < TT; s++) {
        const int t = dir ? (TT - 1 - s) : s;

        float xp0 = 0.f, xp1 = 0.f, xp2 = 0.f, xp3 = 0.f;
        if (tid < 128) {
            const size_t xb = ((size_t)(cb * TT + t)) * G4 + U0 + cu;
            xp0 = xs[xb];
            xp1 = xs[xb + 512];
            xp2 = xs[xb + 1024];
            xp3 = xs[xb + 1536];
        }

        if (s == 0) {
            for (int i = tid; i < 16 * HPAD; i += 256) h_sh[i] = 0.f;
        } else {
            const float* hg = &g_hbuf[dir][(s - 1) & 1][0][0];
            for (int idx = tid * 4; idx < BB * HH2; idx += 1024) {
                const float4 v = __ldcg((const float4*)&hg[idx]);
                const int b = idx >> 9, k = idx & 511;
                *(float4*)&h_sh[b * HPAD + k] = v;
            }
        }
        __syncthreads();

        float cl0[4] = {0,0,0,0}, cl1[4] = {0,0,0,0};
        float ch0[4] = {0,0,0,0}, ch1[4] = {0,0,0,0};
#pragma unroll
        for (int j = 0; j < 16; j += 2) {
            {
                const int k0 = kb + j * 8 + fc;
                unsigned m0, m1, m2, m3;
                const unsigned sa = (unsigned)__cvta_generic_to_shared(&h_sh[fr * HPAD + k0]);
                ldsm_x4(m0, m1, m2, m3, sa);
                mma_tf32(cl0, a[j][0], a[j][1], a[j][2], a[j][3], m0, m2);
                mma_tf32(ch0, a[j][0], a[j][1], a[j][2], a[j][3], m1, m3);
            }
            {
                const int k0 = kb + (j + 1) * 8 + fc;
                unsigned m0, m1, m2, m3;
                const unsigned sa = (unsigned)__cvta_generic_to_shared(&h_sh[fr * HPAD + k0]);
                ldsm_x4(m0, m1, m2, m3, sa);
                mma_tf32(cl1, a[j+1][0], a[j+1][1], a[j+1][2], a[j+1][3], m0, m2);
                mma_tf32(ch1, a[j+1][0], a[j+1][1], a[j+1][2], a[j+1][3], m1, m3);
            }
        }

        *(float2*)&red[ksl][r_lo][2 * qc]     = make_float2(cl0[0]+cl1[0], cl0[1]+cl1[1]);
        *(float2*)&red[ksl][r_hi][2 * qc]     = make_float2(cl0[2]+cl1[2], cl0[3]+cl1[3]);
        *(float2*)&red[ksl][r_lo][8 + 2 * qc] = make_float2(ch0[0]+ch1[0], ch0[1]+ch1[1]);
        *(float2*)&red[ksl][r_hi][8 + 2 * qc] = make_float2(ch0[2]+ch1[2], ch0[3]+ch1[3]);
        __syncthreads();

        if (tid < 128) {
            const int r0 = 0 * 8 + cu, r1 = 1 * 8 + cu, r2 = 2 * 8 + cu, r3 = 3 * 8 + cu;
            const float zi = red[0][r0][cb] + red[1][r0][cb] + red[2][r0][cb] + red[3][r0][cb] + xp0;
            const float zf = red[0][r1][cb] + red[1][r1][cb] + red[2][r1][cb] + red[3][r1][cb] + xp1;
            const float zg = red[0][r2][cb] + red[1][r2][cb] + red[2][r2][cb] + red[3][r2][cb] + xp2;
            const float zo = red[0][r3][cb] + red[1][r3][cb] + red[2][r3][cb] + red[3][r3][cb] + xp3;
            const float is = fast_sigmoid(zi);
            const float fs = fast_sigmoid(zf);
            const float gv = fast_tanh(zg);
            const float os = fast_sigmoid(zo);
            c_state = fs * c_state + is * gv;
            const float hn = os * fast_tanh(c_state);
            __stcg(&g_hbuf[dir][s & 1][cb][U0 + cu], hn);
            __stcg(&g_enc[((size_t)(cb * TT + t)) * HHID + dir * HH2 + U0 + cu], hn);
        }

        dir_barrier_mono(dir, 64u * (unsigned)(s + 1));
    }
}

// ---------------- span mean-pool + LayerNorm ----------------
__global__ void __launch_bounds__(256)
span_pool_ln_kernel(const int* __restrict__ heads, const int* __restrict__ tails,
                    const float* __restrict__ lng, const float* __restrict__ lnb)
{
    const int r = blockIdx.x;
    const int b = r >> 5;
    int p0 = heads[r] + 1; if (p0 < 0) p0 = 0;
    int p1 = tails[r];     if (p1 > TT) p1 = TT;
    const int tid = threadIdx.x;
    const int d = tid * 4;

    float s0=0,s1=0,s2=0,s3=0;
    for (int p = p0; p < p1; p++) {
        const float4 vv = *(const float4*)&g_enc[(size_t)(b * TT + p) * HHID + d];
        s0 += vv.x; s1 += vv.y; s2 += vv.z; s3 += vv.w;
    }
    int cnt = p1 - p0; if (cnt < 1) cnt = 1;
    const float inv = 1.f / (float)cnt;
    const float v0=s0*inv, v1=s1*inv, v2=s2*inv, v3=s3*inv;

    __shared__ float red[256];
    __shared__ float stats[2];
    red[tid] = v0+v1+v2+v3;
    __syncthreads();
    for (int st = 128; st > 0; st >>= 1) { if (tid < st) red[tid] += red[tid+st]; __syncthreads(); }
    if (tid == 0) stats[0] = red[0] * (1.f / HHID);
    __syncthreads();
    const float mean = stats[0];
    const float q0=v0-mean, q1=v1-mean, q2=v2-mean, q3=v3-mean;
    red[tid] = q0*q0+q1*q1+q2*q2+q3*q3;
    __syncthreads();
    for (int st = 128; st > 0; st >>= 1) { if (tid < st) red[tid] += red[tid+st]; __syncthreads(); }
    if (tid == 0) stats[1] = rsqrtf(red[0] * (1.f / HHID) + 1e-7f);
    __syncthreads();
    const float rstd = stats[1];
    float* out = &g_feat[(size_t)r * HHID + d];
    out[0] = q0*rstd*lng[d+0] + lnb[d+0];
    out[1] = q1*rstd*lng[d+1] + lnb[d+1];
    out[2] = q2*rstd*lng[d+2] + lnb[d+2];
    out[3] = q3*rstd*lng[d+3] + lnb[d+3];
}

// ---------------- attention ----------------
__global__ void __launch_bounds__(256)
attn_kernel(const int* __restrict__ am)
{
    const int bh = blockIdx.x;
    const int b = bh >> 4;
    const int h = bh & 15;
    __shared__ float qs[SS][DHH], ks[SS][DHH], vs[SS][DHH];
    __shared__ float sc[SS][SS + 1];
    const int tid = threadIdx.x;

    for (int i = tid; i < SS * DHH; i += 256) {
        const int s = i >> 6, d = i & 63;
        const size_t off = (size_t)(b * SS + s) * HHID + h * DHH + d;
        qs[s][d] = g_q[off];
        ks[s][d] = g_k[off];
        vs[s][d] = g_v[off];
    }
    __syncthreads();

    for (int i = tid; i < SS * SS; i += 256) {
        const int qq = i >> 5, kk = i & 31;
        float a = 0.f;
#pragma unroll
        for (int d = 0; d < DHH; d++) a += qs[qq][d] * ks[kk][d];
        const bool valid = (am[b * SS + qq] != 0) && (am[b * SS + kk] != 0);
        sc[qq][kk] = valid ? a * 0.125f : -1e9f;
    }
    __syncthreads();

    const int wid = tid >> 5, lane = tid & 31;
    for (int r = wid; r < SS; r += 8) {
        const float val = sc[r][lane];
        float m = val;
#pragma unroll
        for (int o = 16; o > 0; o >>= 1) m = fmaxf(m, __shfl_xor_sync(FULL, m, o));
        const float e = expf(val - m);
        float sum = e;
#pragma unroll
        for (int o = 16; o > 0; o >>= 1) sum += __shfl_xor_sync(FULL, sum, o);
        sc[r][lane] = e / sum;
    }
    __syncthreads();

    for (int i = tid; i < SS * DHH; i += 256) {
        const int qq = i >> 6, d = i & 63;
        float a = 0.f;
#pragma unroll
        for (int kk = 0; kk < SS; kk++) a += sc[qq][kk] * vs[kk][d];
        g_ctx[(size_t)(b * SS + qq) * HHID + h * DHH + d] = a;
    }
}

// ---------------- residual + LayerNorm ----------------
__global__ void __launch_bounds__(256)
resid_ln_kernel(const float* __restrict__ lng, const float* __restrict__ lnb)
{
    const int r = blockIdx.x;
    const int tid = threadIdx.x;
    const int d = tid * 4;
    const size_t base = (size_t)r * HHID + d;
    const float4 a = *(const float4*)&g_ao[base];
    const float4 f = *(const float4*)&g_feat[base];
    const float v0=a.x+f.x, v1=a.y+f.y, v2=a.z+f.z, v3=a.w+f.w;

    __shared__ float red[256];
    __shared__ float stats[2];
    red[tid] = v0+v1+v2+v3;
    __syncthreads();
    for (int st = 128; st > 0; st >>= 1) { if (tid < st) red[tid] += red[tid+st]; __syncthreads(); }
    if (tid == 0) stats[0] = red[0] * (1.f / HHID);
    __syncthreads();
    const float mean = stats[0];
    const float q0=v0-mean, q1=v1-mean, q2=v2-mean, q3=v3-mean;
    red[tid] = q0*q0+q1*q1+q2*q2+q3*q3;
    __syncthreads();
    for (int st = 128; st > 0; st >>= 1) { if (tid < st) red[tid] += red[tid+st]; __syncthreads(); }
    if (tid == 0) stats[1] = rsqrtf(red[0] * (1.f / HHID) + 1e-7f);
    __syncthreads();
    const float rstd = stats[1];
    float* out = &g_feat2[base];
    out[0] = q0*rstd*lng[d+0] + lnb[d+0];
    out[1] = q1*rstd*lng[d+1] + lnb[d+1];
    out[2] = q2*rstd*lng[d+2] + lnb[d+2];
    out[3] = q3*rstd*lng[d+3] + lnb[d+3];
}

// ---------------- classifier + per-span loss terms ----------------
__global__ void __launch_bounds__(128)
loss_terms_kernel(const int* __restrict__ labels, const float* __restrict__ wf,
                  const int* __restrict__ am,
                  const float* __restrict__ Wc, const float* __restrict__ bc)
{
    const int r = blockIdx.x;
    const int tid = threadIdx.x;
    const float* row = &g_feat2[(size_t)r * HHID];
    float d0=0, d1=0, d2=0;
    for (int i = tid; i < HHID; i += 128) {
        const float x = row[i];
        d0 += x * Wc[i*3+0];
        d1 += x * Wc[i*3+1];
        d2 += x * Wc[i*3+2];
    }
    __shared__ float r0[128], r1[128], r2[128];
    r0[tid]=d0; r1[tid]=d1; r2[tid]=d2;
    __syncthreads();
    for (int st = 64; st > 0; st >>= 1) {
        if (tid < st) { r0[tid]+=r0[tid+st]; r1[tid]+=r1[tid+st]; r2[tid]+=r2[tid+st]; }
        __syncthreads();
    }
    if (tid == 0) {
        const float z0 = r0[0]+bc[0], z1 = r1[0]+bc[1], z2 = r2[0]+bc[2];
        const float m = fmaxf(z0, fmaxf(z1, z2));
        const float e0 = expf(z0-m), e1 = expf(z1-m), e2 = expf(z2-m);
        const float lse = m + logf(e0+e1+e2);
        const int lab = labels[r];
        const bool valid = lab >= 0;
        const int lc = valid ? lab : 0;
        const float zl = (lc==0) ? z0 : ((lc==1) ? z1 : z2);
        const float logp = zl - lse;
        const float pt = expf(logp);
        const float spanm = ((am[r]!=0) && valid) ? 1.f : 0.f;
        const float vm = valid ? 1.f : 0.f;
        const float omp = 1.f - pt;
        g_terms[r*4+0] = (-logp * wf[r]) * spanm;
        g_terms[r*4+1] = spanm;
        g_terms[r*4+2] = (-(omp*omp) * logp) * vm;
        g_terms[r*4+3] = vm;
    }
}

__global__ void __launch_bounds__(256)
final_loss_kernel(float* __restrict__ out)
{
    const int tid = threadIdx.x;
    float a0=0,a1=0,a2=0,a3=0;
    for (int r = tid; r < BB*SS; r += 256) {
        a0 += g_terms[r*4+0]; a1 += g_terms[r*4+1];
        a2 += g_terms[r*4+2]; a3 += g_terms[r*4+3];
    }
    __shared__ float s0[256], s1[256], s2[256], s3[256];
    s0[tid]=a0; s1[tid]=a1; s2[tid]=a2; s3[tid]=a3;
    __syncthreads();
    for (int st = 128; st > 0; st >>= 1) {
        if (tid < st) { s0[tid]+=s0[tid+st]; s1[tid]+=s1[tid+st]; s2[tid]+=s2[tid+st]; s3[tid]+=s3[tid+st]; }
        __syncthreads();
    }
    if (tid == 0)
        out[0] = s0[0] / fmaxf(s1[0], 1.f) + s2[0] / fmaxf(s3[0], 1.f);
}

// ---------------- launch ----------------
extern "C" void kernel_launch(void* const* d_in, const int* in_sizes, int n_in,
                              void* d_out, int out_size)
{
    const float* hs     = (const float*)d_in[0];
    const int*   heads  = (const int*)  d_in[1];
    const int*   tails  = (const int*)  d_in[2];
    const int*   am     = (const int*)  d_in[3];
    const int*   labels = (const int*)  d_in[4];
    const float* wf     = (const float*)d_in[5];
    const float* Wih_f  = (const float*)d_in[6];
    const float* Whh_f  = (const float*)d_in[7];
    const float* b_f    = (const float*)d_in[8];
    const float* Wih_b  = (const float*)d_in[9];
    const float* Whh_b  = (const float*)d_in[10];
    const float* b_b    = (const float*)d_in[11];
    const float* ln1g   = (const float*)d_in[12];
    const float* ln1b   = (const float*)d_in[13];
    const float* Wq     = (const float*)d_in[14];
    const float* bq     = (const float*)d_in[15];
    const float* Wk     = (const float*)d_in[16];
    const float* bk     = (const float*)d_in[17];
    const float* Wv     = (const float*)d_in[18];
    const float* bv     = (const float*)d_in[19];
    const float* Wo     = (const float*)d_in[20];
    const float* bo     = (const float*)d_in[21];
    const float* ln2g   = (const float*)d_in[22];
    const float* ln2b   = (const float*)d_in[23];
    const float* Wc     = (const float*)d_in[24];
    const float* bc     = (const float*)d_in[25];

    float *p_xs_f, *p_xs_b, *p_feat, *p_q, *p_k, *p_v, *p_ctx, *p_ao, *p_wt;
    cudaGetSymbolAddress((void**)&p_xs_f,  g_xs_f);
    cudaGetSymbolAddress((void**)&p_xs_b,  g_xs_b);
    cudaGetSymbolAddress((void**)&p_feat,  g_feat);
    cudaGetSymbolAddress((void**)&p_q,     g_q);
    cudaGetSymbolAddress((void**)&p_k,     g_k);
    cudaGetSymbolAddress((void**)&p_v,     g_v);
    cudaGetSymbolAddress((void**)&p_ctx,   g_ctx);
    cudaGetSymbolAddress((void**)&p_ao,    g_ao);
    cudaGetSymbolAddress((void**)&p_wt,    g_wt);

    // index 0: init (loss terms + barrier counters)
    init_kernel<<<8, 256>>>();

    // input projections: tf32, 2-stage + A-prefetch
    {
        dim3 grid(G4/128, (BB*TT)/128), blk(256);
        tf32_gemm_tn<<<grid, blk>>>(hs, Wih_f, b_f, p_xs_f, BB*TT, G4, HHID);
        tf32_gemm_tn<<<grid, blk>>>(hs, Wih_b, b_b, p_xs_b, BB*TT, G4, HHID);
    }

    // index 3: persistent bidirectional scan (R14-exact)
    lstm_scan_kernel<<<128, 256>>>(Whh_f, Whh_b);

    // transpose QKV/O weights
    {
        dim3 grid(32, 32), blk(256);
        transpose_kernel<<<grid, blk>>>(Wq, p_wt + 0 * HHID * HHID);
        transpose_kernel<<<grid, blk>>>(Wk, p_wt + 1 * HHID * HHID);
        transpose_kernel<<<grid, blk>>>(Wv, p_wt + 2 * HHID * HHID);
        transpose_kernel<<<grid, blk>>>(Wo, p_wt + 3 * HHID * HHID);
    }

    // span pool + LN1
    span_pool_ln_kernel<<<BB*SS, 256>>>(heads, tails, ln1g, ln1b);

    // q,k,v
    {
        dim3 grid(HHID/128, (BB*SS)/128), blk(256);
        tf32_gemm_tn<<<grid, blk>>>(p_feat, p_wt + 0 * HHID * HHID, bq, p_q, BB*SS, HHID, HHID);
        tf32_gemm_tn<<<grid, blk>>>(p_feat, p_wt + 1 * HHID * HHID, bk, p_k, BB*SS, HHID, HHID);
        tf32_gemm_tn<<<grid, blk>>>(p_feat, p_wt + 2 * HHID * HHID, bv, p_v, BB*SS, HHID, HHID);
    }

    attn_kernel<<<BB*NHH, 256>>>(am);

    {
        dim3 grid(HHID/128, (BB*SS)/128), blk(256);
        tf32_gemm_tn<<<grid, blk>>>(p_ctx, p_wt + 3 * HHID * HHID, bo, p_ao, BB*SS, HHID, HHID);
    }

    resid_ln_kernel<<<BB*SS, 256>>>(ln2g, ln2b);

    loss_terms_kernel<<<BB*SS, 128>>>(labels, wf, am, Wc, bc);

    final_loss_kernel<<<1, 256>>>((float*)d_out);
}

// round 16
// speedup vs baseline: 1.2199x; 1.0684x over previous
#include <cuda_runtime.h>
#include <math.h>

#define FULL 0xffffffffu
#define BB   16
#define TT   1024
#define HHID 1024
#define SS   32
#define CC   3
#define NHH  16
#define DHH  64
#define HH2  512
#define G4   2048

// ---------------- scratch ----------------
__device__ float g_xs_f[BB*TT*G4];
__device__ float g_xs_b[BB*TT*G4];
__device__ float g_enc [BB*TT*HHID];
__device__ float g_hbuf[2][2][BB][HH2];
__device__ float g_feat [BB*SS*HHID];
__device__ float g_q    [BB*SS*HHID];
__device__ float g_k    [BB*SS*HHID];
__device__ float g_v    [BB*SS*HHID];
__device__ float g_ctx  [BB*SS*HHID];
__device__ float g_ao   [BB*SS*HHID];
__device__ float g_feat2[BB*SS*HHID];
__device__ float g_terms[BB*SS*4];
__device__ float g_wt[4][HHID*HHID];

// monotonic per-direction barrier counters, own 128B lines
struct __align__(128) PadCtr { unsigned v; unsigned pad[31]; };
__device__ PadCtr g_ctr[2];

// ---------------- fast activation helpers ----------------
__device__ __forceinline__ float fast_sigmoid(float x)
{
    return __fdividef(1.f, 1.f + __expf(-x));
}
__device__ __forceinline__ float fast_tanh(float x)
{
    const float e2 = __expf(2.f * x);
    return __fdividef(e2 - 1.f, e2 + 1.f);
}

// ---------------- init kernel ----------------
__global__ void init_kernel()
{
    const int i = blockIdx.x * blockDim.x + threadIdx.x;
    if (i < BB * SS * 4) g_terms[i] = 0.f;
    if (i == 0) { g_ctr[0].v = 0u; g_ctr[1].v = 0u; }
}

// ---------------- cp.async helpers ----------------
__device__ __forceinline__ void cp_async16(unsigned saddr, const void* gptr)
{
    asm volatile("cp.async.cg.shared.global [%0], [%1], 16;" :: "r"(saddr), "l"(gptr));
}
__device__ __forceinline__ void cp_commit() { asm volatile("cp.async.commit_group;"); }
template<int N>
__device__ __forceinline__ void cp_wait() { asm volatile("cp.async.wait_group %0;" :: "n"(N)); }

// ---------------- tf32 mma helpers ----------------
__device__ __forceinline__ void ldsm_x4(unsigned& r0, unsigned& r1, unsigned& r2, unsigned& r3,
                                        unsigned saddr)
{
    asm volatile("ldmatrix.sync.aligned.m8n8.x4.shared.b16 {%0,%1,%2,%3}, [%4];"
                 : "=r"(r0), "=r"(r1), "=r"(r2), "=r"(r3) : "r"(saddr));
}
__device__ __forceinline__ void mma_tf32(float* c, unsigned a0, unsigned a1, unsigned a2, unsigned a3,
                                         unsigned b0, unsigned b1)
{
    asm volatile(
        "mma.sync.aligned.m16n8k8.row.col.f32.tf32.tf32.f32 "
        "{%0,%1,%2,%3}, {%4,%5,%6,%7}, {%8,%9}, {%0,%1,%2,%3};"
        : "+f"(c[0]), "+f"(c[1]), "+f"(c[2]), "+f"(c[3])
        : "r"(a0), "r"(a1), "r"(a2), "r"(a3), "r"(b0), "r"(b1));
}

// ---------------- tf32 GEMM: C[M,N] = A[M,K] @ B[N,K]^T + bias  (2-stage, A-prefetch) ----------------
#define PAD 20
__global__ void __launch_bounds__(256)
tf32_gemm_tn(const float* __restrict__ A, const float* __restrict__ B,
             const float* __restrict__ bias, float* __restrict__ C,
             int M, int N, int K)
{
    __shared__ float As[2][128][PAD];
    __shared__ float Bs[2][128][PAD];
    const int tid  = threadIdx.x;
    const int warp = tid >> 5;
    const int lane = tid & 31;
    const int wm   = warp >> 2;
    const int wn   = warp & 3;
    const int bm   = blockIdx.y * 128;
    const int bn   = blockIdx.x * 128;

    float c[4][4][4];
#pragma unroll
    for (int i = 0; i < 4; i++)
#pragma unroll
        for (int j = 0; j < 4; j++)
#pragma unroll
            for (int r = 0; r < 4; r++) c[i][j][r] = 0.f;

    const int lr = tid >> 1;
    const int cc = (tid & 1) * 8;

    const float* Ag = A + (size_t)(bm + lr) * K + cc;
    const float* Bg = B + (size_t)(bn + lr) * K + cc;

    const unsigned sA0 = (unsigned)__cvta_generic_to_shared(&As[0][lr][cc]);
    const unsigned sA1 = (unsigned)__cvta_generic_to_shared(&As[1][lr][cc]);
    const unsigned sB0 = (unsigned)__cvta_generic_to_shared(&Bs[0][lr][cc]);
    const unsigned sB1 = (unsigned)__cvta_generic_to_shared(&Bs[1][lr][cc]);

    const int fr = lane & 15;
    const int fc = ((lane >> 4) << 2);

    cp_async16(sA0,      Ag);
    cp_async16(sA0 + 16, Ag + 4);
    cp_async16(sB0,      Bg);
    cp_async16(sB0 + 16, Bg + 4);
    cp_commit();

    const int KT = K / 16;
    for (int kt = 0; kt < KT; kt++) {
        const int cur = kt & 1;
        if (kt + 1 < KT) {
            const float* Ap = Ag + (size_t)(kt + 1) * 16;
            const float* Bp = Bg + (size_t)(kt + 1) * 16;
            const unsigned dA = cur ? sA0 : sA1;
            const unsigned dB = cur ? sB0 : sB1;
            cp_async16(dA,      Ap);
            cp_async16(dA + 16, Ap + 4);
            cp_async16(dB,      Bp);
            cp_async16(dB + 16, Bp + 4);
            cp_commit();
            cp_wait<1>();
        } else {
            cp_wait<0>();
        }
        __syncthreads();

#pragma unroll
        for (int ks = 0; ks < 2; ks++) {
            const int k0 = ks * 8 + fc;
            unsigned b0a, b1a, b2a, b3a, b0b, b1b, b2b, b3b;
            unsigned av[4][4];
            {
                unsigned sa = (unsigned)__cvta_generic_to_shared(&Bs[cur][wn*32 + fr][k0]);
                ldsm_x4(b0a, b1a, b2a, b3a, sa);
                unsigned sb = (unsigned)__cvta_generic_to_shared(&Bs[cur][wn*32 + 16 + fr][k0]);
                ldsm_x4(b0b, b1b, b2b, b3b, sb);
            }
#pragma unroll
            for (int mf = 0; mf < 4; mf++) {
                unsigned sa = (unsigned)__cvta_generic_to_shared(&As[cur][wm*64 + mf*16 + fr][k0]);
                ldsm_x4(av[mf][0], av[mf][1], av[mf][2], av[mf][3], sa);
            }
#pragma unroll
            for (int mf = 0; mf < 4; mf++) {
                mma_tf32(c[mf][0], av[mf][0], av[mf][1], av[mf][2], av[mf][3], b0a, b2a);
                mma_tf32(c[mf][1], av[mf][0], av[mf][1], av[mf][2], av[mf][3], b1a, b3a);
                mma_tf32(c[mf][2], av[mf][0], av[mf][1], av[mf][2], av[mf][3], b0b, b2b);
                mma_tf32(c[mf][3], av[mf][0], av[mf][1], av[mf][2], av[mf][3], b1b, b3b);
            }
        }
        __syncthreads();
    }

    const int g  = lane >> 2;
    const int tg = lane & 3;
#pragma unroll
    for (int mf = 0; mf < 4; mf++) {
        const int row0 = bm + wm*64 + mf*16 + g;
#pragma unroll
        for (int nf = 0; nf < 4; nf++) {
            const int col0 = bn + wn*32 + nf*8 + 2*tg;
            const float2 bv = *(const float2*)&bias[col0];
            float2 v0 = make_float2(c[mf][nf][0] + bv.x, c[mf][nf][1] + bv.y);
            float2 v1 = make_float2(c[mf][nf][2] + bv.x, c[mf][nf][3] + bv.y);
            *(float2*)&C[(size_t)row0 * N + col0]       = v0;
            *(float2*)&C[(size_t)(row0 + 8) * N + col0] = v1;
        }
    }
}

// ---------------- 1024x1024 transpose ----------------
__global__ void __launch_bounds__(256)
transpose_kernel(const float* __restrict__ in, float* __restrict__ out)
{
    __shared__ float tile[32][33];
    const int bx = blockIdx.x * 32, by = blockIdx.y * 32;
    const int tx = threadIdx.x & 31, ty4 = (threadIdx.x >> 5) * 4;
#pragma unroll
    for (int r = 0; r < 4; r++)
        tile[ty4 + r][tx] = in[(size_t)(by + ty4 + r) * HHID + bx + tx];
    __syncthreads();
#pragma unroll
    for (int r = 0; r < 4; r++)
        out[(size_t)(bx + ty4 + r) * HHID + by + tx] = tile[tx][ty4 + r];
}

// ---------------- persistent bidirectional LSTM scan (split barrier + xs prefetch) ----------------
#define HPAD 516
__global__ void __launch_bounds__(256)
lstm_scan_kernel(const float* __restrict__ Whh_f, const float* __restrict__ Whh_b)
{
    __shared__ float h_sh[16 * HPAD];
    __shared__ float red[4][32][18];

    const int cid  = blockIdx.x;
    const int dir  = cid >> 6;
    const int ug   = cid & 63;
    const int U0   = ug * 8;
    const int tid  = threadIdx.x;
    const int w    = tid >> 5;
    const int lane = tid & 31;
    const int rg   = w >> 2;
    const int ksl  = w & 3;
    const int kb   = ksl * 128;
    const int qr   = lane >> 2;
    const int qc   = lane & 3;
    const int r_lo = rg * 16 + qr;
    const int r_hi = r_lo + 8;
    const int fr   = lane & 15;
    const int fc   = (lane >> 4) << 2;

    const float* __restrict__ Whh = dir ? Whh_b : Whh_f;
    const float* __restrict__ xs  = dir ? g_xs_b : g_xs_f;
    unsigned* const ctr = &g_ctr[dir].v;

    unsigned a[16][4];
    {
        const int grow_lo = (r_lo >> 3) * HH2 + U0 + (r_lo & 7);
        const int grow_hi = (r_hi >> 3) * HH2 + U0 + (r_hi & 7);
        const float* Wlo = Whh + (size_t)grow_lo * HH2;
        const float* Whi = Whh + (size_t)grow_hi * HH2;
#pragma unroll
        for (int j = 0; j < 16; j++) {
            const int k0 = kb + j * 8 + qc;
            a[j][0] = __float_as_uint(Wlo[k0]);
            a[j][1] = __float_as_uint(Whi[k0]);
            a[j][2] = __float_as_uint(Wlo[k0 + 4]);
            a[j][3] = __float_as_uint(Whi[k0 + 4]);
        }
    }

    const int cb = tid >> 3;
    const int cu = tid & 7;
    float c_state = 0.f;

    // prefetch xs for step 0
    float xp0 = 0.f, xp1 = 0.f, xp2 = 0.f, xp3 = 0.f;
    if (tid < 128) {
        const int t0 = dir ? (TT - 1) : 0;
        const size_t xb = ((size_t)(cb * TT + t0)) * G4 + U0 + cu;
        xp0 = xs[xb];
        xp1 = xs[xb + 512];
        xp2 = xs[xb + 1024];
        xp3 = xs[xb + 1536];
    }

    for (int s = 0; s < TT; s++) {
        const int t = dir ? (TT - 1 - s) : s;

        if (s == 0) {
            for (int i = tid; i < 16 * HPAD; i += 256) h_sh[i] = 0.f;
        } else {
            const float* hg = &g_hbuf[dir][(s - 1) & 1][0][0];
            for (int idx = tid * 4; idx < BB * HH2; idx += 1024) {
                const float4 v = __ldcg((const float4*)&hg[idx]);
                const int b = idx >> 9, k = idx & 511;
                *(float4*)&h_sh[b * HPAD + k] = v;
            }
        }
        __syncthreads();

        float cl0[4] = {0,0,0,0}, cl1[4] = {0,0,0,0};
        float ch0[4] = {0,0,0,0}, ch1[4] = {0,0,0,0};
#pragma unroll
        for (int j = 0; j < 16; j += 2) {
            {
                const int k0 = kb + j * 8 + fc;
                unsigned m0, m1, m2, m3;
                const unsigned sa = (unsigned)__cvta_generic_to_shared(&h_sh[fr * HPAD + k0]);
                ldsm_x4(m0, m1, m2, m3, sa);
                mma_tf32(cl0, a[j][0], a[j][1], a[j][2], a[j][3], m0, m2);
                mma_tf32(ch0, a[j][0], a[j][1], a[j][2], a[j][3], m1, m3);
            }
            {
                const int k0 = kb + (j + 1) * 8 + fc;
                unsigned m0, m1, m2, m3;
                const unsigned sa = (unsigned)__cvta_generic_to_shared(&h_sh[fr * HPAD + k0]);
                ldsm_x4(m0, m1, m2, m3, sa);
                mma_tf32(cl1, a[j+1][0], a[j+1][1], a[j+1][2], a[j+1][3], m0, m2);
                mma_tf32(ch1, a[j+1][0], a[j+1][1], a[j+1][2], a[j+1][3], m1, m3);
            }
        }

        *(float2*)&red[ksl][r_lo][2 * qc]     = make_float2(cl0[0]+cl1[0], cl0[1]+cl1[1]);
        *(float2*)&red[ksl][r_hi][2 * qc]     = make_float2(cl0[2]+cl1[2], cl0[3]+cl1[3]);
        *(float2*)&red[ksl][r_lo][8 + 2 * qc] = make_float2(ch0[0]+ch1[0], ch0[1]+ch1[1]);
        *(float2*)&red[ksl][r_hi][8 + 2 * qc] = make_float2(ch0[2]+ch1[2], ch0[3]+ch1[3]);
        __syncthreads();

        if (tid < 128) {
            const int r0 = 0 * 8 + cu, r1 = 1 * 8 + cu, r2 = 2 * 8 + cu, r3 = 3 * 8 + cu;
            const float zi = red[0][r0][cb] + red[1][r0][cb] + red[2][r0][cb] + red[3][r0][cb] + xp0;
            const float zf = red[0][r1][cb] + red[1][r1][cb] + red[2][r1][cb] + red[3][r1][cb] + xp1;
            const float zg = red[0][r2][cb] + red[1][r2][cb] + red[2][r2][cb] + red[3][r2][cb] + xp2;
            const float zo = red[0][r3][cb] + red[1][r3][cb] + red[2][r3][cb] + red[3][r3][cb] + xp3;
            const float is = fast_sigmoid(zi);
            const float fs = fast_sigmoid(zf);
            const float gv = fast_tanh(zg);
            const float os = fast_sigmoid(zo);
            c_state = fs * c_state + is * gv;
            const float hn = os * fast_tanh(c_state);
            __stcg(&g_hbuf[dir][s & 1][cb][U0 + cu], hn);
            __stcg(&g_enc[((size_t)(cb * TT + t)) * HHID + dir * HH2 + U0 + cu], hn);
        }

        // split barrier: sync (h stores drained cta-wide), arrive, prefetch xs(s+1), wait, sync
        __syncthreads();
        if (tid == 0) {
            asm volatile("red.release.gpu.global.add.u32 [%0], %1;" :: "l"(ctr), "r"(1u) : "memory");
        }
        if (s + 1 < TT && tid < 128) {
            const int tn = dir ? (TT - 2 - s) : (s + 1);
            const size_t xb = ((size_t)(cb * TT + tn)) * G4 + U0 + cu;
            xp0 = xs[xb];
            xp1 = xs[xb + 512];
            xp2 = xs[xb + 1024];
            xp3 = xs[xb + 1536];
        }
        if (tid == 0) {
            const unsigned target = 64u * (unsigned)(s + 1);
            unsigned v;
            do {
                asm volatile("ld.acquire.gpu.global.u32 %0, [%1];" : "=r"(v) : "l"(ctr) : "memory");
            } while (v < target);
        }
        __syncthreads();
    }
}

// ---------------- span mean-pool + LayerNorm ----------------
__global__ void __launch_bounds__(256)
span_pool_ln_kernel(const int* __restrict__ heads, const int* __restrict__ tails,
                    const float* __restrict__ lng, const float* __restrict__ lnb)
{
    const int r = blockIdx.x;
    const int b = r >> 5;
    int p0 = heads[r] + 1; if (p0 < 0) p0 = 0;
    int p1 = tails[r];     if (p1 > TT) p1 = TT;
    const int tid = threadIdx.x;
    const int d = tid * 4;

    float s0=0,s1=0,s2=0,s3=0;
    for (int p = p0; p < p1; p++) {
        const float4 vv = *(const float4*)&g_enc[(size_t)(b * TT + p) * HHID + d];
        s0 += vv.x; s1 += vv.y; s2 += vv.z; s3 += vv.w;
    }
    int cnt = p1 - p0; if (cnt < 1) cnt = 1;
    const float inv = 1.f / (float)cnt;
    const float v0=s0*inv, v1=s1*inv, v2=s2*inv, v3=s3*inv;

    __shared__ float red[256];
    __shared__ float stats[2];
    red[tid] = v0+v1+v2+v3;
    __syncthreads();
    for (int st = 128; st > 0; st >>= 1) { if (tid < st) red[tid] += red[tid+st]; __syncthreads(); }
    if (tid == 0) stats[0] = red[0] * (1.f / HHID);
    __syncthreads();
    const float mean = stats[0];
    const float q0=v0-mean, q1=v1-mean, q2=v2-mean, q3=v3-mean;
    red[tid] = q0*q0+q1*q1+q2*q2+q3*q3;
    __syncthreads();
    for (int st = 128; st > 0; st >>= 1) { if (tid < st) red[tid] += red[tid+st]; __syncthreads(); }
    if (tid == 0) stats[1] = rsqrtf(red[0] * (1.f / HHID) + 1e-7f);
    __syncthreads();
    const float rstd = stats[1];
    float* out = &g_feat[(size_t)r * HHID + d];
    out[0] = q0*rstd*lng[d+0] + lnb[d+0];
    out[1] = q1*rstd*lng[d+1] + lnb[d+1];
    out[2] = q2*rstd*lng[d+2] + lnb[d+2];
    out[3] = q3*rstd*lng[d+3] + lnb[d+3];
}

// ---------------- attention ----------------
__global__ void __launch_bounds__(256)
attn_kernel(const int* __restrict__ am)
{
    const int bh = blockIdx.x;
    const int b = bh >> 4;
    const int h = bh & 15;
    __shared__ float qs[SS][DHH], ks[SS][DHH], vs[SS][DHH];
    __shared__ float sc[SS][SS + 1];
    const int tid = threadIdx.x;

    for (int i = tid; i < SS * DHH; i += 256) {
        const int s = i >> 6, d = i & 63;
        const size_t off = (size_t)(b * SS + s) * HHID + h * DHH + d;
        qs[s][d] = g_q[off];
        ks[s][d] = g_k[off];
        vs[s][d] = g_v[off];
    }
    __syncthreads();

    for (int i = tid; i < SS * SS; i += 256) {
        const int qq = i >> 5, kk = i & 31;
        float a = 0.f;
#pragma unroll
        for (int d = 0; d < DHH; d++) a += qs[qq][d] * ks[kk][d];
        const bool valid = (am[b * SS + qq] != 0) && (am[b * SS + kk] != 0);
        sc[qq][kk] = valid ? a * 0.125f : -1e9f;
    }
    __syncthreads();

    const int wid = tid >> 5, lane = tid & 31;
    for (int r = wid; r < SS; r += 8) {
        const float val = sc[r][lane];
        float m = val;
#pragma unroll
        for (int o = 16; o > 0; o >>= 1) m = fmaxf(m, __shfl_xor_sync(FULL, m, o));
        const float e = expf(val - m);
        float sum = e;
#pragma unroll
        for (int o = 16; o > 0; o >>= 1) sum += __shfl_xor_sync(FULL, sum, o);
        sc[r][lane] = e / sum;
    }
    __syncthreads();

    for (int i = tid; i < SS * DHH; i += 256) {
        const int qq = i >> 6, d = i & 63;
        float a = 0.f;
#pragma unroll
        for (int kk = 0; kk < SS; kk++) a += sc[qq][kk] * vs[kk][d];
        g_ctx[(size_t)(b * SS + qq) * HHID + h * DHH + d] = a;
    }
}

// ---------------- residual + LayerNorm ----------------
__global__ void __launch_bounds__(256)
resid_ln_kernel(const float* __restrict__ lng, const float* __restrict__ lnb)
{
    const int r = blockIdx.x;
    const int tid = threadIdx.x;
    const int d = tid * 4;
    const size_t base = (size_t)r * HHID + d;
    const float4 a = *(const float4*)&g_ao[base];
    const float4 f = *(const float4*)&g_feat[base];
    const float v0=a.x+f.x, v1=a.y+f.y, v2=a.z+f.z, v3=a.w+f.w;

    __shared__ float red[256];
    __shared__ float stats[2];
    red[tid] = v0+v1+v2+v3;
    __syncthreads();
    for (int st = 128; st > 0; st >>= 1) { if (tid < st) red[tid] += red[tid+st]; __syncthreads(); }
    if (tid == 0) stats[0] = red[0] * (1.f / HHID);
    __syncthreads();
    const float mean = stats[0];
    const float q0=v0-mean, q1=v1-mean, q2=v2-mean, q3=v3-mean;
    red[tid] = q0*q0+q1*q1+q2*q2+q3*q3;
    __syncthreads();
    for (int st = 128; st > 0; st >>= 1) { if (tid < st) red[tid] += red[tid+st]; __syncthreads(); }
    if (tid == 0) stats[1] = rsqrtf(red[0] * (1.f / HHID) + 1e-7f);
    __syncthreads();
    const float rstd = stats[1];
    float* out = &g_feat2[base];
    out[0] = q0*rstd*lng[d+0] + lnb[d+0];
    out[1] = q1*rstd*lng[d+1] + lnb[d+1];
    out[2] = q2*rstd*lng[d+2] + lnb[d+2];
    out[3] = q3*rstd*lng[d+3] + lnb[d+3];
}

// ---------------- classifier + per-span loss terms ----------------
__global__ void __launch_bounds__(128)
loss_terms_kernel(const int* __restrict__ labels, const float* __restrict__ wf,
                  const int* __restrict__ am,
                  const float* __restrict__ Wc, const float* __restrict__ bc)
{
    const int r = blockIdx.x;
    const int tid = threadIdx.x;
    const float* row = &g_feat2[(size_t)r * HHID];
    float d0=0, d1=0, d2=0;
    for (int i = tid; i < HHID; i += 128) {
        const float x = row[i];
        d0 += x * Wc[i*3+0];
        d1 += x * Wc[i*3+1];
        d2 += x * Wc[i*3+2];
    }
    __shared__ float r0[128], r1[128], r2[128];
    r0[tid]=d0; r1[tid]=d1; r2[tid]=d2;
    __syncthreads();
    for (int st = 64; st > 0; st >>= 1) {
        if (tid < st) { r0[tid]+=r0[tid+st]; r1[tid]+=r1[tid+st]; r2[tid]+=r2[tid+st]; }
        __syncthreads();
    }
    if (tid == 0) {
        const float z0 = r0[0]+bc[0], z1 = r1[0]+bc[1], z2 = r2[0]+bc[2];
        const float m = fmaxf(z0, fmaxf(z1, z2));
        const float e0 = expf(z0-m), e1 = expf(z1-m), e2 = expf(z2-m);
        const float lse = m + logf(e0+e1+e2);
        const int lab = labels[r];
        const bool valid = lab >= 0;
        const int lc = valid ? lab : 0;
        const float zl = (lc==0) ? z0 : ((lc==1) ? z1 : z2);
        const float logp = zl - lse;
        const float pt = expf(logp);
        const float spanm = ((am[r]!=0) && valid) ? 1.f : 0.f;
        const float vm = valid ? 1.f : 0.f;
        const float omp = 1.f - pt;
        g_terms[r*4+0] = (-logp * wf[r]) * spanm;
        g_terms[r*4+1] = spanm;
        g_terms[r*4+2] = (-(omp*omp) * logp) * vm;
        g_terms[r*4+3] = vm;
    }
}

__global__ void __launch_bounds__(256)
final_loss_kernel(float* __restrict__ out)
{
    const int tid = threadIdx.x;
    float a0=0,a1=0,a2=0,a3=0;
    for (int r = tid; r < BB*SS; r += 256) {
        a0 += g_terms[r*4+0]; a1 += g_terms[r*4+1];
        a2 += g_terms[r*4+2]; a3 += g_terms[r*4+3];
    }
    __shared__ float s0[256], s1[256], s2[256], s3[256];
    s0[tid]=a0; s1[tid]=a1; s2[tid]=a2; s3[tid]=a3;
    __syncthreads();
    for (int st = 128; st > 0; st >>= 1) {
        if (tid < st) { s0[tid]+=s0[tid+st]; s1[tid]+=s1[tid+st]; s2[tid]+=s2[tid+st]; s3[tid]+=s3[tid+st]; }
        __syncthreads();
    }
    if (tid == 0)
        out[0] = s0[0] / fmaxf(s1[0], 1.f) + s2[0] / fmaxf(s3[0], 1.f);
}

// ---------------- launch ----------------
extern "C" void kernel_launch(void* const* d_in, const int* in_sizes, int n_in,
                              void* d_out, int out_size)
{
    const float* hs     = (const float*)d_in[0];
    const int*   heads  = (const int*)  d_in[1];
    const int*   tails  = (const int*)  d_in[2];
    const int*   am     = (const int*)  d_in[3];
    const int*   labels = (const int*)  d_in[4];
    const float* wf     = (const float*)d_in[5];
    const float* Wih_f  = (const float*)d_in[6];
    const float* Whh_f  = (const float*)d_in[7];
    const float* b_f    = (const float*)d_in[8];
    const float* Wih_b  = (const float*)d_in[9];
    const float* Whh_b  = (const float*)d_in[10];
    const float* b_b    = (const float*)d_in[11];
    const float* ln1g   = (const float*)d_in[12];
    const float* ln1b   = (const float*)d_in[13];
    const float* Wq     = (const float*)d_in[14];
    const float* bq     = (const float*)d_in[15];
    const float* Wk     = (const float*)d_in[16];
    const float* bk     = (const float*)d_in[17];
    const float* Wv     = (const float*)d_in[18];
    const float* bv     = (const float*)d_in[19];
    const float* Wo     = (const float*)d_in[20];
    const float* bo     = (const float*)d_in[21];
    const float* ln2g   = (const float*)d_in[22];
    const float* ln2b   = (const float*)d_in[23];
    const float* Wc     = (const float*)d_in[24];
    const float* bc     = (const float*)d_in[25];

    float *p_xs_f, *p_xs_b, *p_feat, *p_q, *p_k, *p_v, *p_ctx, *p_ao, *p_wt;
    cudaGetSymbolAddress((void**)&p_xs_f,  g_xs_f);
    cudaGetSymbolAddress((void**)&p_xs_b,  g_xs_b);
    cudaGetSymbolAddress((void**)&p_feat,  g_feat);
    cudaGetSymbolAddress((void**)&p_q,     g_q);
    cudaGetSymbolAddress((void**)&p_k,     g_k);
    cudaGetSymbolAddress((void**)&p_v,     g_v);
    cudaGetSymbolAddress((void**)&p_ctx,   g_ctx);
    cudaGetSymbolAddress((void**)&p_ao,    g_ao);
    cudaGetSymbolAddress((void**)&p_wt,    g_wt);

    // index 0: init (loss terms + barrier counters)
    init_kernel<<<8, 256>>>();

    // input projections: tf32, 2-stage + A-prefetch
    {
        dim3 grid(G4/128, (BB*TT)/128), blk(256);
        tf32_gemm_tn<<<grid, blk>>>(hs, Wih_f, b_f, p_xs_f, BB*TT, G4, HHID);
        tf32_gemm_tn<<<grid, blk>>>(hs, Wih_b, b_b, p_xs_b, BB*TT, G4, HHID);
    }

    // index 3: persistent bidirectional scan (split barrier + xs prefetch under wait)
    lstm_scan_kernel<<<128, 256>>>(Whh_f, Whh_b);

    // transpose QKV/O weights
    {
        dim3 grid(32, 32), blk(256);
        transpose_kernel<<<grid, blk>>>(Wq, p_wt + 0 * HHID * HHID);
        transpose_kernel<<<grid, blk>>>(Wk, p_wt + 1 * HHID * HHID);
        transpose_kernel<<<grid, blk>>>(Wv, p_wt + 2 * HHID * HHID);
        transpose_kernel<<<grid, blk>>>(Wo, p_wt + 3 * HHID * HHID);
    }

    // span pool + LN1
    span_pool_ln_kernel<<<BB*SS, 256>>>(heads, tails, ln1g, ln1b);

    // q,k,v
    {
        dim3 grid(HHID/128, (BB*SS)/128), blk(256);
        tf32_gemm_tn<<<grid, blk>>>(p_feat, p_wt + 0 * HHID * HHID, bq, p_q, BB*SS, HHID, HHID);
        tf32_gemm_tn<<<grid, blk>>>(p_feat, p_wt + 1 * HHID * HHID, bk, p_k, BB*SS, HHID, HHID);
        tf32_gemm_tn<<<grid, blk>>>(p_feat, p_wt + 2 * HHID * HHID, bv, p_v, BB*SS, HHID, HHID);
    }

    attn_kernel<<<BB*NHH, 256>>>(am);

    {
        dim3 grid(HHID/128, (BB*SS)/128), blk(256);
        tf32_gemm_tn<<<grid, blk>>>(p_ctx, p_wt + 3 * HHID * HHID, bo, p_ao, BB*SS, HHID, HHID);
    }

    resid_ln_kernel<<<BB*SS, 256>>>(ln2g, ln2b);

    loss_terms_kernel<<<BB*SS, 128>>>(labels, wf, am, Wc, bc);

    final_loss_kernel<<<1, 256>>>((float*)d_out);
}

// round 17
// speedup vs baseline: 1.2394x; 1.0159x over previous
#include <cuda_runtime.h>
#include <math.h>

#define FULL 0xffffffffu
#define BB   16
#define TT   1024
#define HHID 1024
#define SS   32
#define CC   3
#define NHH  16
#define DHH  64
#define HH2  512
#define G4   2048

// ---------------- scratch ----------------
__device__ float g_xs_f[BB*TT*G4];
__device__ float g_xs_b[BB*TT*G4];
__device__ float g_enc [BB*TT*HHID];
__device__ float g_hbuf[2][2][BB][HH2];
__device__ float g_feat [BB*SS*HHID];
__device__ float g_q    [BB*SS*HHID];
__device__ float g_k    [BB*SS*HHID];
__device__ float g_v    [BB*SS*HHID];
__device__ float g_ctx  [BB*SS*HHID];
__device__ float g_ao   [BB*SS*HHID];
__device__ float g_feat2[BB*SS*HHID];
__device__ float g_terms[BB*SS*4];
__device__ float g_wt[4][HHID*HHID];

struct __align__(128) PadCtr { unsigned v; unsigned pad[31]; };
__device__ PadCtr g_ctr[2];        // scan step barrier (monotonic)
__device__ PadCtr g_chunk[2][8];   // xs chunk readiness (target 256 each)

// ---------------- fast activation helpers ----------------
__device__ __forceinline__ float fast_sigmoid(float x)
{
    return __fdividef(1.f, 1.f + __expf(-x));
}
__device__ __forceinline__ float fast_tanh(float x)
{
    const float e2 = __expf(2.f * x);
    return __fdividef(e2 - 1.f, e2 + 1.f);
}

// ---------------- init kernel ----------------
__global__ void init_kernel()
{
    const int i = blockIdx.x * blockDim.x + threadIdx.x;
    if (i < BB * SS * 4) g_terms[i] = 0.f;
    if (i == 0) { g_ctr[0].v = 0u; g_ctr[1].v = 0u; }
    if (i < 16) g_chunk[i >> 3][i & 7].v = 0u;
}

// ---------------- cp.async helpers ----------------
__device__ __forceinline__ void cp_async16(unsigned saddr, const void* gptr)
{
    asm volatile("cp.async.cg.shared.global [%0], [%1], 16;" :: "r"(saddr), "l"(gptr));
}
__device__ __forceinline__ void cp_commit() { asm volatile("cp.async.commit_group;"); }
template<int N>
__device__ __forceinline__ void cp_wait() { asm volatile("cp.async.wait_group %0;" :: "n"(N)); }

// ---------------- tf32 mma helpers ----------------
__device__ __forceinline__ void ldsm_x4(unsigned& r0, unsigned& r1, unsigned& r2, unsigned& r3,
                                        unsigned saddr)
{
    asm volatile("ldmatrix.sync.aligned.m8n8.x4.shared.b16 {%0,%1,%2,%3}, [%4];"
                 : "=r"(r0), "=r"(r1), "=r"(r2), "=r"(r3) : "r"(saddr));
}
__device__ __forceinline__ void mma_tf32(float* c, unsigned a0, unsigned a1, unsigned a2, unsigned a3,
                                         unsigned b0, unsigned b1)
{
    asm volatile(
        "mma.sync.aligned.m16n8k8.row.col.f32.tf32.tf32.f32 "
        "{%0,%1,%2,%3}, {%4,%5,%6,%7}, {%8,%9}, {%0,%1,%2,%3};"
        : "+f"(c[0]), "+f"(c[1]), "+f"(c[2]), "+f"(c[3])
        : "r"(a0), "r"(a1), "r"(a2), "r"(a3), "r"(b0), "r"(b1));
}

#define PAD 20
#define HPAD 516
// smem budget: scan 16*HPAD + 4*32*18 = 10560 floats; gemm 2*2*128*PAD = 10240 floats
#define SMEM_FLOATS (16 * HPAD + 4 * 32 * 18)

// ---------------- gemm tile body (C[M,N]=A@B^T+bias), smem passed in ----------------
__device__ __forceinline__ void gemm_tile(
    float* smem_buf,
    const float* __restrict__ A, const float* __restrict__ B,
    const float* __restrict__ bias, float* __restrict__ C,
    int bm, int bn, int N, int K)
{
    float (*As)[128][PAD] = reinterpret_cast<float(*)[128][PAD]>(smem_buf);
    float (*Bs)[128][PAD] = reinterpret_cast<float(*)[128][PAD]>(smem_buf + 2 * 128 * PAD);
    const int tid  = threadIdx.x;
    const int warp = tid >> 5;
    const int lane = tid & 31;
    const int wm   = warp >> 2;
    const int wn   = warp & 3;

    float c[4][4][4];
#pragma unroll
    for (int i = 0; i < 4; i++)
#pragma unroll
        for (int j = 0; j < 4; j++)
#pragma unroll
            for (int r = 0; r < 4; r++) c[i][j][r] = 0.f;

    const int lr = tid >> 1;
    const int cc = (tid & 1) * 8;

    const float* Ag = A + (size_t)(bm + lr) * K + cc;
    const float* Bg = B + (size_t)(bn + lr) * K + cc;

    const unsigned sA0 = (unsigned)__cvta_generic_to_shared(&As[0][lr][cc]);
    const unsigned sA1 = (unsigned)__cvta_generic_to_shared(&As[1][lr][cc]);
    const unsigned sB0 = (unsigned)__cvta_generic_to_shared(&Bs[0][lr][cc]);
    const unsigned sB1 = (unsigned)__cvta_generic_to_shared(&Bs[1][lr][cc]);

    const int fr = lane & 15;
    const int fc = ((lane >> 4) << 2);

    cp_async16(sA0,      Ag);
    cp_async16(sA0 + 16, Ag + 4);
    cp_async16(sB0,      Bg);
    cp_async16(sB0 + 16, Bg + 4);
    cp_commit();

    const int KT = K / 16;
    for (int kt = 0; kt < KT; kt++) {
        const int cur = kt & 1;
        if (kt + 1 < KT) {
            const float* Ap = Ag + (size_t)(kt + 1) * 16;
            const float* Bp = Bg + (size_t)(kt + 1) * 16;
            const unsigned dA = cur ? sA0 : sA1;
            const unsigned dB = cur ? sB0 : sB1;
            cp_async16(dA,      Ap);
            cp_async16(dA + 16, Ap + 4);
            cp_async16(dB,      Bp);
            cp_async16(dB + 16, Bp + 4);
            cp_commit();
            cp_wait<1>();
        } else {
            cp_wait<0>();
        }
        __syncthreads();

#pragma unroll
        for (int ks = 0; ks < 2; ks++) {
            const int k0 = ks * 8 + fc;
            unsigned b0a, b1a, b2a, b3a, b0b, b1b, b2b, b3b;
            unsigned av[4][4];
            {
                unsigned sa = (unsigned)__cvta_generic_to_shared(&Bs[cur][wn*32 + fr][k0]);
                ldsm_x4(b0a, b1a, b2a, b3a, sa);
                unsigned sb = (unsigned)__cvta_generic_to_shared(&Bs[cur][wn*32 + 16 + fr][k0]);
                ldsm_x4(b0b, b1b, b2b, b3b, sb);
            }
#pragma unroll
            for (int mf = 0; mf < 4; mf++) {
                unsigned sa = (unsigned)__cvta_generic_to_shared(&As[cur][wm*64 + mf*16 + fr][k0]);
                ldsm_x4(av[mf][0], av[mf][1], av[mf][2], av[mf][3], sa);
            }
#pragma unroll
            for (int mf = 0; mf < 4; mf++) {
                mma_tf32(c[mf][0], av[mf][0], av[mf][1], av[mf][2], av[mf][3], b0a, b2a);
                mma_tf32(c[mf][1], av[mf][0], av[mf][1], av[mf][2], av[mf][3], b1a, b3a);
                mma_tf32(c[mf][2], av[mf][0], av[mf][1], av[mf][2], av[mf][3], b0b, b2b);
                mma_tf32(c[mf][3], av[mf][0], av[mf][1], av[mf][2], av[mf][3], b1b, b3b);
            }
        }
        __syncthreads();
    }

    const int g  = lane >> 2;
    const int tg = lane & 3;
#pragma unroll
    for (int mf = 0; mf < 4; mf++) {
        const int row0 = bm + wm*64 + mf*16 + g;
#pragma unroll
        for (int nf = 0; nf < 4; nf++) {
            const int col0 = bn + wn*32 + nf*8 + 2*tg;
            const float2 bv = *(const float2*)&bias[col0];
            float2 v0 = make_float2(c[mf][nf][0] + bv.x, c[mf][nf][1] + bv.y);
            float2 v1 = make_float2(c[mf][nf][2] + bv.x, c[mf][nf][3] + bv.y);
            *(float2*)&C[(size_t)row0 * N + col0]       = v0;
            *(float2*)&C[(size_t)(row0 + 8) * N + col0] = v1;
        }
    }
}

// ---------------- standalone tf32 GEMM (QKV / O) ----------------
__global__ void __launch_bounds__(256)
tf32_gemm_tn(const float* __restrict__ A, const float* __restrict__ B,
             const float* __restrict__ bias, float* __restrict__ C,
             int M, int N, int K)
{
    __shared__ float smem_buf[2 * 2 * 128 * PAD];
    gemm_tile(smem_buf, A, B, bias, C, blockIdx.y * 128, blockIdx.x * 128, N, K);
}

// ---------------- fused: scan (CTAs 0..127) + projection producers (CTAs 128..255) ----------------
__global__ void __launch_bounds__(256, 2)
fused_scan_gemm(const float* __restrict__ Whh_f, const float* __restrict__ Whh_b,
                const float* __restrict__ hs,
                const float* __restrict__ Wih_f, const float* __restrict__ b_f,
                const float* __restrict__ Wih_b, const float* __restrict__ b_b)
{
    __shared__ float smem_buf[SMEM_FLOATS];
    const int tid = threadIdx.x;

    if (blockIdx.x >= 128) {
        // ---------------- GEMM producer ----------------
        const int worker = blockIdx.x - 128;
        for (int j = 0; j < 32; j++) {
            const int item = worker + 128 * j;       // 0..4095, ascending priority
            const int p    = item >> 9;              // priority level 0..7
            const int r    = item & 511;
            const int dirg = r >> 8;
            const int q    = r & 255;
            const int b    = q >> 4;
            const int nb   = q & 15;
            const int tch  = dirg ? (7 - p) : p;     // chunk produced
            const int bm   = (b * 8 + tch) * 128;
            const int bn   = nb * 128;
            const float* Bw   = dirg ? Wih_b : Wih_f;
            const float* bias = dirg ? b_b : b_f;
            float* C = dirg ? g_xs_b : g_xs_f;
            gemm_tile(smem_buf, hs, Bw, bias, C, bm, bn, G4, HHID);
            __syncthreads();
            if (tid == 0) {
                unsigned* cc = &g_chunk[dirg][tch].v;
                asm volatile("red.release.gpu.global.add.u32 [%0], %1;" :: "l"(cc), "r"(1u) : "memory");
            }
            __syncthreads();
        }
        return;
    }

    // ---------------- scan consumer ----------------
    float* h_sh = smem_buf;
    float (*red)[32][18] = reinterpret_cast<float(*)[32][18]>(smem_buf + 16 * HPAD);

    const int cid  = blockIdx.x;
    const int dir  = cid >> 6;
    const int ug   = cid & 63;
    const int U0   = ug * 8;
    const int w    = tid >> 5;
    const int lane = tid & 31;
    const int rg   = w >> 2;
    const int ksl  = w & 3;
    const int kb   = ksl * 128;
    const int qr   = lane >> 2;
    const int qc   = lane & 3;
    const int r_lo = rg * 16 + qr;
    const int r_hi = r_lo + 8;
    const int fr   = lane & 15;
    const int fc   = (lane >> 4) << 2;

    const float* __restrict__ Whh = dir ? Whh_b : Whh_f;
    const float* __restrict__ xs  = dir ? g_xs_b : g_xs_f;
    unsigned* const ctr = &g_ctr[dir].v;

    unsigned a[16][4];
    {
        const int grow_lo = (r_lo >> 3) * HH2 + U0 + (r_lo & 7);
        const int grow_hi = (r_hi >> 3) * HH2 + U0 + (r_hi & 7);
        const float* Wlo = Whh + (size_t)grow_lo * HH2;
        const float* Whi = Whh + (size_t)grow_hi * HH2;
#pragma unroll
        for (int j = 0; j < 16; j++) {
            const int k0 = kb + j * 8 + qc;
            a[j][0] = __float_as_uint(Wlo[k0]);
            a[j][1] = __float_as_uint(Whi[k0]);
            a[j][2] = __float_as_uint(Wlo[k0 + 4]);
            a[j][3] = __float_as_uint(Whi[k0 + 4]);
        }
    }

    const int cb = tid >> 3;
    const int cu = tid & 7;
    float c_state = 0.f;

    // wait for chunk of step 0, then prefetch xs
    if (tid == 0) {
        unsigned* cc = &g_chunk[dir][dir ? 7 : 0].v;
        unsigned v;
        do {
            asm volatile("ld.acquire.gpu.global.u32 %0, [%1];" : "=r"(v) : "l"(cc) : "memory");
        } while (v < 256u);
    }
    __syncthreads();

    float xp0 = 0.f, xp1 = 0.f, xp2 = 0.f, xp3 = 0.f;
    if (tid < 128) {
        const int t0 = dir ? (TT - 1) : 0;
        const size_t xb = ((size_t)(cb * TT + t0)) * G4 + U0 + cu;
        xp0 = __ldcg(&xs[xb]);
        xp1 = __ldcg(&xs[xb + 512]);
        xp2 = __ldcg(&xs[xb + 1024]);
        xp3 = __ldcg(&xs[xb + 1536]);
    }

    for (int s = 0; s < TT; s++) {
        const int t = dir ? (TT - 1 - s) : s;

        if (s == 0) {
            for (int i = tid; i < 16 * HPAD; i += 256) h_sh[i] = 0.f;
        } else {
            const float* hg = &g_hbuf[dir][(s - 1) & 1][0][0];
            for (int idx = tid * 4; idx < BB * HH2; idx += 1024) {
                const float4 v = __ldcg((const float4*)&hg[idx]);
                const int b = idx >> 9, k = idx & 511;
                *(float4*)&h_sh[b * HPAD + k] = v;
            }
        }
        __syncthreads();

        float cl0[4] = {0,0,0,0}, cl1[4] = {0,0,0,0};
        float ch0[4] = {0,0,0,0}, ch1[4] = {0,0,0,0};
#pragma unroll
        for (int j = 0; j < 16; j += 2) {
            {
                const int k0 = kb + j * 8 + fc;
                unsigned m0, m1, m2, m3;
                const unsigned sa = (unsigned)__cvta_generic_to_shared(&h_sh[fr * HPAD + k0]);
                ldsm_x4(m0, m1, m2, m3, sa);
                mma_tf32(cl0, a[j][0], a[j][1], a[j][2], a[j][3], m0, m2);
                mma_tf32(ch0, a[j][0], a[j][1], a[j][2], a[j][3], m1, m3);
            }
            {
                const int k0 = kb + (j + 1) * 8 + fc;
                unsigned m0, m1, m2, m3;
                const unsigned sa = (unsigned)__cvta_generic_to_shared(&h_sh[fr * HPAD + k0]);
                ldsm_x4(m0, m1, m2, m3, sa);
                mma_tf32(cl1, a[j+1][0], a[j+1][1], a[j+1][2], a[j+1][3], m0, m2);
                mma_tf32(ch1, a[j+1][0], a[j+1][1], a[j+1][2], a[j+1][3], m1, m3);
            }
        }

        *(float2*)&red[ksl][r_lo][2 * qc]     = make_float2(cl0[0]+cl1[0], cl0[1]+cl1[1]);
        *(float2*)&red[ksl][r_hi][2 * qc]     = make_float2(cl0[2]+cl1[2], cl0[3]+cl1[3]);
        *(float2*)&red[ksl][r_lo][8 + 2 * qc] = make_float2(ch0[0]+ch1[0], ch0[1]+ch1[1]);
        *(float2*)&red[ksl][r_hi][8 + 2 * qc] = make_float2(ch0[2]+ch1[2], ch0[3]+ch1[3]);
        __syncthreads();

        if (tid < 128) {
            const int r0 = 0 * 8 + cu, r1 = 1 * 8 + cu, r2 = 2 * 8 + cu, r3 = 3 * 8 + cu;
            const float zi = red[0][r0][cb] + red[1][r0][cb] + red[2][r0][cb] + red[3][r0][cb] + xp0;
            const float zf = red[0][r1][cb] + red[1][r1][cb] + red[2][r1][cb] + red[3][r1][cb] + xp1;
            const float zg = red[0][r2][cb] + red[1][r2][cb] + red[2][r2][cb] + red[3][r2][cb] + xp2;
            const float zo = red[0][r3][cb] + red[1][r3][cb] + red[2][r3][cb] + red[3][r3][cb] + xp3;
            const float is = fast_sigmoid(zi);
            const float fs = fast_sigmoid(zf);
            const float gv = fast_tanh(zg);
            const float os = fast_sigmoid(zo);
            c_state = fs * c_state + is * gv;
            const float hn = os * fast_tanh(c_state);
            __stcg(&g_hbuf[dir][s & 1][cb][U0 + cu], hn);
            __stcg(&g_enc[((size_t)(cb * TT + t)) * HHID + dir * HH2 + U0 + cu], hn);
        }

        // split barrier: sync, arrive; chunk-wait if crossing; prefetch xs(s+1); wait; sync
        __syncthreads();
        if (tid == 0) {
            asm volatile("red.release.gpu.global.add.u32 [%0], %1;" :: "l"(ctr), "r"(1u) : "memory");
        }
        if (s + 1 < TT) {
            const int tn = dir ? (TT - 2 - s) : (s + 1);
            if (((s + 1) & 127) == 0) {
                if (tid == 0) {
                    unsigned* cc = &g_chunk[dir][tn >> 7].v;
                    unsigned v;
                    do {
                        asm volatile("ld.acquire.gpu.global.u32 %0, [%1];" : "=r"(v) : "l"(cc) : "memory");
                    } while (v < 256u);
                }
                __syncthreads();
            }
            if (tid < 128) {
                const size_t xb = ((size_t)(cb * TT + tn)) * G4 + U0 + cu;
                xp0 = __ldcg(&xs[xb]);
                xp1 = __ldcg(&xs[xb + 512]);
                xp2 = __ldcg(&xs[xb + 1024]);
                xp3 = __ldcg(&xs[xb + 1536]);
            }
        }
        if (tid == 0) {
            const unsigned target = 64u * (unsigned)(s + 1);
            unsigned v;
            do {
                asm volatile("ld.acquire.gpu.global.u32 %0, [%1];" : "=r"(v) : "l"(ctr) : "memory");
            } while (v < target);
        }
        __syncthreads();
    }
}

// ---------------- 1024x1024 transpose ----------------
__global__ void __launch_bounds__(256)
transpose_kernel(const float* __restrict__ in, float* __restrict__ out)
{
    __shared__ float tile[32][33];
    const int bx = blockIdx.x * 32, by = blockIdx.y * 32;
    const int tx = threadIdx.x & 31, ty4 = (threadIdx.x >> 5) * 4;
#pragma unroll
    for (int r = 0; r < 4; r++)
        tile[ty4 + r][tx] = in[(size_t)(by + ty4 + r) * HHID + bx + tx];
    __syncthreads();
#pragma unroll
    for (int r = 0; r < 4; r++)
        out[(size_t)(bx + ty4 + r) * HHID + by + tx] = tile[tx][ty4 + r];
}

// ---------------- span mean-pool + LayerNorm ----------------
__global__ void __launch_bounds__(256)
span_pool_ln_kernel(const int* __restrict__ heads, const int* __restrict__ tails,
                    const float* __restrict__ lng, const float* __restrict__ lnb)
{
    const int r = blockIdx.x;
    const int b = r >> 5;
    int p0 = heads[r] + 1; if (p0 < 0) p0 = 0;
    int p1 = tails[r];     if (p1 > TT) p1 = TT;
    const int tid = threadIdx.x;
    const int d = tid * 4;

    float s0=0,s1=0,s2=0,s3=0;
    for (int p = p0; p < p1; p++) {
        const float4 vv = *(const float4*)&g_enc[(size_t)(b * TT + p) * HHID + d];
        s0 += vv.x; s1 += vv.y; s2 += vv.z; s3 += vv.w;
    }
    int cnt = p1 - p0; if (cnt < 1) cnt = 1;
    const float inv = 1.f / (float)cnt;
    const float v0=s0*inv, v1=s1*inv, v2=s2*inv, v3=s3*inv;

    __shared__ float red[256];
    __shared__ float stats[2];
    red[tid] = v0+v1+v2+v3;
    __syncthreads();
    for (int st = 128; st > 0; st >>= 1) { if (tid < st) red[tid] += red[tid+st]; __syncthreads(); }
    if (tid == 0) stats[0] = red[0] * (1.f / HHID);
    __syncthreads();
    const float mean = stats[0];
    const float q0=v0-mean, q1=v1-mean, q2=v2-mean, q3=v3-mean;
    red[tid] = q0*q0+q1*q1+q2*q2+q3*q3;
    __syncthreads();
    for (int st = 128; st > 0; st >>= 1) { if (tid < st) red[tid] += red[tid+st]; __syncthreads(); }
    if (tid == 0) stats[1] = rsqrtf(red[0] * (1.f / HHID) + 1e-7f);
    __syncthreads();
    const float rstd = stats[1];
    float* out = &g_feat[(size_t)r * HHID + d];
    out[0] = q0*rstd*lng[d+0] + lnb[d+0];
    out[1] = q1*rstd*lng[d+1] + lnb[d+1];
    out[2] = q2*rstd*lng[d+2] + lnb[d+2];
    out[3] = q3*rstd*lng[d+3] + lnb[d+3];
}

// ---------------- attention ----------------
__global__ void __launch_bounds__(256)
attn_kernel(const int* __restrict__ am)
{
    const int bh = blockIdx.x;
    const int b = bh >> 4;
    const int h = bh & 15;
    __shared__ float qs[SS][DHH], ks[SS][DHH], vs[SS][DHH];
    __shared__ float sc[SS][SS + 1];
    const int tid = threadIdx.x;

    for (int i = tid; i < SS * DHH; i += 256) {
        const int s = i >> 6, d = i & 63;
        const size_t off = (size_t)(b * SS + s) * HHID + h * DHH + d;
        qs[s][d] = g_q[off];
        ks[s][d] = g_k[off];
        vs[s][d] = g_v[off];
    }
    __syncthreads();

    for (int i = tid; i < SS * SS; i += 256) {
        const int qq = i >> 5, kk = i & 31;
        float a = 0.f;
#pragma unroll
        for (int d = 0; d < DHH; d++) a += qs[qq][d] * ks[kk][d];
        const bool valid = (am[b * SS + qq] != 0) && (am[b * SS + kk] != 0);
        sc[qq][kk] = valid ? a * 0.125f : -1e9f;
    }
    __syncthreads();

    const int wid = tid >> 5, lane = tid & 31;
    for (int r = wid; r < SS; r += 8) {
        const float val = sc[r][lane];
        float m = val;
#pragma unroll
        for (int o = 16; o > 0; o >>= 1) m = fmaxf(m, __shfl_xor_sync(FULL, m, o));
        const float e = expf(val - m);
        float sum = e;
#pragma unroll
        for (int o = 16; o > 0; o >>= 1) sum += __shfl_xor_sync(FULL, sum, o);
        sc[r][lane] = e / sum;
    }
    __syncthreads();

    for (int i = tid; i < SS * DHH; i += 256) {
        const int qq = i >> 6, d = i & 63;
        float a = 0.f;
#pragma unroll
        for (int kk = 0; kk < SS; kk++) a += sc[qq][kk] * vs[kk][d];
        g_ctx[(size_t)(b * SS + qq) * HHID + h * DHH + d] = a;
    }
}

// ---------------- residual + LayerNorm ----------------
__global__ void __launch_bounds__(256)
resid_ln_kernel(const float* __restrict__ lng, const float* __restrict__ lnb)
{
    const int r = blockIdx.x;
    const int tid = threadIdx.x;
    const int d = tid * 4;
    const size_t base = (size_t)r * HHID + d;
    const float4 a = *(const float4*)&g_ao[base];
    const float4 f = *(const float4*)&g_feat[base];
    const float v0=a.x+f.x, v1=a.y+f.y, v2=a.z+f.z, v3=a.w+f.w;

    __shared__ float red[256];
    __shared__ float stats[2];
    red[tid] = v0+v1+v2+v3;
    __syncthreads();
    for (int st = 128; st > 0; st >>= 1) { if (tid < st) red[tid] += red[tid+st]; __syncthreads(); }
    if (tid == 0) stats[0] = red[0] * (1.f / HHID);
    __syncthreads();
    const float mean = stats[0];
    const float q0=v0-mean, q1=v1-mean, q2=v2-mean, q3=v3-mean;
    red[tid] = q0*q0+q1*q1+q2*q2+q3*q3;
    __syncthreads();
    for (int st = 128; st > 0; st >>= 1) { if (tid < st) red[tid] += red[tid+st]; __syncthreads(); }
    if (tid == 0) stats[1] = rsqrtf(red[0] * (1.f / HHID) + 1e-7f);
    __syncthreads();
    const float rstd = stats[1];
    float* out = &g_feat2[base];
    out[0] = q0*rstd*lng[d+0] + lnb[d+0];
    out[1] = q1*rstd*lng[d+1] + lnb[d+1];
    out[2] = q2*rstd*lng[d+2] + lnb[d+2];
    out[3] = q3*rstd*lng[d+3] + lnb[d+3];
}

// ---------------- classifier + per-span loss terms ----------------
__global__ void __launch_bounds__(128)
loss_terms_kernel(const int* __restrict__ labels, const float* __restrict__ wf,
                  const int* __restrict__ am,
                  const float* __restrict__ Wc, const float* __restrict__ bc)
{
    const int r = blockIdx.x;
    const int tid = threadIdx.x;
    const float* row = &g_feat2[(size_t)r * HHID];
    float d0=0, d1=0, d2=0;
    for (int i = tid; i < HHID; i += 128) {
        const float x = row[i];
        d0 += x * Wc[i*3+0];
        d1 += x * Wc[i*3+1];
        d2 += x * Wc[i*3+2];
    }
    __shared__ float r0[128], r1[128], r2[128];
    r0[tid]=d0; r1[tid]=d1; r2[tid]=d2;
    __syncthreads();
    for (int st = 64; st > 0; st >>= 1) {
        if (tid < st) { r0[tid]+=r0[tid+st]; r1[tid]+=r1[tid+st]; r2[tid]+=r2[tid+st]; }
        __syncthreads();
    }
    if (tid == 0) {
        const float z0 = r0[0]+bc[0], z1 = r1[0]+bc[1], z2 = r2[0]+bc[2];
        const float m = fmaxf(z0, fmaxf(z1, z2));
        const float e0 = expf(z0-m), e1 = expf(z1-m), e2 = expf(z2-m);
        const float lse = m + logf(e0+e1+e2);
        const int lab = labels[r];
        const bool valid = lab >= 0;
        const int lc = valid ? lab : 0;
        const float zl = (lc==0) ? z0 : ((lc==1) ? z1 : z2);
        const float logp = zl - lse;
        const float pt = expf(logp);
        const float spanm = ((am[r]!=0) && valid) ? 1.f : 0.f;
        const float vm = valid ? 1.f : 0.f;
        const float omp = 1.f - pt;
        g_terms[r*4+0] = (-logp * wf[r]) * spanm;
        g_terms[r*4+1] = spanm;
        g_terms[r*4+2] = (-(omp*omp) * logp) * vm;
        g_terms[r*4+3] = vm;
    }
}

__global__ void __launch_bounds__(256)
final_loss_kernel(float* __restrict__ out)
{
    const int tid = threadIdx.x;
    float a0=0,a1=0,a2=0,a3=0;
    for (int r = tid; r < BB*SS; r += 256) {
        a0 += g_terms[r*4+0]; a1 += g_terms[r*4+1];
        a2 += g_terms[r*4+2]; a3 += g_terms[r*4+3];
    }
    __shared__ float s0[256], s1[256], s2[256], s3[256];
    s0[tid]=a0; s1[tid]=a1; s2[tid]=a2; s3[tid]=a3;
    __syncthreads();
    for (int st = 128; st > 0; st >>= 1) {
        if (tid < st) { s0[tid]+=s0[tid+st]; s1[tid]+=s1[tid+st]; s2[tid]+=s2[tid+st]; s3[tid]+=s3[tid+st]; }
        __syncthreads();
    }
    if (tid == 0)
        out[0] = s0[0] / fmaxf(s1[0], 1.f) + s2[0] / fmaxf(s3[0], 1.f);
}

// ---------------- launch ----------------
extern "C" void kernel_launch(void* const* d_in, const int* in_sizes, int n_in,
                              void* d_out, int out_size)
{
    const float* hs     = (const float*)d_in[0];
    const int*   heads  = (const int*)  d_in[1];
    const int*   tails  = (const int*)  d_in[2];
    const int*   am     = (const int*)  d_in[3];
    const int*   labels = (const int*)  d_in[4];
    const float* wf     = (const float*)d_in[5];
    const float* Wih_f  = (const float*)d_in[6];
    const float* Whh_f  = (const float*)d_in[7];
    const float* b_f    = (const float*)d_in[8];
    const float* Wih_b  = (const float*)d_in[9];
    const float* Whh_b  = (const float*)d_in[10];
    const float* b_b    = (const float*)d_in[11];
    const float* ln1g   = (const float*)d_in[12];
    const float* ln1b   = (const float*)d_in[13];
    const float* Wq     = (const float*)d_in[14];
    const float* bq     = (const float*)d_in[15];
    const float* Wk     = (const float*)d_in[16];
    const float* bk     = (const float*)d_in[17];
    const float* Wv     = (const float*)d_in[18];
    const float* bv     = (const float*)d_in[19];
    const float* Wo     = (const float*)d_in[20];
    const float* bo     = (const float*)d_in[21];
    const float* ln2g   = (const float*)d_in[22];
    const float* ln2b   = (const float*)d_in[23];
    const float* Wc     = (const float*)d_in[24];
    const float* bc     = (const float*)d_in[25];

    float *p_feat, *p_q, *p_k, *p_v, *p_ctx, *p_ao, *p_wt;
    cudaGetSymbolAddress((void**)&p_feat,  g_feat);
    cudaGetSymbolAddress((void**)&p_q,     g_q);
    cudaGetSymbolAddress((void**)&p_k,     g_k);
    cudaGetSymbolAddress((void**)&p_v,     g_v);
    cudaGetSymbolAddress((void**)&p_ctx,   g_ctx);
    cudaGetSymbolAddress((void**)&p_ao,    g_ao);
    cudaGetSymbolAddress((void**)&p_wt,    g_wt);

    // init: loss terms + barrier + chunk counters
    init_kernel<<<8, 256>>>();

    // fused: projection producers + persistent bidirectional scan
    fused_scan_gemm<<<256, 256>>>(Whh_f, Whh_b, hs, Wih_f, b_f, Wih_b, b_b);

    // transpose QKV/O weights
    {
        dim3 grid(32, 32), blk(256);
        transpose_kernel<<<grid, blk>>>(Wq, p_wt + 0 * HHID * HHID);
        transpose_kernel<<<grid, blk>>>(Wk, p_wt + 1 * HHID * HHID);
        transpose_kernel<<<grid, blk>>>(Wv, p_wt + 2 * HHID * HHID);
        transpose_kernel<<<grid, blk>>>(Wo, p_wt + 3 * HHID * HHID);
    }

    // span pool + LN1
    span_pool_ln_kernel<<<BB*SS, 256>>>(heads, tails, ln1g, ln1b);

    // q,k,v
    {
        dim3 grid(HHID/128, (BB*SS)/128), blk(256);
        tf32_gemm_tn<<<grid, blk>>>(p_feat, p_wt + 0 * HHID * HHID, bq, p_q, BB*SS, HHID, HHID);
        tf32_gemm_tn<<<grid, blk>>>(p_feat, p_wt + 1 * HHID * HHID, bk, p_k, BB*SS, HHID, HHID);
        tf32_gemm_tn<<<grid, blk>>>(p_feat, p_wt + 2 * HHID * HHID, bv, p_v, BB*SS, HHID, HHID);
    }

    attn_kernel<<<BB*NHH, 256>>>(am);

    {
        dim3 grid(HHID/128, (BB*SS)/128), blk(256);
        tf32_gemm_tn<<<grid, blk>>>(p_ctx, p_wt + 3 * HHID * HHID, bo, p_ao, BB*SS, HHID, HHID);
    }

    resid_ln_kernel<<<BB*SS, 256>>>(ln2g, ln2b);

    loss_terms_kernel<<<BB*SS, 128>>>(labels, wf, am, Wc, bc);

    final_loss_kernel<<<1, 256>>>((float*)d_out);
}